// round 1
// baseline (speedup 1.0000x reference)
#include <cuda_runtime.h>
#include <math.h>

#define HID 1024
#define NE 3
#define DI 1280
#define D2 2560
#define NB 4
#define SEQ 4096
#define EPSV 1e-6f

// ---------------- scratch (device globals; no allocation allowed) ----------------
__device__ float g_xn[(size_t)NB * SEQ * HID];        // 67 MB  normalized x
__device__ float g_partial[NB * 32 * HID];            // pooled partials
__device__ float g_pooled[NB * HID];
__device__ float g_probs[NB * NE];
__device__ float g_Wi[(size_t)NB * HID * D2];         // 42 MB  mixed w_in
__device__ float g_bi[NB * D2];
__device__ float g_Wo[(size_t)NB * DI * HID];         // 21 MB  mixed w_out
__device__ float g_bo[NB * HID];
__device__ float g_zh[(size_t)NB * SEQ * D2];         // 168 MB GEMM1 output
__device__ float g_hs[(size_t)NB * SEQ * DI];         // 84 MB  scan output

// ---------------- 1. RMSNorm ----------------
// one block per (b,s) row; 256 threads x float4 = 1024 elems
__global__ void rmsnorm_kernel(const float* __restrict__ in,
                               const float* __restrict__ nw,
                               float* __restrict__ xn) {
    long long row = blockIdx.x;
    const float4* ip = (const float4*)(in + row * HID);
    float4 v = ip[threadIdx.x];
    float ss = v.x * v.x + v.y * v.y + v.z * v.z + v.w * v.w;
    // warp reduce
    #pragma unroll
    for (int o = 16; o > 0; o >>= 1) ss += __shfl_xor_sync(0xffffffffu, ss, o);
    __shared__ float ws[8];
    int wid = threadIdx.x >> 5, lid = threadIdx.x & 31;
    if (lid == 0) ws[wid] = ss;
    __syncthreads();
    float tot;
    if (wid == 0) {
        float t = (lid < 8) ? ws[lid] : 0.f;
        #pragma unroll
        for (int o = 4; o > 0; o >>= 1) t += __shfl_xor_sync(0xffffffffu, t, o);
        if (lid == 0) ws[0] = t;
    }
    __syncthreads();
    tot = ws[0];
    float scale = rsqrtf(tot * (1.0f / HID) + EPSV);
    float4 w = ((const float4*)nw)[threadIdx.x];
    float4 o4;
    o4.x = v.x * scale * w.x;
    o4.y = v.y * scale * w.y;
    o4.z = v.z * scale * w.z;
    o4.w = v.w * scale * w.w;
    ((float4*)(xn + row * HID))[threadIdx.x] = o4;
}

// ---------------- 2. pooled mean over S (two stage) ----------------
__global__ void pool1_kernel(const float* __restrict__ xn, float* __restrict__ partial) {
    int b = blockIdx.x >> 5;
    int c = blockIdx.x & 31;
    int h = threadIdx.x;  // blockDim = 1024
    const float* base = xn + ((long long)b * SEQ + (long long)c * 128) * HID + h;
    float s = 0.f;
    #pragma unroll 8
    for (int i = 0; i < 128; i++) s += base[(long long)i * HID];
    partial[(long long)blockIdx.x * HID + h] = s;
}

__global__ void pool2_kernel(const float* __restrict__ partial, float* __restrict__ pooled) {
    int b = blockIdx.x;
    int h = threadIdx.x;
    float s = 0.f;
    #pragma unroll
    for (int c = 0; c < 32; c++) s += partial[(long long)(b * 32 + c) * HID + h];
    pooled[b * HID + h] = s * (1.0f / SEQ);
}

// ---------------- 3. router: logits + softmax ----------------
__global__ void router_kernel(const float* __restrict__ pooled,
                              const float* __restrict__ rw,
                              const float* __restrict__ rb,
                              float* __restrict__ probs) {
    // 128 threads; each accumulates all 12 (b,e) partial dots
    __shared__ float sm[12][128];
    float acc[12];
    #pragma unroll
    for (int i = 0; i < 12; i++) acc[i] = 0.f;
    for (int h = threadIdx.x; h < HID; h += 128) {
        float r0 = rw[h * NE + 0], r1 = rw[h * NE + 1], r2 = rw[h * NE + 2];
        #pragma unroll
        for (int b = 0; b < NB; b++) {
            float p = pooled[b * HID + h];
            acc[b * 3 + 0] += p * r0;
            acc[b * 3 + 1] += p * r1;
            acc[b * 3 + 2] += p * r2;
        }
    }
    #pragma unroll
    for (int i = 0; i < 12; i++) sm[i][threadIdx.x] = acc[i];
    __syncthreads();
    for (int st = 64; st > 0; st >>= 1) {
        if (threadIdx.x < st) {
            #pragma unroll
            for (int i = 0; i < 12; i++) sm[i][threadIdx.x] += sm[i][threadIdx.x + st];
        }
        __syncthreads();
    }
    if (threadIdx.x < NB) {
        int b = threadIdx.x;
        float l0 = sm[b * 3 + 0][0] + rb[0];
        float l1 = sm[b * 3 + 1][0] + rb[1];
        float l2 = sm[b * 3 + 2][0] + rb[2];
        float mx = fmaxf(l0, fmaxf(l1, l2));
        float e0 = expf(l0 - mx), e1 = expf(l1 - mx), e2 = expf(l2 - mx);
        float inv = 1.0f / (e0 + e1 + e2);
        probs[b * 3 + 0] = e0 * inv;
        probs[b * 3 + 1] = e1 * inv;
        probs[b * 3 + 2] = e2 * inv;
    }
}

// ---------------- 4. expert mixing: dst[b] = sum_e probs[b,e]*src[e] ----------------
__global__ void mix_kernel(float* __restrict__ dst, const float* __restrict__ src,
                           const float* __restrict__ probs, long long elemsPerExpert) {
    long long i = ((long long)blockIdx.x * blockDim.x + threadIdx.x) * 4;
    long long total = (long long)NB * elemsPerExpert;
    long long stride = (long long)gridDim.x * blockDim.x * 4;
    for (; i < total; i += stride) {
        int b = (int)(i / elemsPerExpert);
        long long j = i - (long long)b * elemsPerExpert;
        float p0 = probs[b * 3 + 0], p1 = probs[b * 3 + 1], p2 = probs[b * 3 + 2];
        float4 a = *(const float4*)(src + j);
        float4 c = *(const float4*)(src + elemsPerExpert + j);
        float4 e = *(const float4*)(src + 2 * elemsPerExpert + j);
        float4 o;
        o.x = p0 * a.x + p1 * c.x + p2 * e.x;
        o.y = p0 * a.y + p1 * c.y + p2 * e.y;
        o.z = p0 * a.z + p1 * c.z + p2 * e.z;
        o.w = p0 * a.w + p1 * c.w + p2 * e.w;
        *(float4*)(dst + i) = o;
    }
}

// ---------------- 5/7. batched SGEMM 128x128x8, TM=TN=8, 256 threads ----------------
// C[b] (MxN) = A[b] (MxK) @ B[b] (KxN) + bias[b] (N)  [+ resid[b] (MxN)]
__global__ __launch_bounds__(256) void sgemm_kernel(
    const float* __restrict__ A, const float* __restrict__ B,
    const float* __restrict__ bias, const float* __restrict__ resid,
    float* __restrict__ C, int M, int N, int K,
    long long sA, long long sB, long long sC, long long sR) {
    const int BM = 128, BN = 128, BK = 8, TM = 8, TN = 8;
    int bb = blockIdx.z;
    const float* Ap = A + (long long)bb * sA + (long long)blockIdx.y * BM * K;
    const float* Bp = B + (long long)bb * sB + (long long)blockIdx.x * BN;
    const float* biasp = bias + (long long)bb * N;
    const float* residp = resid ? (resid + (long long)bb * sR) : nullptr;
    float* Cp = C + (long long)bb * sC;

    __shared__ float As[BK * BM];
    __shared__ float Bs[BK * BN];

    int tid = threadIdx.x;
    int innerRowA = tid >> 1, innerColA = (tid & 1) * 4;
    int innerRowB = tid >> 5, innerColB = (tid & 31) * 4;
    int threadRow = tid >> 4, threadCol = tid & 15;

    float acc[TM * TN];
    #pragma unroll
    for (int i = 0; i < TM * TN; i++) acc[i] = 0.f;
    float regM[TM], regN[TN];

    for (int k0 = 0; k0 < K; k0 += BK) {
        float4 a = *(const float4*)(Ap + (long long)innerRowA * K + innerColA);
        As[(innerColA + 0) * BM + innerRowA] = a.x;
        As[(innerColA + 1) * BM + innerRowA] = a.y;
        As[(innerColA + 2) * BM + innerRowA] = a.z;
        As[(innerColA + 3) * BM + innerRowA] = a.w;
        *(float4*)(Bs + innerRowB * BN + innerColB) =
            *(const float4*)(Bp + (long long)innerRowB * N + innerColB);
        __syncthreads();
        Ap += BK;
        Bp += (long long)BK * N;
        #pragma unroll
        for (int k = 0; k < BK; k++) {
            #pragma unroll
            for (int m = 0; m < TM; m++) regM[m] = As[k * BM + threadRow * TM + m];
            #pragma unroll
            for (int n = 0; n < TN; n++) regN[n] = Bs[k * BN + threadCol * TN + n];
            #pragma unroll
            for (int m = 0; m < TM; m++)
                #pragma unroll
                for (int n = 0; n < TN; n++) acc[m * TN + n] += regM[m] * regN[n];
        }
        __syncthreads();
    }

    #pragma unroll
    for (int m = 0; m < TM; m++) {
        long long row = (long long)blockIdx.y * BM + threadRow * TM + m;
        #pragma unroll
        for (int n = 0; n < TN; n += 4) {
            long long col = (long long)blockIdx.x * BN + threadCol * TN + n;
            float4 r;
            r.x = acc[m * TN + n + 0];
            r.y = acc[m * TN + n + 1];
            r.z = acc[m * TN + n + 2];
            r.w = acc[m * TN + n + 3];
            float4 bv = *(const float4*)(biasp + col);
            r.x += bv.x; r.y += bv.y; r.z += bv.z; r.w += bv.w;
            if (residp) {
                float4 rv = *(const float4*)(residp + row * N + col);
                r.x += rv.x; r.y += rv.y; r.z += rv.z; r.w += rv.w;
            }
            *(float4*)(Cp + row * N + col) = r;
        }
    }
}

// ---------------- 6. GRU scan: 5120 independent chains over S ----------------
__global__ void scan_kernel(const float* __restrict__ zh, float* __restrict__ hs,
                            float* __restrict__ new_state) {
    int idx = blockIdx.x * blockDim.x + threadIdx.x;
    if (idx >= NB * DI) return;
    int b = idx / DI, d = idx - b * DI;
    const float* base = zh + (long long)b * SEQ * D2 + d;
    float* hbase = hs + (long long)b * SEQ * DI + d;
    float h = 0.f;
    const int U = 8;
    for (int s0 = 0; s0 < SEQ; s0 += U) {
        float hid[U], gat[U];
        #pragma unroll
        for (int u = 0; u < U; u++) {
            hid[u] = base[(long long)(s0 + u) * D2];
            gat[u] = base[(long long)(s0 + u) * D2 + DI];
        }
        #pragma unroll
        for (int u = 0; u < U; u++) {
            float z = 1.0f / (1.0f + __expf(-gat[u]));
            float x = hid[u];
            float ht = (x >= 0.f) ? (x + 0.5f) : (1.0f / (1.0f + __expf(-x)));
            h = (1.0f - z) * h + z * ht;
            hbase[(long long)(s0 + u) * DI] = h;
        }
    }
    new_state[idx] = h;
}

__global__ void aux_kernel(float* __restrict__ out, long long off) { out[off] = 0.0f; }

// ---------------- launch ----------------
extern "C" void kernel_launch(void* const* d_in, const int* in_sizes, int n_in,
                              void* d_out, int out_size) {
    const float* inputs   = (const float*)d_in[0];
    const float* norm_w   = (const float*)d_in[1];
    const float* router_w = (const float*)d_in[2];
    const float* router_b = (const float*)d_in[3];
    const float* w_in     = (const float*)d_in[4];
    const float* b_in     = (const float*)d_in[5];
    const float* w_out    = (const float*)d_in[6];
    const float* b_out    = (const float*)d_in[7];
    float* out = (float*)d_out;

    float *xn, *partial, *pooled, *probs, *Wi, *bi, *Wo, *bo, *zh, *hs;
    cudaGetSymbolAddress((void**)&xn, g_xn);
    cudaGetSymbolAddress((void**)&partial, g_partial);
    cudaGetSymbolAddress((void**)&pooled, g_pooled);
    cudaGetSymbolAddress((void**)&probs, g_probs);
    cudaGetSymbolAddress((void**)&Wi, g_Wi);
    cudaGetSymbolAddress((void**)&bi, g_bi);
    cudaGetSymbolAddress((void**)&Wo, g_Wo);
    cudaGetSymbolAddress((void**)&bo, g_bo);
    cudaGetSymbolAddress((void**)&zh, g_zh);
    cudaGetSymbolAddress((void**)&hs, g_hs);

    // 1. RMSNorm
    rmsnorm_kernel<<<NB * SEQ, 256>>>(inputs, norm_w, xn);
    // 2. pooled mean
    pool1_kernel<<<NB * 32, 1024>>>(xn, partial);
    pool2_kernel<<<NB, 1024>>>(partial, pooled);
    // 3. router softmax
    router_kernel<<<1, 128>>>(pooled, router_w, router_b, probs);
    // 4. mix weights/biases
    {
        long long eW = (long long)HID * D2;      // 2,621,440
        long long nblk = (NB * eW / 4 + 255) / 256;
        mix_kernel<<<(int)nblk, 256>>>(Wi, w_in, probs, eW);
        long long eWo = (long long)DI * HID;     // 1,310,720
        nblk = (NB * eWo / 4 + 255) / 256;
        mix_kernel<<<(int)nblk, 256>>>(Wo, w_out, probs, eWo);
        mix_kernel<<<(NB * D2 / 4 + 255) / 256, 256>>>(bi, b_in, probs, D2);
        mix_kernel<<<(NB * HID / 4 + 255) / 256, 256>>>(bo, b_out, probs, HID);
    }
    // 5. GEMM1: zh = xn @ Wi + bi   (M=4096, N=2560, K=1024)
    {
        dim3 grid(D2 / 128, SEQ / 128, NB);
        sgemm_kernel<<<grid, 256>>>(xn, Wi, bi, nullptr, zh,
                                    SEQ, D2, HID,
                                    (long long)SEQ * HID, (long long)HID * D2,
                                    (long long)SEQ * D2, 0);
    }
    // 6. scan (writes hs and new_state region of d_out)
    scan_kernel<<<(NB * DI + 255) / 256, 256>>>(zh, hs, out + (long long)NB * SEQ * HID);
    // 7. GEMM2: out = hs @ Wo + bo + inputs  (M=4096, N=1024, K=1280)
    {
        dim3 grid(HID / 128, SEQ / 128, NB);
        sgemm_kernel<<<grid, 256>>>(hs, Wo, bo, inputs, out,
                                    SEQ, HID, DI,
                                    (long long)SEQ * DI, (long long)DI * HID,
                                    (long long)SEQ * HID, (long long)SEQ * HID);
    }
    // 8. aux_loss = 0 (last element)
    aux_kernel<<<1, 1>>>(out, (long long)out_size - 1);
}

// round 3
// speedup vs baseline: 2.2743x; 2.2743x over previous
#include <cuda_runtime.h>
#include <math.h>
#include <stdint.h>

#define HID 1024
#define NE 3
#define DI 1280
#define D2 2560
#define NB 4
#define SEQ 4096
#define EPSV 1e-6f

// ---------------- scratch (device globals) ----------------
__device__ float g_xn[(size_t)NB * SEQ * HID];
__device__ float g_partial[NB * 32 * HID];
__device__ float g_pooled[NB * HID];
__device__ float g_probs[NB * NE];
__device__ float g_WiT[(size_t)NB * HID * D2];   // [b][n=2560][k=1024]
__device__ float g_bi[NB * D2];
__device__ float g_WoT[(size_t)NB * DI * HID];   // [b][n=1024][k=1280]
__device__ float g_bo[NB * HID];
__device__ float g_zh[(size_t)NB * SEQ * D2];
__device__ float g_hs[(size_t)NB * SEQ * DI];

__device__ __forceinline__ uint32_t ftf32(float x) {
    uint32_t r;
    asm("cvt.rna.tf32.f32 %0, %1;" : "=r"(r) : "f"(x));
    return r;
}

// ---------------- 1. RMSNorm ----------------
__global__ void rmsnorm_kernel(const float* __restrict__ in,
                               const float* __restrict__ nw,
                               float* __restrict__ xn) {
    long long row = blockIdx.x;
    const float4* ip = (const float4*)(in + row * HID);
    float4 v = ip[threadIdx.x];
    float ss = v.x * v.x + v.y * v.y + v.z * v.z + v.w * v.w;
    #pragma unroll
    for (int o = 16; o > 0; o >>= 1) ss += __shfl_xor_sync(0xffffffffu, ss, o);
    __shared__ float ws[8];
    int wid = threadIdx.x >> 5, lid = threadIdx.x & 31;
    if (lid == 0) ws[wid] = ss;
    __syncthreads();
    if (wid == 0) {
        float t = (lid < 8) ? ws[lid] : 0.f;
        #pragma unroll
        for (int o = 4; o > 0; o >>= 1) t += __shfl_xor_sync(0xffffffffu, t, o);
        if (lid == 0) ws[0] = t;
    }
    __syncthreads();
    float scale = rsqrtf(ws[0] * (1.0f / HID) + EPSV);
    float4 w = ((const float4*)nw)[threadIdx.x];
    float4 o4;
    o4.x = v.x * scale * w.x;
    o4.y = v.y * scale * w.y;
    o4.z = v.z * scale * w.z;
    o4.w = v.w * scale * w.w;
    ((float4*)(xn + row * HID))[threadIdx.x] = o4;
}

// ---------------- 2. pooled mean ----------------
__global__ void pool1_kernel(const float* __restrict__ xn, float* __restrict__ partial) {
    int b = blockIdx.x >> 5;
    int c = blockIdx.x & 31;
    int h = threadIdx.x;
    const float* base = xn + ((long long)b * SEQ + (long long)c * 128) * HID + h;
    float s = 0.f;
    #pragma unroll 8
    for (int i = 0; i < 128; i++) s += base[(long long)i * HID];
    partial[(long long)blockIdx.x * HID + h] = s;
}
__global__ void pool2_kernel(const float* __restrict__ partial, float* __restrict__ pooled) {
    int b = blockIdx.x, h = threadIdx.x;
    float s = 0.f;
    #pragma unroll
    for (int c = 0; c < 32; c++) s += partial[(long long)(b * 32 + c) * HID + h];
    pooled[b * HID + h] = s * (1.0f / SEQ);
}

// ---------------- 3. router ----------------
__global__ void router_kernel(const float* __restrict__ pooled,
                              const float* __restrict__ rw,
                              const float* __restrict__ rb,
                              float* __restrict__ probs) {
    __shared__ float sm[12][128];
    float acc[12];
    #pragma unroll
    for (int i = 0; i < 12; i++) acc[i] = 0.f;
    for (int h = threadIdx.x; h < HID; h += 128) {
        float r0 = rw[h * NE + 0], r1 = rw[h * NE + 1], r2 = rw[h * NE + 2];
        #pragma unroll
        for (int b = 0; b < NB; b++) {
            float p = pooled[b * HID + h];
            acc[b * 3 + 0] += p * r0;
            acc[b * 3 + 1] += p * r1;
            acc[b * 3 + 2] += p * r2;
        }
    }
    #pragma unroll
    for (int i = 0; i < 12; i++) sm[i][threadIdx.x] = acc[i];
    __syncthreads();
    for (int st = 64; st > 0; st >>= 1) {
        if (threadIdx.x < st) {
            #pragma unroll
            for (int i = 0; i < 12; i++) sm[i][threadIdx.x] += sm[i][threadIdx.x + st];
        }
        __syncthreads();
    }
    if (threadIdx.x < NB) {
        int b = threadIdx.x;
        float l0 = sm[b * 3 + 0][0] + rb[0];
        float l1 = sm[b * 3 + 1][0] + rb[1];
        float l2 = sm[b * 3 + 2][0] + rb[2];
        float mx = fmaxf(l0, fmaxf(l1, l2));
        float e0 = expf(l0 - mx), e1 = expf(l1 - mx), e2 = expf(l2 - mx);
        float inv = 1.0f / (e0 + e1 + e2);
        probs[b * 3 + 0] = e0 * inv;
        probs[b * 3 + 1] = e1 * inv;
        probs[b * 3 + 2] = e2 * inv;
    }
}

// ---------------- 4a. mixed + transposed weights ----------------
__global__ void mixT_kernel(float* __restrict__ dst, const float* __restrict__ src,
                            const float* __restrict__ probs, int K, int N) {
    __shared__ float t0[32][33], t1[32][33], t2[32][33];
    int tx = threadIdx.x, ty = threadIdx.y;
    int k0 = blockIdx.y * 32, n0 = blockIdx.x * 32;
    long long eSz = (long long)K * N;
    #pragma unroll
    for (int i = 0; i < 4; i++) {
        int k = k0 + ty + i * 8;
        long long o = (long long)k * N + n0 + tx;
        t0[ty + i * 8][tx] = src[o];
        t1[ty + i * 8][tx] = src[eSz + o];
        t2[ty + i * 8][tx] = src[2 * eSz + o];
    }
    __syncthreads();
    #pragma unroll
    for (int b = 0; b < NB; b++) {
        float p0 = probs[b * 3 + 0], p1 = probs[b * 3 + 1], p2 = probs[b * 3 + 2];
        #pragma unroll
        for (int i = 0; i < 4; i++) {
            int n = n0 + ty + i * 8;
            int k = k0 + tx;
            dst[(long long)b * eSz + (long long)n * K + k] =
                p0 * t0[tx][ty + i * 8] + p1 * t1[tx][ty + i * 8] + p2 * t2[tx][ty + i * 8];
        }
    }
}

// ---------------- 4b. mixed biases ----------------
__global__ void mixv_kernel(float* __restrict__ dst, const float* __restrict__ src,
                            const float* __restrict__ probs, int n) {
    int i = blockIdx.x * blockDim.x + threadIdx.x;
    if (i >= NB * n) return;
    int b = i / n, j = i - b * n;
    dst[i] = probs[b * 3 + 0] * src[j] + probs[b * 3 + 1] * src[n + j] +
             probs[b * 3 + 2] * src[2 * n + j];
}

// ---------------- 5/7. TF32 mma.sync GEMM ----------------
// C[b](MxN) = A[b](MxK, row-major) @ B[b](NxK, K-major)^T + bias[b] (+ resid)
// BM=BN=128, BK=16, 256 threads (8 warps), warp tile 64x32, mma m16n8k8.
__device__ __forceinline__ void mma_tf32(float& d0, float& d1, float& d2, float& d3,
                                         uint32_t a0, uint32_t a1, uint32_t a2, uint32_t a3,
                                         uint32_t b0, uint32_t b1) {
    asm volatile("mma.sync.aligned.m16n8k8.row.col.f32.tf32.tf32.f32 "
                 "{%0,%1,%2,%3}, {%4,%5,%6,%7}, {%8,%9}, {%0,%1,%2,%3};"
                 : "+f"(d0), "+f"(d1), "+f"(d2), "+f"(d3)
                 : "r"(a0), "r"(a1), "r"(a2), "r"(a3), "r"(b0), "r"(b1));
}

__global__ __launch_bounds__(256, 2) void tmma_kernel(
    const float* __restrict__ A, const float* __restrict__ B,
    const float* __restrict__ bias, const float* __restrict__ resid,
    float* __restrict__ C, int K, int N,
    long long sA, long long sB, long long sC) {
    // SMEM: 2 stages x (A 2048 + B 2048) floats = 32KB
    __shared__ float sm[8192];
    const int tid = threadIdx.x;
    const int wid = tid >> 5;
    const int lane = tid & 31;
    const int bb = blockIdx.z;

    const float* Ap = A + (long long)bb * sA + (long long)blockIdx.y * 128 * K;
    const float* Bp = B + (long long)bb * sB + (long long)blockIdx.x * 128 * K;

    // staging decomposition (same for A and B loads)
    const int srow = tid >> 2;          // 0..63 (+64 for second half)
    const int sc = tid & 3;             // float4 index within 16-wide k
    const int sks = sc >> 1;
    const int sj = sc & 1;

    const int g = lane >> 2, t = lane & 3;
    const int slotSelf = g * 4 + (((g >> 1) + t) & 3);
    const int wm = wid >> 2;            // 0..1
    const int wn = wid & 3;             // 0..3

    float acc[4][4][4];
    #pragma unroll
    for (int i = 0; i < 4; i++)
        #pragma unroll
        for (int j = 0; j < 4; j++)
            #pragma unroll
            for (int q = 0; q < 4; q++) acc[i][j][q] = 0.f;

    const int KT = K >> 4;
    float4 ra[2], rb[2];

    // prologue: load k-tile 0
    #pragma unroll
    for (int u = 0; u < 2; u++) {
        int row = srow + u * 64;
        ra[u] = *(const float4*)(Ap + (long long)row * K + sc * 4);
        rb[u] = *(const float4*)(Bp + (long long)row * K + sc * 4);
    }

    auto stash = [&](int stg) {
        float* smA = sm + stg * 4096;
        float* smB = smA + 2048;
        #pragma unroll
        for (int u = 0; u < 2; u++) {
            int row = srow + u * 64;
            int mt = row >> 4, rhi = (row >> 3) & 1, gg = row & 7;
            int ia = sj * 2 + rhi;
            int abase = (mt * 2 + sks) * 128;
            float av[4] = {ra[u].x, ra[u].y, ra[u].z, ra[u].w};
            #pragma unroll
            for (int e = 0; e < 4; e++) {
                int slot = gg * 4 + (((gg >> 1) + e) & 3);
                smA[abase + slot * 4 + ia] = __uint_as_float(ftf32(av[e]));
            }
            int nt = row >> 3;
            int bbase = (nt * 2 + sks) * 64;
            float bv[4] = {rb[u].x, rb[u].y, rb[u].z, rb[u].w};
            #pragma unroll
            for (int e = 0; e < 4; e++) {
                int slot = gg * 4 + (((gg >> 1) + e) & 3);
                smB[bbase + slot * 2 + sj] = __uint_as_float(ftf32(bv[e]));
            }
        }
    };

    stash(0);
    __syncthreads();

    for (int kt = 0; kt < KT; kt++) {
        const int stg = kt & 1;
        if (kt + 1 < KT) {
            const float* Ak = Ap + (long long)(kt + 1) * 16;
            const float* Bk = Bp + (long long)(kt + 1) * 16;
            #pragma unroll
            for (int u = 0; u < 2; u++) {
                int row = srow + u * 64;
                ra[u] = *(const float4*)(Ak + (long long)row * K + sc * 4);
                rb[u] = *(const float4*)(Bk + (long long)row * K + sc * 4);
            }
        }
        const float* smA = sm + stg * 4096;
        const float* smB = smA + 2048;
        #pragma unroll
        for (int ks = 0; ks < 2; ks++) {
            uint32_t af[4][4];
            uint32_t bf[4][2];
            #pragma unroll
            for (int mf = 0; mf < 4; mf++) {
                int mt = wm * 4 + mf;
                float4 v = *(const float4*)(smA + (mt * 2 + ks) * 128 + slotSelf * 4);
                af[mf][0] = __float_as_uint(v.x);
                af[mf][1] = __float_as_uint(v.y);
                af[mf][2] = __float_as_uint(v.z);
                af[mf][3] = __float_as_uint(v.w);
            }
            #pragma unroll
            for (int nf = 0; nf < 4; nf++) {
                int nt = wn * 4 + nf;
                float2 v = *(const float2*)(smB + (nt * 2 + ks) * 64 + slotSelf * 2);
                bf[nf][0] = __float_as_uint(v.x);
                bf[nf][1] = __float_as_uint(v.y);
            }
            #pragma unroll
            for (int mf = 0; mf < 4; mf++)
                #pragma unroll
                for (int nf = 0; nf < 4; nf++)
                    mma_tf32(acc[mf][nf][0], acc[mf][nf][1], acc[mf][nf][2], acc[mf][nf][3],
                             af[mf][0], af[mf][1], af[mf][2], af[mf][3],
                             bf[nf][0], bf[nf][1]);
        }
        if (kt + 1 < KT) stash((kt + 1) & 1);
        __syncthreads();
    }

    // epilogue: direct float2 stores (32B-sector aligned per 4-lane row group)
    const long long m0 = (long long)blockIdx.y * 128;
    const int n0 = blockIdx.x * 128;
    float* Cp = C + (long long)bb * sC;
    const float* Rp = resid ? (resid + (long long)bb * sC) : nullptr;
    const float* bp = bias + (long long)bb * N + n0;
    #pragma unroll
    for (int mf = 0; mf < 4; mf++) {
        long long r0 = m0 + (wm * 4 + mf) * 16 + g;
        #pragma unroll
        for (int nf = 0; nf < 4; nf++) {
            int col = (wn * 4 + nf) * 8 + 2 * t;
            float2 bv = *(const float2*)(bp + col);
            long long o0 = r0 * N + n0 + col;
            long long o1 = (r0 + 8) * N + n0 + col;
            float2 v0 = make_float2(acc[mf][nf][0] + bv.x, acc[mf][nf][1] + bv.y);
            float2 v1 = make_float2(acc[mf][nf][2] + bv.x, acc[mf][nf][3] + bv.y);
            if (Rp) {
                float2 q0 = *(const float2*)(Rp + o0);
                float2 q1 = *(const float2*)(Rp + o1);
                v0.x += q0.x; v0.y += q0.y;
                v1.x += q1.x; v1.y += q1.y;
            }
            *(float2*)(Cp + o0) = v0;
            *(float2*)(Cp + o1) = v1;
        }
    }
}

// ---------------- 6. GRU scan ----------------
__global__ void scan_kernel(const float* __restrict__ zh, float* __restrict__ hs,
                            float* __restrict__ ns) {
    int idx = blockIdx.x * blockDim.x + threadIdx.x;
    if (idx >= NB * DI) return;
    int b = idx / DI, d = idx - b * DI;
    const float* base = zh + (long long)b * SEQ * D2 + d;
    float* hb = hs + (long long)b * SEQ * DI + d;
    const int U = 16;
    float h0a[U], g0a[U], h1a[U], g1a[U];
    #pragma unroll
    for (int u = 0; u < U; u++) {
        h0a[u] = base[(long long)u * D2];
        g0a[u] = base[(long long)u * D2 + DI];
    }
    float h = 0.f;
    for (int s0 = 0; s0 < SEQ; s0 += 2 * U) {
        {
            const float* nb = base + (long long)(s0 + U) * D2;
            #pragma unroll
            for (int u = 0; u < U; u++) {
                h1a[u] = nb[(long long)u * D2];
                g1a[u] = nb[(long long)u * D2 + DI];
            }
        }
        #pragma unroll
        for (int u = 0; u < U; u++) {
            float z = 1.f / (1.f + __expf(-g0a[u]));
            float x = h0a[u];
            float ht = (x >= 0.f) ? (x + 0.5f) : (1.f / (1.f + __expf(-x)));
            h = (1.0f - z) * h + z * ht;
            hb[(long long)(s0 + u) * DI] = h;
        }
        if (s0 + 2 * U < SEQ) {
            const float* nb = base + (long long)(s0 + 2 * U) * D2;
            #pragma unroll
            for (int u = 0; u < U; u++) {
                h0a[u] = nb[(long long)u * D2];
                g0a[u] = nb[(long long)u * D2 + DI];
            }
        }
        #pragma unroll
        for (int u = 0; u < U; u++) {
            float z = 1.f / (1.f + __expf(-g1a[u]));
            float x = h1a[u];
            float ht = (x >= 0.f) ? (x + 0.5f) : (1.f / (1.f + __expf(-x)));
            h = (1.0f - z) * h + z * ht;
            hb[(long long)(s0 + U + u) * DI] = h;
        }
    }
    ns[idx] = h;
}

__global__ void aux_kernel(float* __restrict__ out, long long off) { out[off] = 0.0f; }

// ---------------- launch ----------------
extern "C" void kernel_launch(void* const* d_in, const int* in_sizes, int n_in,
                              void* d_out, int out_size) {
    const float* inputs   = (const float*)d_in[0];
    const float* norm_w   = (const float*)d_in[1];
    const float* router_w = (const float*)d_in[2];
    const float* router_b = (const float*)d_in[3];
    const float* w_in     = (const float*)d_in[4];
    const float* b_in     = (const float*)d_in[5];
    const float* w_out    = (const float*)d_in[6];
    const float* b_out    = (const float*)d_in[7];
    float* out = (float*)d_out;

    float *xn, *partial, *pooled, *probs, *WiT, *bi, *WoT, *bo, *zh, *hs;
    cudaGetSymbolAddress((void**)&xn, g_xn);
    cudaGetSymbolAddress((void**)&partial, g_partial);
    cudaGetSymbolAddress((void**)&pooled, g_pooled);
    cudaGetSymbolAddress((void**)&probs, g_probs);
    cudaGetSymbolAddress((void**)&WiT, g_WiT);
    cudaGetSymbolAddress((void**)&bi, g_bi);
    cudaGetSymbolAddress((void**)&WoT, g_WoT);
    cudaGetSymbolAddress((void**)&bo, g_bo);
    cudaGetSymbolAddress((void**)&zh, g_zh);
    cudaGetSymbolAddress((void**)&hs, g_hs);

    rmsnorm_kernel<<<NB * SEQ, 256>>>(inputs, norm_w, xn);
    pool1_kernel<<<NB * 32, 1024>>>(xn, partial);
    pool2_kernel<<<NB, 1024>>>(partial, pooled);
    router_kernel<<<1, 128>>>(pooled, router_w, router_b, probs);

    {
        dim3 blk(32, 8);
        dim3 g1(D2 / 32, HID / 32);
        mixT_kernel<<<g1, blk>>>(WiT, w_in, probs, HID, D2);
        dim3 g2(HID / 32, DI / 32);
        mixT_kernel<<<g2, blk>>>(WoT, w_out, probs, DI, HID);
        mixv_kernel<<<(NB * D2 + 255) / 256, 256>>>(bi, b_in, probs, D2);
        mixv_kernel<<<(NB * HID + 255) / 256, 256>>>(bo, b_out, probs, HID);
    }

    {   // GEMM1: zh = xn @ WiT^T + bi   (M=4096, N=2560, K=1024)
        dim3 grid(D2 / 128, SEQ / 128, NB);
        tmma_kernel<<<grid, 256>>>(xn, WiT, bi, nullptr, zh, HID, D2,
                                   (long long)SEQ * HID, (long long)HID * D2,
                                   (long long)SEQ * D2);
    }

    scan_kernel<<<(NB * DI + 255) / 256, 256>>>(zh, hs, out + (long long)NB * SEQ * HID);

    {   // GEMM2: out = hs @ WoT^T + bo + inputs   (M=4096, N=1024, K=1280)
        dim3 grid(HID / 128, SEQ / 128, NB);
        tmma_kernel<<<grid, 256>>>(hs, WoT, bo, inputs, out, DI, HID,
                                   (long long)SEQ * DI, (long long)DI * HID,
                                   (long long)SEQ * HID);
    }

    aux_kernel<<<1, 1>>>(out, (long long)out_size - 1);
}

// round 4
// speedup vs baseline: 2.2979x; 1.0104x over previous
#include <cuda_runtime.h>
#include <cuda_bf16.h>
#include <math.h>
#include <stdint.h>

#define HID 1024
#define NE 3
#define DI 1280
#define D2 2560
#define NB 4
#define SEQ 4096
#define EPSV 1e-6f

// ---------------- scratch (device globals) ----------------
__device__ __nv_bfloat16 g_xnh[(size_t)NB * SEQ * HID];     // normalized x, bf16
__device__ float g_partial[NB * 32 * HID];
__device__ float g_pooled[NB * HID];
__device__ float g_probs[NB * NE];
__device__ __nv_bfloat16 g_WiT[(size_t)NB * HID * D2];      // [b][n=2560][k=1024] bf16
__device__ float g_bi[NB * D2];
__device__ __nv_bfloat16 g_WoT[(size_t)NB * DI * HID];      // [b][n=1024][k=1280] bf16
__device__ float g_bo[NB * HID];
__device__ float g_zh[(size_t)NB * SEQ * D2];               // GEMM1 out, fp32
__device__ __nv_bfloat16 g_hs[(size_t)NB * SEQ * DI];       // scan out, bf16

// ---------------- 1. RMSNorm -> bf16 ----------------
__global__ void rmsnorm_kernel(const float* __restrict__ in,
                               const float* __restrict__ nw,
                               __nv_bfloat16* __restrict__ xnh) {
    long long row = blockIdx.x;
    const float4* ip = (const float4*)(in + row * HID);
    float4 v = ip[threadIdx.x];
    float ss = v.x * v.x + v.y * v.y + v.z * v.z + v.w * v.w;
    #pragma unroll
    for (int o = 16; o > 0; o >>= 1) ss += __shfl_xor_sync(0xffffffffu, ss, o);
    __shared__ float ws[8];
    int wid = threadIdx.x >> 5, lid = threadIdx.x & 31;
    if (lid == 0) ws[wid] = ss;
    __syncthreads();
    if (wid == 0) {
        float t = (lid < 8) ? ws[lid] : 0.f;
        #pragma unroll
        for (int o = 4; o > 0; o >>= 1) t += __shfl_xor_sync(0xffffffffu, t, o);
        if (lid == 0) ws[0] = t;
    }
    __syncthreads();
    float scale = rsqrtf(ws[0] * (1.0f / HID) + EPSV);
    float4 w = ((const float4*)nw)[threadIdx.x];
    __nv_bfloat162 p0 = __floats2bfloat162_rn(v.x * scale * w.x, v.y * scale * w.y);
    __nv_bfloat162 p1 = __floats2bfloat162_rn(v.z * scale * w.z, v.w * scale * w.w);
    uint2 u;
    u.x = *(uint32_t*)&p0;
    u.y = *(uint32_t*)&p1;
    *(uint2*)(xnh + row * HID + threadIdx.x * 4) = u;
}

// ---------------- 2. pooled mean (from bf16) ----------------
__global__ void pool1_kernel(const __nv_bfloat16* __restrict__ xnh, float* __restrict__ partial) {
    int b = blockIdx.x >> 5;
    int c = blockIdx.x & 31;
    int h = threadIdx.x;
    const __nv_bfloat16* base = xnh + ((long long)b * SEQ + (long long)c * 128) * HID + h;
    float s = 0.f;
    #pragma unroll 8
    for (int i = 0; i < 128; i++) s += __bfloat162float(base[(long long)i * HID]);
    partial[(long long)blockIdx.x * HID + h] = s;
}
__global__ void pool2_kernel(const float* __restrict__ partial, float* __restrict__ pooled) {
    int b = blockIdx.x, h = threadIdx.x;
    float s = 0.f;
    #pragma unroll
    for (int c = 0; c < 32; c++) s += partial[(long long)(b * 32 + c) * HID + h];
    pooled[b * HID + h] = s * (1.0f / SEQ);
}

// ---------------- 3. router ----------------
__global__ void router_kernel(const float* __restrict__ pooled,
                              const float* __restrict__ rw,
                              const float* __restrict__ rb,
                              float* __restrict__ probs) {
    __shared__ float sm[12][128];
    float acc[12];
    #pragma unroll
    for (int i = 0; i < 12; i++) acc[i] = 0.f;
    for (int h = threadIdx.x; h < HID; h += 128) {
        float r0 = rw[h * NE + 0], r1 = rw[h * NE + 1], r2 = rw[h * NE + 2];
        #pragma unroll
        for (int b = 0; b < NB; b++) {
            float p = pooled[b * HID + h];
            acc[b * 3 + 0] += p * r0;
            acc[b * 3 + 1] += p * r1;
            acc[b * 3 + 2] += p * r2;
        }
    }
    #pragma unroll
    for (int i = 0; i < 12; i++) sm[i][threadIdx.x] = acc[i];
    __syncthreads();
    for (int st = 64; st > 0; st >>= 1) {
        if (threadIdx.x < st) {
            #pragma unroll
            for (int i = 0; i < 12; i++) sm[i][threadIdx.x] += sm[i][threadIdx.x + st];
        }
        __syncthreads();
    }
    if (threadIdx.x < NB) {
        int b = threadIdx.x;
        float l0 = sm[b * 3 + 0][0] + rb[0];
        float l1 = sm[b * 3 + 1][0] + rb[1];
        float l2 = sm[b * 3 + 2][0] + rb[2];
        float mx = fmaxf(l0, fmaxf(l1, l2));
        float e0 = expf(l0 - mx), e1 = expf(l1 - mx), e2 = expf(l2 - mx);
        float inv = 1.0f / (e0 + e1 + e2);
        probs[b * 3 + 0] = e0 * inv;
        probs[b * 3 + 1] = e1 * inv;
        probs[b * 3 + 2] = e2 * inv;
    }
}

// ---------------- 4a. mixed + transposed weights -> bf16 ----------------
__global__ void mixT_kernel(__nv_bfloat16* __restrict__ dst, const float* __restrict__ src,
                            const float* __restrict__ probs, int K, int N) {
    __shared__ float t0[32][33], t1[32][33], t2[32][33];
    int tx = threadIdx.x, ty = threadIdx.y;
    int k0 = blockIdx.y * 32, n0 = blockIdx.x * 32;
    long long eSz = (long long)K * N;
    #pragma unroll
    for (int i = 0; i < 4; i++) {
        int k = k0 + ty + i * 8;
        long long o = (long long)k * N + n0 + tx;
        t0[ty + i * 8][tx] = src[o];
        t1[ty + i * 8][tx] = src[eSz + o];
        t2[ty + i * 8][tx] = src[2 * eSz + o];
    }
    __syncthreads();
    #pragma unroll
    for (int b = 0; b < NB; b++) {
        float p0 = probs[b * 3 + 0], p1 = probs[b * 3 + 1], p2 = probs[b * 3 + 2];
        #pragma unroll
        for (int i = 0; i < 4; i++) {
            int n = n0 + ty + i * 8;
            int k = k0 + tx;
            float v = p0 * t0[tx][ty + i * 8] + p1 * t1[tx][ty + i * 8] + p2 * t2[tx][ty + i * 8];
            dst[(long long)b * eSz + (long long)n * K + k] = __float2bfloat16(v);
        }
    }
}

// ---------------- 4b. mixed biases (fp32) ----------------
__global__ void mixv_kernel(float* __restrict__ dst, const float* __restrict__ src,
                            const float* __restrict__ probs, int n) {
    int i = blockIdx.x * blockDim.x + threadIdx.x;
    if (i >= NB * n) return;
    int b = i / n, j = i - b * n;
    dst[i] = probs[b * 3 + 0] * src[j] + probs[b * 3 + 1] * src[n + j] +
             probs[b * 3 + 2] * src[2 * n + j];
}

// ---------------- 5/7. bf16 mma.sync m16n8k16 GEMM ----------------
// C[b](MxN) = A[b](MxK bf16 row-major) @ B[b](NxK bf16 K-major)^T + bias (+ resid)
// BM=BN=128, BK=16, 256 threads (8 warps), warp tile 64x32.
__device__ __forceinline__ void mma_bf16(float& d0, float& d1, float& d2, float& d3,
                                         uint32_t a0, uint32_t a1, uint32_t a2, uint32_t a3,
                                         uint32_t b0, uint32_t b1) {
    asm volatile("mma.sync.aligned.m16n8k16.row.col.f32.bf16.bf16.f32 "
                 "{%0,%1,%2,%3}, {%4,%5,%6,%7}, {%8,%9}, {%0,%1,%2,%3};"
                 : "+f"(d0), "+f"(d1), "+f"(d2), "+f"(d3)
                 : "r"(a0), "r"(a1), "r"(a2), "r"(a3), "r"(b0), "r"(b1));
}

__global__ __launch_bounds__(256, 2) void hgemm_kernel(
    const __nv_bfloat16* __restrict__ A, const __nv_bfloat16* __restrict__ B,
    const float* __restrict__ bias, const float* __restrict__ resid,
    float* __restrict__ C, int K, int N,
    long long sA, long long sB, long long sC) {
    // 2 stages x (A 1024 + B 1024) u32 = 16KB
    __shared__ uint32_t sm[4096];
    const int tid = threadIdx.x;
    const int wid = tid >> 5;
    const int lane = tid & 31;
    const int bb = blockIdx.z;

    const __nv_bfloat16* Ap = A + (long long)bb * sA + (long long)blockIdx.y * 128 * K;
    const __nv_bfloat16* Bp = B + (long long)bb * sB + (long long)blockIdx.x * 128 * K;

    const int lrow = tid >> 1;          // 0..127
    const int lhalf = tid & 1;          // k half (0: k0..7, 1: k8..15)

    const int g = lane >> 2, t = lane & 3;
    const int slotSelf = g * 4 + (((g >> 1) + t) & 3);
    const int wm = wid >> 2;            // 0..1
    const int wn = wid & 3;             // 0..3

    float acc[4][4][4];
    #pragma unroll
    for (int i = 0; i < 4; i++)
        #pragma unroll
        for (int j = 0; j < 4; j++)
            #pragma unroll
            for (int q = 0; q < 4; q++) acc[i][j][q] = 0.f;

    const int KT = K >> 4;
    uint4 ra, rb;

    ra = *(const uint4*)(Ap + (long long)lrow * K + lhalf * 8);
    rb = *(const uint4*)(Bp + (long long)lrow * K + lhalf * 8);

    const int mt = lrow >> 4, nt = lrow >> 3;
    const int rhi = (lrow >> 3) & 1, gg = lrow & 7;
    const int iaA = lhalf * 2 + rhi;

    auto stash = [&](int stg) {
        uint32_t* smA = sm + stg * 2048;
        uint32_t* smB = smA + 1024;
        uint32_t wa[4] = {ra.x, ra.y, ra.z, ra.w};
        uint32_t wb[4] = {rb.x, rb.y, rb.z, rb.w};
        #pragma unroll
        for (int e = 0; e < 4; e++) {
            int slot = gg * 4 + (((gg >> 1) + e) & 3);
            smA[mt * 128 + slot * 4 + iaA] = wa[e];
            smB[nt * 64 + slot * 2 + lhalf] = wb[e];
        }
    };

    stash(0);
    __syncthreads();

    for (int kt = 0; kt < KT; kt++) {
        const int stg = kt & 1;
        if (kt + 1 < KT) {
            const __nv_bfloat16* Ak = Ap + (kt + 1) * 16;
            const __nv_bfloat16* Bk = Bp + (kt + 1) * 16;
            ra = *(const uint4*)(Ak + (long long)lrow * K + lhalf * 8);
            rb = *(const uint4*)(Bk + (long long)lrow * K + lhalf * 8);
        }
        const uint32_t* smA = sm + stg * 2048;
        const uint32_t* smB = smA + 1024;
        uint32_t af[4][4];
        uint32_t bf[4][2];
        #pragma unroll
        for (int mf = 0; mf < 4; mf++) {
            uint4 v = *(const uint4*)(smA + (wm * 4 + mf) * 128 + slotSelf * 4);
            af[mf][0] = v.x; af[mf][1] = v.y; af[mf][2] = v.z; af[mf][3] = v.w;
        }
        #pragma unroll
        for (int nf = 0; nf < 4; nf++) {
            uint2 v = *(const uint2*)(smB + (wn * 4 + nf) * 64 + slotSelf * 2);
            bf[nf][0] = v.x; bf[nf][1] = v.y;
        }
        #pragma unroll
        for (int mf = 0; mf < 4; mf++)
            #pragma unroll
            for (int nf = 0; nf < 4; nf++)
                mma_bf16(acc[mf][nf][0], acc[mf][nf][1], acc[mf][nf][2], acc[mf][nf][3],
                         af[mf][0], af[mf][1], af[mf][2], af[mf][3],
                         bf[nf][0], bf[nf][1]);
        if (kt + 1 < KT) stash((kt + 1) & 1);
        __syncthreads();
    }

    // epilogue: direct float2 stores
    const long long m0 = (long long)blockIdx.y * 128;
    const int n0 = blockIdx.x * 128;
    float* Cp = C + (long long)bb * sC;
    const float* Rp = resid ? (resid + (long long)bb * sC) : nullptr;
    const float* bp = bias + (long long)bb * N + n0;
    #pragma unroll
    for (int mf = 0; mf < 4; mf++) {
        long long r0 = m0 + (wm * 4 + mf) * 16 + g;
        #pragma unroll
        for (int nf = 0; nf < 4; nf++) {
            int col = (wn * 4 + nf) * 8 + 2 * t;
            float2 bv = *(const float2*)(bp + col);
            long long o0 = r0 * N + n0 + col;
            long long o1 = (r0 + 8) * N + n0 + col;
            float2 v0 = make_float2(acc[mf][nf][0] + bv.x, acc[mf][nf][1] + bv.y);
            float2 v1 = make_float2(acc[mf][nf][2] + bv.x, acc[mf][nf][3] + bv.y);
            if (Rp) {
                float2 q0 = *(const float2*)(Rp + o0);
                float2 q1 = *(const float2*)(Rp + o1);
                v0.x += q0.x; v0.y += q0.y;
                v1.x += q1.x; v1.y += q1.y;
            }
            *(float2*)(Cp + o0) = v0;
            *(float2*)(Cp + o1) = v1;
        }
    }
}

// ---------------- 6. GRU scan: SMEM-staged, coalesced ----------------
// grid = NB * (DI/256) = 20 blocks, 256 threads; each thread owns one d column.
#define SCH 16
__global__ __launch_bounds__(256) void scan_kernel(const float* __restrict__ zh,
                                                   __nv_bfloat16* __restrict__ hsb,
                                                   float* __restrict__ ns) {
    __shared__ float sh[SCH][256];
    __shared__ float sg[SCH][256];
    __shared__ __nv_bfloat16 sO[SCH][256];
    const int b = blockIdx.x / (DI / 256);
    const int d0 = (blockIdx.x % (DI / 256)) * 256;
    const int tid = threadIdx.x;
    const float* zb = zh + (long long)b * SEQ * D2;
    __nv_bfloat16* hb = hsb + (long long)b * SEQ * DI;
    float h = 0.f;
    for (int s0 = 0; s0 < SEQ; s0 += SCH) {
        #pragma unroll
        for (int i = 0; i < 4; i++) {
            int lin = i * 256 + tid;
            int row = lin >> 6;
            int c4 = (lin & 63) * 4;
            const float* rp = zb + (long long)(s0 + row) * D2 + d0 + c4;
            *(float4*)&sh[row][c4] = *(const float4*)rp;
            *(float4*)&sg[row][c4] = *(const float4*)(rp + DI);
        }
        __syncthreads();
        // precompute out-of-chain terms, then 1-FMA chain
        float a[SCH], w[SCH];
        #pragma unroll
        for (int s = 0; s < SCH; s++) {
            float z = 1.f / (1.f + __expf(-sg[s][tid]));
            float x = sh[s][tid];
            float ht = (x >= 0.f) ? (x + 0.5f) : (1.f / (1.f + __expf(-x)));
            a[s] = 1.0f - z;
            w[s] = z * ht;
        }
        #pragma unroll
        for (int s = 0; s < SCH; s++) {
            h = fmaf(h, a[s], w[s]);
            sO[s][tid] = __float2bfloat16(h);
        }
        __syncthreads();
        #pragma unroll
        for (int i = 0; i < 2; i++) {
            int lin = i * 256 + tid;
            int row = lin >> 5;
            int c = (lin & 31) * 8;
            *(uint4*)(hb + (long long)(s0 + row) * DI + d0 + c) = *(uint4*)&sO[row][c];
        }
        __syncthreads();
    }
    ns[b * DI + d0 + tid] = h;
}

__global__ void aux_kernel(float* __restrict__ out, long long off) { out[off] = 0.0f; }

// ---------------- launch ----------------
extern "C" void kernel_launch(void* const* d_in, const int* in_sizes, int n_in,
                              void* d_out, int out_size) {
    const float* inputs   = (const float*)d_in[0];
    const float* norm_w   = (const float*)d_in[1];
    const float* router_w = (const float*)d_in[2];
    const float* router_b = (const float*)d_in[3];
    const float* w_in     = (const float*)d_in[4];
    const float* b_in     = (const float*)d_in[5];
    const float* w_out    = (const float*)d_in[6];
    const float* b_out    = (const float*)d_in[7];
    float* out = (float*)d_out;

    __nv_bfloat16 *xnh, *WiT, *WoT, *hs;
    float *partial, *pooled, *probs, *bi, *bo, *zh;
    cudaGetSymbolAddress((void**)&xnh, g_xnh);
    cudaGetSymbolAddress((void**)&partial, g_partial);
    cudaGetSymbolAddress((void**)&pooled, g_pooled);
    cudaGetSymbolAddress((void**)&probs, g_probs);
    cudaGetSymbolAddress((void**)&WiT, g_WiT);
    cudaGetSymbolAddress((void**)&bi, g_bi);
    cudaGetSymbolAddress((void**)&WoT, g_WoT);
    cudaGetSymbolAddress((void**)&bo, g_bo);
    cudaGetSymbolAddress((void**)&zh, g_zh);
    cudaGetSymbolAddress((void**)&hs, g_hs);

    rmsnorm_kernel<<<NB * SEQ, 256>>>(inputs, norm_w, xnh);
    pool1_kernel<<<NB * 32, 1024>>>(xnh, partial);
    pool2_kernel<<<NB, 1024>>>(partial, pooled);
    router_kernel<<<1, 128>>>(pooled, router_w, router_b, probs);

    {
        dim3 blk(32, 8);
        dim3 g1(D2 / 32, HID / 32);
        mixT_kernel<<<g1, blk>>>(WiT, w_in, probs, HID, D2);
        dim3 g2(HID / 32, DI / 32);
        mixT_kernel<<<g2, blk>>>(WoT, w_out, probs, DI, HID);
        mixv_kernel<<<(NB * D2 + 255) / 256, 256>>>(bi, b_in, probs, D2);
        mixv_kernel<<<(NB * HID + 255) / 256, 256>>>(bo, b_out, probs, HID);
    }

    {   // GEMM1: zh = xnh @ WiT^T + bi   (M=4096, N=2560, K=1024)
        dim3 grid(D2 / 128, SEQ / 128, NB);
        hgemm_kernel<<<grid, 256>>>(xnh, WiT, bi, nullptr, zh, HID, D2,
                                    (long long)SEQ * HID, (long long)HID * D2,
                                    (long long)SEQ * D2);
    }

    scan_kernel<<<NB * (DI / 256), 256>>>(zh, hs, out + (long long)NB * SEQ * HID);

    {   // GEMM2: out = hs @ WoT^T + bo + inputs   (M=4096, N=1024, K=1280)
        dim3 grid(HID / 128, SEQ / 128, NB);
        hgemm_kernel<<<grid, 256>>>(hs, WoT, bo, inputs, out, DI, HID,
                                    (long long)SEQ * DI, (long long)DI * HID,
                                    (long long)SEQ * HID);
    }

    aux_kernel<<<1, 1>>>(out, (long long)out_size - 1);
}

// round 5
// speedup vs baseline: 8.0927x; 3.5217x over previous
#include <cuda_runtime.h>
#include <cuda_bf16.h>
#include <math.h>
#include <stdint.h>

#define HID 1024
#define NE 3
#define DI 1280
#define D2 2560
#define NB 4
#define SEQ 4096
#define EPSV 1e-6f
#define NCH 32          // scan chunks
#define CH  128         // steps per chunk

// ---------------- scratch (device globals) ----------------
__device__ __nv_bfloat16 g_xnh[(size_t)NB * SEQ * HID];
__device__ float g_partial[NB * 32 * HID];
__device__ float g_pooled[NB * HID];
__device__ float g_probs[NB * NE];
__device__ __nv_bfloat16 g_WiT[(size_t)NB * HID * D2];
__device__ float g_bi[NB * D2];
__device__ __nv_bfloat16 g_WoT[(size_t)NB * DI * HID];
__device__ float g_bo[NB * HID];
__device__ float g_zh[(size_t)NB * SEQ * D2];
__device__ __nv_bfloat16 g_hs[(size_t)NB * SEQ * DI];
__device__ float g_cA[NB * NCH * DI];
__device__ float g_cW[NB * NCH * DI];
__device__ float g_h0[NB * NCH * DI];

// ---------------- PTX helpers ----------------
__device__ __forceinline__ uint32_t smem_u32(const void* p) {
    uint32_t a;
    asm("{ .reg .u64 t; cvta.to.shared.u64 t, %1; cvt.u32.u64 %0, t; }" : "=r"(a) : "l"(p));
    return a;
}
__device__ __forceinline__ void cpa16(uint32_t dst, const void* src) {
    asm volatile("{\n .reg .u64 g;\n cvta.to.global.u64 g, %1;\n"
                 " cp.async.cg.shared.global [%0], [g], 16;\n}"
                 :: "r"(dst), "l"(src));
}
__device__ __forceinline__ void ldsm_x4(uint32_t& r0, uint32_t& r1, uint32_t& r2, uint32_t& r3,
                                        uint32_t addr) {
    asm volatile("ldmatrix.sync.aligned.m8n8.x4.shared.b16 {%0,%1,%2,%3}, [%4];"
                 : "=r"(r0), "=r"(r1), "=r"(r2), "=r"(r3) : "r"(addr));
}
__device__ __forceinline__ void mma_bf16(float& d0, float& d1, float& d2, float& d3,
                                         uint32_t a0, uint32_t a1, uint32_t a2, uint32_t a3,
                                         uint32_t b0, uint32_t b1) {
    asm volatile("mma.sync.aligned.m16n8k16.row.col.f32.bf16.bf16.f32 "
                 "{%0,%1,%2,%3}, {%4,%5,%6,%7}, {%8,%9}, {%0,%1,%2,%3};"
                 : "+f"(d0), "+f"(d1), "+f"(d2), "+f"(d3)
                 : "r"(a0), "r"(a1), "r"(a2), "r"(a3), "r"(b0), "r"(b1));
}

// ---------------- 1. RMSNorm -> bf16 ----------------
__global__ void rmsnorm_kernel(const float* __restrict__ in,
                               const float* __restrict__ nw,
                               __nv_bfloat16* __restrict__ xnh) {
    long long row = blockIdx.x;
    const float4* ip = (const float4*)(in + row * HID);
    float4 v = ip[threadIdx.x];
    float ss = v.x * v.x + v.y * v.y + v.z * v.z + v.w * v.w;
    #pragma unroll
    for (int o = 16; o > 0; o >>= 1) ss += __shfl_xor_sync(0xffffffffu, ss, o);
    __shared__ float ws[8];
    int wid = threadIdx.x >> 5, lid = threadIdx.x & 31;
    if (lid == 0) ws[wid] = ss;
    __syncthreads();
    if (wid == 0) {
        float t = (lid < 8) ? ws[lid] : 0.f;
        #pragma unroll
        for (int o = 4; o > 0; o >>= 1) t += __shfl_xor_sync(0xffffffffu, t, o);
        if (lid == 0) ws[0] = t;
    }
    __syncthreads();
    float scale = rsqrtf(ws[0] * (1.0f / HID) + EPSV);
    float4 w = ((const float4*)nw)[threadIdx.x];
    __nv_bfloat162 p0 = __floats2bfloat162_rn(v.x * scale * w.x, v.y * scale * w.y);
    __nv_bfloat162 p1 = __floats2bfloat162_rn(v.z * scale * w.z, v.w * scale * w.w);
    uint2 u;
    u.x = *(uint32_t*)&p0;
    u.y = *(uint32_t*)&p1;
    *(uint2*)(xnh + row * HID + threadIdx.x * 4) = u;
}

// ---------------- 2. pooled mean ----------------
__global__ void pool1_kernel(const __nv_bfloat16* __restrict__ xnh, float* __restrict__ partial) {
    int b = blockIdx.x >> 5;
    int c = blockIdx.x & 31;
    int h = threadIdx.x;
    const __nv_bfloat16* base = xnh + ((long long)b * SEQ + (long long)c * 128) * HID + h;
    float s = 0.f;
    #pragma unroll 8
    for (int i = 0; i < 128; i++) s += __bfloat162float(base[(long long)i * HID]);
    partial[(long long)blockIdx.x * HID + h] = s;
}
__global__ void pool2_kernel(const float* __restrict__ partial, float* __restrict__ pooled) {
    int b = blockIdx.x, h = threadIdx.x;
    float s = 0.f;
    #pragma unroll
    for (int c = 0; c < 32; c++) s += partial[(long long)(b * 32 + c) * HID + h];
    pooled[b * HID + h] = s * (1.0f / SEQ);
}

// ---------------- 3. router ----------------
__global__ void router_kernel(const float* __restrict__ pooled,
                              const float* __restrict__ rw,
                              const float* __restrict__ rb,
                              float* __restrict__ probs) {
    __shared__ float sm[12][128];
    float acc[12];
    #pragma unroll
    for (int i = 0; i < 12; i++) acc[i] = 0.f;
    for (int h = threadIdx.x; h < HID; h += 128) {
        float r0 = rw[h * NE + 0], r1 = rw[h * NE + 1], r2 = rw[h * NE + 2];
        #pragma unroll
        for (int b = 0; b < NB; b++) {
            float p = pooled[b * HID + h];
            acc[b * 3 + 0] += p * r0;
            acc[b * 3 + 1] += p * r1;
            acc[b * 3 + 2] += p * r2;
        }
    }
    #pragma unroll
    for (int i = 0; i < 12; i++) sm[i][threadIdx.x] = acc[i];
    __syncthreads();
    for (int st = 64; st > 0; st >>= 1) {
        if (threadIdx.x < st) {
            #pragma unroll
            for (int i = 0; i < 12; i++) sm[i][threadIdx.x] += sm[i][threadIdx.x + st];
        }
        __syncthreads();
    }
    if (threadIdx.x < NB) {
        int b = threadIdx.x;
        float l0 = sm[b * 3 + 0][0] + rb[0];
        float l1 = sm[b * 3 + 1][0] + rb[1];
        float l2 = sm[b * 3 + 2][0] + rb[2];
        float mx = fmaxf(l0, fmaxf(l1, l2));
        float e0 = expf(l0 - mx), e1 = expf(l1 - mx), e2 = expf(l2 - mx);
        float inv = 1.0f / (e0 + e1 + e2);
        probs[b * 3 + 0] = e0 * inv;
        probs[b * 3 + 1] = e1 * inv;
        probs[b * 3 + 2] = e2 * inv;
    }
}

// ---------------- 4. fused mixing (weights transposed->bf16, biases fp32) ----------------
__device__ __forceinline__ void mixT_body(__nv_bfloat16* __restrict__ dst,
                                          const float* __restrict__ src,
                                          const float* __restrict__ probs,
                                          int K, int N, int bx, int by, int tid) {
    __shared__ float t0[32][33], t1[32][33], t2[32][33];
    int tx = tid & 31, ty = tid >> 5;
    int k0 = by * 32, n0 = bx * 32;
    long long eSz = (long long)K * N;
    #pragma unroll
    for (int i = 0; i < 4; i++) {
        int k = k0 + ty + i * 8;
        long long o = (long long)k * N + n0 + tx;
        t0[ty + i * 8][tx] = src[o];
        t1[ty + i * 8][tx] = src[eSz + o];
        t2[ty + i * 8][tx] = src[2 * eSz + o];
    }
    __syncthreads();
    #pragma unroll
    for (int b = 0; b < NB; b++) {
        float p0 = probs[b * 3 + 0], p1 = probs[b * 3 + 1], p2 = probs[b * 3 + 2];
        #pragma unroll
        for (int i = 0; i < 4; i++) {
            int n = n0 + ty + i * 8;
            int k = k0 + tx;
            float v = p0 * t0[tx][ty + i * 8] + p1 * t1[tx][ty + i * 8] + p2 * t2[tx][ty + i * 8];
            dst[(long long)b * eSz + (long long)n * K + k] = __float2bfloat16(v);
        }
    }
}

__global__ void mix_all_kernel(__nv_bfloat16* __restrict__ WiT, __nv_bfloat16* __restrict__ WoT,
                               float* __restrict__ bi, float* __restrict__ bo,
                               const float* __restrict__ w_in, const float* __restrict__ w_out,
                               const float* __restrict__ b_in, const float* __restrict__ b_out,
                               const float* __restrict__ probs) {
    int bid = blockIdx.x, tid = threadIdx.x;
    if (bid < 2560) {                      // WiT: K=HID, N=D2, 80 x 32 tiles
        mixT_body(WiT, w_in, probs, HID, D2, bid % 80, bid / 80, tid);
    } else if (bid < 3840) {               // WoT: K=DI, N=HID, 32 x 40 tiles
        int id = bid - 2560;
        mixT_body(WoT, w_out, probs, DI, HID, id % 32, id / 32, tid);
    } else if (bid < 3880) {               // bi: NB*D2 = 10240
        int i = (bid - 3840) * 256 + tid;
        if (i < NB * D2) {
            int b = i / D2, j = i - b * D2;
            bi[i] = probs[b * 3 + 0] * b_in[j] + probs[b * 3 + 1] * b_in[D2 + j] +
                    probs[b * 3 + 2] * b_in[2 * D2 + j];
        }
    } else {                               // bo: NB*HID = 4096
        int i = (bid - 3880) * 256 + tid;
        if (i < NB * HID) {
            int b = i / HID, j = i - b * HID;
            bo[i] = probs[b * 3 + 0] * b_out[j] + probs[b * 3 + 1] * b_out[HID + j] +
                    probs[b * 3 + 2] * b_out[2 * HID + j];
        }
    }
}

// ---------------- 5/7. bf16 GEMM: cp.async 4-stage + ldmatrix ----------------
// C[b](MxN) = A[b](MxK bf16 row-major) @ B[b](NxK bf16 K-major)^T + bias (+resid)
// BM=BN=128, BK=32, 256 threads (8 warps), warp tile 64x32.
#define STAGE_BYTES 16384

__global__ __launch_bounds__(256, 2) void hgemm_kernel(
    const __nv_bfloat16* __restrict__ A, const __nv_bfloat16* __restrict__ B,
    const float* __restrict__ bias, const float* __restrict__ resid,
    float* __restrict__ C, int K, int N,
    long long sA, long long sB, long long sC) {
    extern __shared__ uint8_t dsm[];
    const uint32_t smb = smem_u32(dsm);
    const int tid = threadIdx.x;
    const int wid = tid >> 5;
    const int lane = tid & 31;
    const int bb = blockIdx.z;

    const __nv_bfloat16* Abase = A + (long long)bb * sA + (long long)blockIdx.y * 128 * K;
    const __nv_bfloat16* Bbase = B + (long long)bb * sB + (long long)blockIdx.x * 128 * K;

    const int g = lane >> 2, t = lane & 3;
    const int wm = wid >> 2;   // 0..1
    const int wn = wid & 3;    // 0..3

    float acc[4][4][4];
    #pragma unroll
    for (int i = 0; i < 4; i++)
        #pragma unroll
        for (int j = 0; j < 4; j++)
            #pragma unroll
            for (int q = 0; q < 4; q++) acc[i][j][q] = 0.f;

    const int KT = K >> 5;

    auto issue = [&](int kt, int stg) {
        uint32_t sb = smb + stg * STAGE_BYTES;
        #pragma unroll
        for (int u = 0; u < 2; u++) {
            int c = tid + u * 256;
            int row = c >> 2, k16 = c & 3;
            int phys = k16 ^ ((row >> 1) & 3);
            uint32_t off = row * 64 + phys * 16;
            cpa16(sb + off, Abase + (long long)row * K + kt * 32 + k16 * 8);
            cpa16(sb + 8192 + off, Bbase + (long long)row * K + kt * 32 + k16 * 8);
        }
    };

    issue(0, 0);
    asm volatile("cp.async.commit_group;" ::: "memory");
    issue(1, 1);
    asm volatile("cp.async.commit_group;" ::: "memory");
    issue(2, 2);
    asm volatile("cp.async.commit_group;" ::: "memory");

    // ldmatrix lane addressing
    const int mi = lane >> 3;          // matrix index 0..3
    const int l7 = lane & 7;

    for (int kt = 0; kt < KT; kt++) {
        asm volatile("cp.async.wait_group 2;" ::: "memory");
        __syncthreads();
        if (kt + 3 < KT) issue(kt + 3, (kt + 3) & 3);
        asm volatile("cp.async.commit_group;" ::: "memory");

        uint32_t sa = smb + (kt & 3) * STAGE_BYTES;
        uint32_t sbm = sa + 8192;
        #pragma unroll
        for (int ks = 0; ks < 2; ks++) {
            uint32_t af[4][4], bf[4][2];
            #pragma unroll
            for (int mf = 0; mf < 4; mf++) {
                int row = wm * 64 + mf * 16 + l7 + (mi & 1) * 8;
                int chunk = 2 * ks + (mi >> 1);
                int phys = chunk ^ ((row >> 1) & 3);
                ldsm_x4(af[mf][0], af[mf][1], af[mf][2], af[mf][3],
                        sa + row * 64 + phys * 16);
            }
            #pragma unroll
            for (int p = 0; p < 2; p++) {
                int row = wn * 32 + p * 16 + l7 + (mi >> 1) * 8;
                int chunk = 2 * ks + (mi & 1);
                int phys = chunk ^ ((row >> 1) & 3);
                uint32_t r0, r1, r2, r3;
                ldsm_x4(r0, r1, r2, r3, sbm + row * 64 + phys * 16);
                bf[2 * p][0] = r0; bf[2 * p][1] = r1;
                bf[2 * p + 1][0] = r2; bf[2 * p + 1][1] = r3;
            }
            #pragma unroll
            for (int mf = 0; mf < 4; mf++)
                #pragma unroll
                for (int nf = 0; nf < 4; nf++)
                    mma_bf16(acc[mf][nf][0], acc[mf][nf][1], acc[mf][nf][2], acc[mf][nf][3],
                             af[mf][0], af[mf][1], af[mf][2], af[mf][3],
                             bf[nf][0], bf[nf][1]);
        }
    }

    // epilogue
    const long long m0 = (long long)blockIdx.y * 128;
    const int n0 = blockIdx.x * 128;
    float* Cp = C + (long long)bb * sC;
    const float* Rp = resid ? (resid + (long long)bb * sC) : nullptr;
    const float* bp = bias + (long long)bb * N + n0;
    #pragma unroll
    for (int mf = 0; mf < 4; mf++) {
        long long r0 = m0 + (wm * 4 + mf) * 16 + g;
        #pragma unroll
        for (int nf = 0; nf < 4; nf++) {
            int col = (wn * 4 + nf) * 8 + 2 * t;
            float2 bv = *(const float2*)(bp + col);
            long long o0 = r0 * N + n0 + col;
            long long o1 = (r0 + 8) * N + n0 + col;
            float2 v0 = make_float2(acc[mf][nf][0] + bv.x, acc[mf][nf][1] + bv.y);
            float2 v1 = make_float2(acc[mf][nf][2] + bv.x, acc[mf][nf][3] + bv.y);
            if (Rp) {
                float2 q0 = *(const float2*)(Rp + o0);
                float2 q1 = *(const float2*)(Rp + o1);
                v0.x += q0.x; v0.y += q0.y;
                v1.x += q1.x; v1.y += q1.y;
            }
            *(float2*)(Cp + o0) = v0;
            *(float2*)(Cp + o1) = v1;
        }
    }
}

// ---------------- 6. chunked GRU scan ----------------
// a_s = 1-z, w_s = z*ht ; h_s = a_s*h_{s-1} + w_s
__device__ __forceinline__ void gru_aw(float hid, float gat, float& a, float& w) {
    float z = __fdividef(1.f, 1.f + __expf(-gat));
    float ht = (hid >= 0.f) ? (hid + 0.5f) : __fdividef(1.f, 1.f + __expf(-hid));
    a = 1.0f - z;
    w = z * ht;
}

// 6a: per-chunk composites. grid = NB * 5 * NCH, block 256.
__global__ __launch_bounds__(256) void scan_a_kernel(const float* __restrict__ zh,
                                                     float* __restrict__ cA,
                                                     float* __restrict__ cW) {
    __shared__ float sh[16][256], sg[16][256];
    int bid = blockIdx.x;
    int b = bid / (5 * NCH);
    int rem = bid % (5 * NCH);
    int gA = rem / NCH, c = rem % NCH;
    int d0 = gA * 256;
    const int tid = threadIdx.x;
    const float* zb = zh + (long long)b * SEQ * D2;
    float Acc = 1.f, Wcc = 0.f;
    for (int s0 = c * CH; s0 < (c + 1) * CH; s0 += 16) {
        #pragma unroll
        for (int i = 0; i < 4; i++) {
            int lin = i * 256 + tid;
            int row = lin >> 6;
            int c4 = (lin & 63) * 4;
            const float* rp = zb + (long long)(s0 + row) * D2 + d0 + c4;
            *(float4*)&sh[row][c4] = *(const float4*)rp;
            *(float4*)&sg[row][c4] = *(const float4*)(rp + DI);
        }
        __syncthreads();
        #pragma unroll
        for (int s = 0; s < 16; s++) {
            float a, w;
            gru_aw(sh[s][tid], sg[s][tid], a, w);
            Acc = a * Acc;
            Wcc = fmaf(a, Wcc, w);
        }
        __syncthreads();
    }
    int o = (b * NCH + c) * DI + d0 + tid;
    cA[o] = Acc;
    cW[o] = Wcc;
}

// 6b: chunk prefix. grid = NB*5, block 256.
__global__ void scan_b_kernel(const float* __restrict__ cA, const float* __restrict__ cW,
                              float* __restrict__ h0) {
    int b = blockIdx.x / 5, gA = blockIdx.x % 5;
    int d = gA * 256 + threadIdx.x;
    float h = 0.f;
    #pragma unroll
    for (int c = 0; c < NCH; c++) {
        int o = (b * NCH + c) * DI + d;
        h0[o] = h;
        h = fmaf(cA[o], h, cW[o]);
    }
}

// 6c: replay within chunk, write hs bf16 (+ ns on last chunk). grid = NB*5*NCH.
__global__ __launch_bounds__(256) void scan_c_kernel(const float* __restrict__ zh,
                                                     const float* __restrict__ h0,
                                                     __nv_bfloat16* __restrict__ hsb,
                                                     float* __restrict__ ns) {
    __shared__ float sh[16][256], sg[16][256];
    __shared__ __nv_bfloat16 sO[16][256];
    int bid = blockIdx.x;
    int b = bid / (5 * NCH);
    int rem = bid % (5 * NCH);
    int gA = rem / NCH, c = rem % NCH;
    int d0 = gA * 256;
    const int tid = threadIdx.x;
    const float* zb = zh + (long long)b * SEQ * D2;
    __nv_bfloat16* hb = hsb + (long long)b * SEQ * DI;
    float h = h0[(b * NCH + c) * DI + d0 + tid];
    for (int s0 = c * CH; s0 < (c + 1) * CH; s0 += 16) {
        #pragma unroll
        for (int i = 0; i < 4; i++) {
            int lin = i * 256 + tid;
            int row = lin >> 6;
            int c4 = (lin & 63) * 4;
            const float* rp = zb + (long long)(s0 + row) * D2 + d0 + c4;
            *(float4*)&sh[row][c4] = *(const float4*)rp;
            *(float4*)&sg[row][c4] = *(const float4*)(rp + DI);
        }
        __syncthreads();
        #pragma unroll
        for (int s = 0; s < 16; s++) {
            float a, w;
            gru_aw(sh[s][tid], sg[s][tid], a, w);
            h = fmaf(a, h, w);
            sO[s][tid] = __float2bfloat16(h);
        }
        __syncthreads();
        #pragma unroll
        for (int i = 0; i < 2; i++) {
            int lin = i * 256 + tid;
            int row = lin >> 5;
            int cc = (lin & 31) * 8;
            *(uint4*)(hb + (long long)(s0 + row) * DI + d0 + cc) = *(uint4*)&sO[row][cc];
        }
        __syncthreads();
    }
    if (c == NCH - 1) ns[b * DI + d0 + tid] = h;
}

__global__ void aux_kernel(float* __restrict__ out, long long off) { out[off] = 0.0f; }

// ---------------- launch ----------------
extern "C" void kernel_launch(void* const* d_in, const int* in_sizes, int n_in,
                              void* d_out, int out_size) {
    const float* inputs   = (const float*)d_in[0];
    const float* norm_w   = (const float*)d_in[1];
    const float* router_w = (const float*)d_in[2];
    const float* router_b = (const float*)d_in[3];
    const float* w_in     = (const float*)d_in[4];
    const float* b_in     = (const float*)d_in[5];
    const float* w_out    = (const float*)d_in[6];
    const float* b_out    = (const float*)d_in[7];
    float* out = (float*)d_out;

    __nv_bfloat16 *xnh, *WiT, *WoT, *hs;
    float *partial, *pooled, *probs, *bi, *bo, *zh, *cA, *cW, *h0;
    cudaGetSymbolAddress((void**)&xnh, g_xnh);
    cudaGetSymbolAddress((void**)&partial, g_partial);
    cudaGetSymbolAddress((void**)&pooled, g_pooled);
    cudaGetSymbolAddress((void**)&probs, g_probs);
    cudaGetSymbolAddress((void**)&WiT, g_WiT);
    cudaGetSymbolAddress((void**)&bi, g_bi);
    cudaGetSymbolAddress((void**)&WoT, g_WoT);
    cudaGetSymbolAddress((void**)&bo, g_bo);
    cudaGetSymbolAddress((void**)&zh, g_zh);
    cudaGetSymbolAddress((void**)&hs, g_hs);
    cudaGetSymbolAddress((void**)&cA, g_cA);
    cudaGetSymbolAddress((void**)&cW, g_cW);
    cudaGetSymbolAddress((void**)&h0, g_h0);

    const int DYN = 4 * STAGE_BYTES;  // 64 KB
    cudaFuncSetAttribute(hgemm_kernel, cudaFuncAttributeMaxDynamicSharedMemorySize, DYN);

    // 1..4
    rmsnorm_kernel<<<NB * SEQ, 256>>>(inputs, norm_w, xnh);
    pool1_kernel<<<NB * 32, 1024>>>(xnh, partial);
    pool2_kernel<<<NB, 1024>>>(partial, pooled);
    router_kernel<<<1, 128>>>(pooled, router_w, router_b, probs);
    // 5: fused mixing
    mix_all_kernel<<<3896, 256>>>(WiT, WoT, bi, bo, w_in, w_out, b_in, b_out, probs);
    // 6: GEMM1 (profiled launch)
    {
        dim3 grid(D2 / 128, SEQ / 128, NB);
        hgemm_kernel<<<grid, 256, DYN>>>(xnh, WiT, bi, nullptr, zh, HID, D2,
                                         (long long)SEQ * HID, (long long)HID * D2,
                                         (long long)SEQ * D2);
    }
    // 7..9: chunked scan
    scan_a_kernel<<<NB * 5 * NCH, 256>>>(zh, cA, cW);
    scan_b_kernel<<<NB * 5, 256>>>(cA, cW, h0);
    scan_c_kernel<<<NB * 5 * NCH, 256>>>(zh, h0, hs, out + (long long)NB * SEQ * HID);
    // 10: GEMM2
    {
        dim3 grid(HID / 128, SEQ / 128, NB);
        hgemm_kernel<<<grid, 256, DYN>>>(hs, WoT, bo, inputs, out, DI, HID,
                                         (long long)SEQ * DI, (long long)DI * HID,
                                         (long long)SEQ * HID);
    }
    aux_kernel<<<1, 1>>>(out, (long long)out_size - 1);
}

// round 6
// speedup vs baseline: 8.8837x; 1.0977x over previous
#include <cuda_runtime.h>
#include <cuda_bf16.h>
#include <cuda_fp16.h>
#include <math.h>
#include <stdint.h>

#define HID 1024
#define NE 3
#define DI 1280
#define D2 2560
#define NB 4
#define SEQ 4096
#define EPSV 1e-6f
#define NCH 32
#define CH  128

// ---------------- scratch (device globals) ----------------
__device__ __nv_bfloat16 g_xnh[(size_t)NB * SEQ * HID];
__device__ float g_partial[NB * 32 * HID];
__device__ float g_probs[NB * NE];
__device__ __nv_bfloat16 g_WiT[(size_t)NB * HID * D2];   // permuted rows (hid/gate interleave)
__device__ float g_bi[NB * D2];                          // permuted to match
__device__ __nv_bfloat16 g_WoT[(size_t)NB * DI * HID];
__device__ float g_bo[NB * HID];
__device__ __half2 g_aw[(size_t)NB * SEQ * DI];          // (a, w) pairs, 84 MB
__device__ __nv_bfloat16 g_hs[(size_t)NB * SEQ * DI];
__device__ float g_cA[NB * NCH * DI];
__device__ float g_cW[NB * NCH * DI];
__device__ float g_h0[NB * NCH * DI];

// ---------------- PTX helpers ----------------
__device__ __forceinline__ uint32_t smem_u32(const void* p) {
    uint32_t a;
    asm("{ .reg .u64 t; cvta.to.shared.u64 t, %1; cvt.u32.u64 %0, t; }" : "=r"(a) : "l"(p));
    return a;
}
__device__ __forceinline__ void cpa16(uint32_t dst, const void* src) {
    asm volatile("{\n .reg .u64 g;\n cvta.to.global.u64 g, %1;\n"
                 " cp.async.cg.shared.global [%0], [g], 16;\n}"
                 :: "r"(dst), "l"(src));
}
__device__ __forceinline__ void ldsm_x4(uint32_t& r0, uint32_t& r1, uint32_t& r2, uint32_t& r3,
                                        uint32_t addr) {
    asm volatile("ldmatrix.sync.aligned.m8n8.x4.shared.b16 {%0,%1,%2,%3}, [%4];"
                 : "=r"(r0), "=r"(r1), "=r"(r2), "=r"(r3) : "r"(addr));
}
__device__ __forceinline__ void mma_bf16(float& d0, float& d1, float& d2, float& d3,
                                         uint32_t a0, uint32_t a1, uint32_t a2, uint32_t a3,
                                         uint32_t b0, uint32_t b1) {
    asm volatile("mma.sync.aligned.m16n8k16.row.col.f32.bf16.bf16.f32 "
                 "{%0,%1,%2,%3}, {%4,%5,%6,%7}, {%8,%9}, {%0,%1,%2,%3};"
                 : "+f"(d0), "+f"(d1), "+f"(d2), "+f"(d3)
                 : "r"(a0), "r"(a1), "r"(a2), "r"(a3), "r"(b0), "r"(b1));
}

// ---------------- 1. RMSNorm -> bf16 ----------------
__global__ void rmsnorm_kernel(const float* __restrict__ in,
                               const float* __restrict__ nw,
                               __nv_bfloat16* __restrict__ xnh) {
    long long row = blockIdx.x;
    const float4* ip = (const float4*)(in + row * HID);
    float4 v = ip[threadIdx.x];
    float ss = v.x * v.x + v.y * v.y + v.z * v.z + v.w * v.w;
    #pragma unroll
    for (int o = 16; o > 0; o >>= 1) ss += __shfl_xor_sync(0xffffffffu, ss, o);
    __shared__ float ws[8];
    int wid = threadIdx.x >> 5, lid = threadIdx.x & 31;
    if (lid == 0) ws[wid] = ss;
    __syncthreads();
    if (wid == 0) {
        float t = (lid < 8) ? ws[lid] : 0.f;
        #pragma unroll
        for (int o = 4; o > 0; o >>= 1) t += __shfl_xor_sync(0xffffffffu, t, o);
        if (lid == 0) ws[0] = t;
    }
    __syncthreads();
    float scale = rsqrtf(ws[0] * (1.0f / HID) + EPSV);
    float4 w = ((const float4*)nw)[threadIdx.x];
    __nv_bfloat162 p0 = __floats2bfloat162_rn(v.x * scale * w.x, v.y * scale * w.y);
    __nv_bfloat162 p1 = __floats2bfloat162_rn(v.z * scale * w.z, v.w * scale * w.w);
    uint2 u;
    u.x = *(uint32_t*)&p0;
    u.y = *(uint32_t*)&p1;
    *(uint2*)(xnh + row * HID + threadIdx.x * 4) = u;
}

// ---------------- 2. pool partial ----------------
__global__ void pool1_kernel(const __nv_bfloat16* __restrict__ xnh, float* __restrict__ partial) {
    int b = blockIdx.x >> 5;
    int c = blockIdx.x & 31;
    int h = threadIdx.x;
    const __nv_bfloat16* base = xnh + ((long long)b * SEQ + (long long)c * 128) * HID + h;
    float s = 0.f;
    #pragma unroll 8
    for (int i = 0; i < 128; i++) s += __bfloat162float(base[(long long)i * HID]);
    partial[(long long)blockIdx.x * HID + h] = s;
}

// ---------------- 3. fused pool2 + router (1 block, 1024 threads) ----------------
__global__ void pool_router_kernel(const float* __restrict__ partial,
                                   const float* __restrict__ rw,
                                   const float* __restrict__ rb,
                                   float* __restrict__ probs) {
    __shared__ float red[12][32];
    __shared__ float logits[12];
    int h = threadIdx.x;
    int wid = h >> 5, lid = h & 31;
    float p[NB];
    #pragma unroll
    for (int b = 0; b < NB; b++) {
        float s = 0.f;
        #pragma unroll
        for (int c = 0; c < 32; c++) s += partial[(long long)(b * 32 + c) * HID + h];
        p[b] = s * (1.0f / SEQ);
    }
    float r0 = rw[h * NE + 0], r1 = rw[h * NE + 1], r2 = rw[h * NE + 2];
    float acc[12];
    #pragma unroll
    for (int b = 0; b < NB; b++) {
        acc[b * 3 + 0] = p[b] * r0;
        acc[b * 3 + 1] = p[b] * r1;
        acc[b * 3 + 2] = p[b] * r2;
    }
    #pragma unroll
    for (int i = 0; i < 12; i++) {
        float v = acc[i];
        #pragma unroll
        for (int o = 16; o > 0; o >>= 1) v += __shfl_xor_sync(0xffffffffu, v, o);
        if (lid == 0) red[i][wid] = v;
    }
    __syncthreads();
    if (wid == 0) {
        #pragma unroll
        for (int i = 0; i < 12; i++) {
            float v = red[i][lid];
            #pragma unroll
            for (int o = 16; o > 0; o >>= 1) v += __shfl_xor_sync(0xffffffffu, v, o);
            if (lid == 0) logits[i] = v;
        }
    }
    __syncthreads();
    if (h < NB) {
        int b = h;
        float l0 = logits[b * 3 + 0] + rb[0];
        float l1 = logits[b * 3 + 1] + rb[1];
        float l2 = logits[b * 3 + 2] + rb[2];
        float mx = fmaxf(l0, fmaxf(l1, l2));
        float e0 = expf(l0 - mx), e1 = expf(l1 - mx), e2 = expf(l2 - mx);
        float inv = 1.0f / (e0 + e1 + e2);
        probs[b * 3 + 0] = e0 * inv;
        probs[b * 3 + 1] = e1 * inv;
        probs[b * 3 + 2] = e2 * inv;
    }
}

// ---------------- 4. fused mixing ----------------
// perm != 0: output row r = (n < DI) ? 2n : 2(n-DI)+1  (hid/gate interleave for GEMM1)
__device__ __forceinline__ void mixT_body(__nv_bfloat16* __restrict__ dst,
                                          const float* __restrict__ src,
                                          const float* __restrict__ probs,
                                          int K, int N, int bx, int by, int tid, int perm) {
    __shared__ float t0[32][33], t1[32][33], t2[32][33];
    int tx = tid & 31, ty = tid >> 5;
    int k0 = by * 32, n0 = bx * 32;
    long long eSz = (long long)K * N;
    #pragma unroll
    for (int i = 0; i < 4; i++) {
        int k = k0 + ty + i * 8;
        long long o = (long long)k * N + n0 + tx;
        t0[ty + i * 8][tx] = src[o];
        t1[ty + i * 8][tx] = src[eSz + o];
        t2[ty + i * 8][tx] = src[2 * eSz + o];
    }
    __syncthreads();
    #pragma unroll
    for (int b = 0; b < NB; b++) {
        float p0 = probs[b * 3 + 0], p1 = probs[b * 3 + 1], p2 = probs[b * 3 + 2];
        #pragma unroll
        for (int i = 0; i < 4; i++) {
            int n = n0 + ty + i * 8;
            int k = k0 + tx;
            float v = p0 * t0[tx][ty + i * 8] + p1 * t1[tx][ty + i * 8] + p2 * t2[tx][ty + i * 8];
            long long r = perm ? ((n < DI) ? 2 * n : 2 * (n - DI) + 1) : n;
            dst[(long long)b * eSz + r * K + k] = __float2bfloat16(v);
        }
    }
}

__global__ void mix_all_kernel(__nv_bfloat16* __restrict__ WiT, __nv_bfloat16* __restrict__ WoT,
                               float* __restrict__ bi, float* __restrict__ bo,
                               const float* __restrict__ w_in, const float* __restrict__ w_out,
                               const float* __restrict__ b_in, const float* __restrict__ b_out,
                               const float* __restrict__ probs) {
    int bid = blockIdx.x, tid = threadIdx.x;
    if (bid < 2560) {
        mixT_body(WiT, w_in, probs, HID, D2, bid % 80, bid / 80, tid, 1);
    } else if (bid < 3840) {
        int id = bid - 2560;
        mixT_body(WoT, w_out, probs, DI, HID, id % 32, id / 32, tid, 0);
    } else if (bid < 3880) {
        int i = (bid - 3840) * 256 + tid;
        if (i < NB * D2) {
            int b = i / D2, j = i - b * D2;
            float v = probs[b * 3 + 0] * b_in[j] + probs[b * 3 + 1] * b_in[D2 + j] +
                      probs[b * 3 + 2] * b_in[2 * D2 + j];
            long long r = (j < DI) ? 2 * j : 2 * (j - DI) + 1;   // permute bi to match WiT
            bi[(long long)b * D2 + r] = v;
        }
    } else {
        int i = (bid - 3880) * 256 + tid;
        if (i < NB * HID) {
            int b = i / HID, j = i - b * HID;
            bo[i] = probs[b * 3 + 0] * b_out[j] + probs[b * 3 + 1] * b_out[HID + j] +
                    probs[b * 3 + 2] * b_out[2 * HID + j];
        }
    }
}

// ---------------- 5/7. bf16 GEMM: cp.async 4-stage + ldmatrix ----------------
#define STAGE_BYTES 16384

__global__ __launch_bounds__(256, 2) void hgemm_kernel(
    const __nv_bfloat16* __restrict__ A, const __nv_bfloat16* __restrict__ B,
    const float* __restrict__ bias, const float* __restrict__ resid,
    float* __restrict__ C, __half2* __restrict__ awOut, int K, int N,
    long long sA, long long sB, long long sC) {
    extern __shared__ uint8_t dsm[];
    const uint32_t smb = smem_u32(dsm);
    const int tid = threadIdx.x;
    const int wid = tid >> 5;
    const int lane = tid & 31;
    const int bb = blockIdx.z;

    const __nv_bfloat16* Abase = A + (long long)bb * sA + (long long)blockIdx.y * 128 * K;
    const __nv_bfloat16* Bbase = B + (long long)bb * sB + (long long)blockIdx.x * 128 * K;

    const int g = lane >> 2, t = lane & 3;
    const int wm = wid >> 2;
    const int wn = wid & 3;

    float acc[4][4][4];
    #pragma unroll
    for (int i = 0; i < 4; i++)
        #pragma unroll
        for (int j = 0; j < 4; j++)
            #pragma unroll
            for (int q = 0; q < 4; q++) acc[i][j][q] = 0.f;

    const int KT = K >> 5;

    auto issue = [&](int kt, int stg) {
        uint32_t sb = smb + stg * STAGE_BYTES;
        #pragma unroll
        for (int u = 0; u < 2; u++) {
            int c = tid + u * 256;
            int row = c >> 2, k16 = c & 3;
            int phys = k16 ^ ((row >> 1) & 3);
            uint32_t off = row * 64 + phys * 16;
            cpa16(sb + off, Abase + (long long)row * K + kt * 32 + k16 * 8);
            cpa16(sb + 8192 + off, Bbase + (long long)row * K + kt * 32 + k16 * 8);
        }
    };

    issue(0, 0);
    asm volatile("cp.async.commit_group;" ::: "memory");
    issue(1, 1);
    asm volatile("cp.async.commit_group;" ::: "memory");
    issue(2, 2);
    asm volatile("cp.async.commit_group;" ::: "memory");

    const int mi = lane >> 3;
    const int l7 = lane & 7;

    for (int kt = 0; kt < KT; kt++) {
        asm volatile("cp.async.wait_group 2;" ::: "memory");
        __syncthreads();
        if (kt + 3 < KT) issue(kt + 3, (kt + 3) & 3);
        asm volatile("cp.async.commit_group;" ::: "memory");

        uint32_t sa = smb + (kt & 3) * STAGE_BYTES;
        uint32_t sbm = sa + 8192;
        #pragma unroll
        for (int ks = 0; ks < 2; ks++) {
            uint32_t af[4][4], bf[4][2];
            #pragma unroll
            for (int mf = 0; mf < 4; mf++) {
                int row = wm * 64 + mf * 16 + l7 + (mi & 1) * 8;
                int chunk = 2 * ks + (mi >> 1);
                int phys = chunk ^ ((row >> 1) & 3);
                ldsm_x4(af[mf][0], af[mf][1], af[mf][2], af[mf][3],
                        sa + row * 64 + phys * 16);
            }
            #pragma unroll
            for (int p = 0; p < 2; p++) {
                int row = wn * 32 + p * 16 + l7 + (mi >> 1) * 8;
                int chunk = 2 * ks + (mi & 1);
                int phys = chunk ^ ((row >> 1) & 3);
                uint32_t r0, r1, r2, r3;
                ldsm_x4(r0, r1, r2, r3, sbm + row * 64 + phys * 16);
                bf[2 * p][0] = r0; bf[2 * p][1] = r1;
                bf[2 * p + 1][0] = r2; bf[2 * p + 1][1] = r3;
            }
            #pragma unroll
            for (int mf = 0; mf < 4; mf++)
                #pragma unroll
                for (int nf = 0; nf < 4; nf++)
                    mma_bf16(acc[mf][nf][0], acc[mf][nf][1], acc[mf][nf][2], acc[mf][nf][3],
                             af[mf][0], af[mf][1], af[mf][2], af[mf][3],
                             bf[nf][0], bf[nf][1]);
        }
    }

    const long long m0 = (long long)blockIdx.y * 128;
    const int n0 = blockIdx.x * 128;
    const float* bp = bias + (long long)bb * N + n0;

    if (awOut) {
        // each acc float2 = (hid, gate) pair -> (a, w) half2
        __half2* ap = awOut + (long long)bb * SEQ * DI;
        const int d0 = n0 >> 1;
        #pragma unroll
        for (int mf = 0; mf < 4; mf++) {
            long long r0 = m0 + (wm * 4 + mf) * 16 + g;
            #pragma unroll
            for (int nf = 0; nf < 4; nf++) {
                int col = (wn * 4 + nf) * 8 + 2 * t;
                float2 bv = *(const float2*)(bp + col);
                int d = d0 + (wn * 4 + nf) * 4 + t;
                {
                    float hid = acc[mf][nf][0] + bv.x;
                    float gat = acc[mf][nf][1] + bv.y;
                    float z = __fdividef(1.f, 1.f + __expf(-gat));
                    float ht = (hid >= 0.f) ? (hid + 0.5f) : __fdividef(1.f, 1.f + __expf(-hid));
                    ap[r0 * DI + d] = __floats2half2_rn(1.0f - z, z * ht);
                }
                {
                    float hid = acc[mf][nf][2] + bv.x;
                    float gat = acc[mf][nf][3] + bv.y;
                    float z = __fdividef(1.f, 1.f + __expf(-gat));
                    float ht = (hid >= 0.f) ? (hid + 0.5f) : __fdividef(1.f, 1.f + __expf(-hid));
                    ap[(r0 + 8) * DI + d] = __floats2half2_rn(1.0f - z, z * ht);
                }
            }
        }
        return;
    }

    float* Cp = C + (long long)bb * sC;
    const float* Rp = resid ? (resid + (long long)bb * sC) : nullptr;
    #pragma unroll
    for (int mf = 0; mf < 4; mf++) {
        long long r0 = m0 + (wm * 4 + mf) * 16 + g;
        #pragma unroll
        for (int nf = 0; nf < 4; nf++) {
            int col = (wn * 4 + nf) * 8 + 2 * t;
            float2 bv = *(const float2*)(bp + col);
            long long o0 = r0 * N + n0 + col;
            long long o1 = (r0 + 8) * N + n0 + col;
            float2 v0 = make_float2(acc[mf][nf][0] + bv.x, acc[mf][nf][1] + bv.y);
            float2 v1 = make_float2(acc[mf][nf][2] + bv.x, acc[mf][nf][3] + bv.y);
            if (Rp) {
                float2 q0 = *(const float2*)(Rp + o0);
                float2 q1 = *(const float2*)(Rp + o1);
                v0.x += q0.x; v0.y += q0.y;
                v1.x += q1.x; v1.y += q1.y;
            }
            *(float2*)(Cp + o0) = v0;
            *(float2*)(Cp + o1) = v1;
        }
    }
}

// ---------------- 6. chunked GRU scan (pure FMA, aw precomputed) ----------------
// 6a: per-chunk composites
__global__ __launch_bounds__(256) void scan_a_kernel(const __half2* __restrict__ aw,
                                                     float* __restrict__ cA,
                                                     float* __restrict__ cW) {
    __shared__ uint32_t sa[16][256];
    int bid = blockIdx.x;
    int b = bid / (5 * NCH);
    int rem = bid % (5 * NCH);
    int gA = rem / NCH, c = rem % NCH;
    int d0 = gA * 256;
    const int tid = threadIdx.x;
    const uint32_t* ab = (const uint32_t*)(aw + (long long)b * SEQ * DI);
    float Acc = 1.f, Wcc = 0.f;
    for (int s0 = c * CH; s0 < (c + 1) * CH; s0 += 16) {
        #pragma unroll
        for (int i = 0; i < 4; i++) {
            int lin = i * 256 + tid;
            int row = lin >> 6;
            int c4 = (lin & 63) * 4;
            *(uint4*)&sa[row][c4] = *(const uint4*)(ab + (long long)(s0 + row) * DI + d0 + c4);
        }
        __syncthreads();
        #pragma unroll
        for (int s = 0; s < 16; s++) {
            uint32_t u = sa[s][tid];
            __half2 hv = *(__half2*)&u;
            float a = __low2float(hv), w = __high2float(hv);
            Acc = a * Acc;
            Wcc = fmaf(a, Wcc, w);
        }
        __syncthreads();
    }
    int o = (b * NCH + c) * DI + d0 + tid;
    cA[o] = Acc;
    cW[o] = Wcc;
}

// 6b: chunk prefix (+ aux write)
__global__ void scan_b_kernel(const float* __restrict__ cA, const float* __restrict__ cW,
                              float* __restrict__ h0, float* __restrict__ auxp) {
    if (blockIdx.x == 0 && threadIdx.x == 0) *auxp = 0.0f;
    int b = blockIdx.x / 5, gA = blockIdx.x % 5;
    int d = gA * 256 + threadIdx.x;
    float h = 0.f;
    #pragma unroll
    for (int c = 0; c < NCH; c++) {
        int o = (b * NCH + c) * DI + d;
        h0[o] = h;
        h = fmaf(cA[o], h, cW[o]);
    }
}

// 6c: replay, write hs bf16 (+ ns on last chunk)
__global__ __launch_bounds__(256) void scan_c_kernel(const __half2* __restrict__ aw,
                                                     const float* __restrict__ h0,
                                                     __nv_bfloat16* __restrict__ hsb,
                                                     float* __restrict__ ns) {
    __shared__ uint32_t sa[16][256];
    __shared__ __nv_bfloat16 sO[16][256];
    int bid = blockIdx.x;
    int b = bid / (5 * NCH);
    int rem = bid % (5 * NCH);
    int gA = rem / NCH, c = rem % NCH;
    int d0 = gA * 256;
    const int tid = threadIdx.x;
    const uint32_t* ab = (const uint32_t*)(aw + (long long)b * SEQ * DI);
    __nv_bfloat16* hb = hsb + (long long)b * SEQ * DI;
    float h = h0[(b * NCH + c) * DI + d0 + tid];
    for (int s0 = c * CH; s0 < (c + 1) * CH; s0 += 16) {
        #pragma unroll
        for (int i = 0; i < 4; i++) {
            int lin = i * 256 + tid;
            int row = lin >> 6;
            int c4 = (lin & 63) * 4;
            *(uint4*)&sa[row][c4] = *(const uint4*)(ab + (long long)(s0 + row) * DI + d0 + c4);
        }
        __syncthreads();
        #pragma unroll
        for (int s = 0; s < 16; s++) {
            uint32_t u = sa[s][tid];
            __half2 hv = *(__half2*)&u;
            h = fmaf(__low2float(hv), h, __high2float(hv));
            sO[s][tid] = __float2bfloat16(h);
        }
        __syncthreads();
        #pragma unroll
        for (int i = 0; i < 2; i++) {
            int lin = i * 256 + tid;
            int row = lin >> 5;
            int cc = (lin & 31) * 8;
            *(uint4*)(hb + (long long)(s0 + row) * DI + d0 + cc) = *(uint4*)&sO[row][cc];
        }
        __syncthreads();
    }
    if (c == NCH - 1) ns[b * DI + d0 + tid] = h;
}

// ---------------- launch ----------------
extern "C" void kernel_launch(void* const* d_in, const int* in_sizes, int n_in,
                              void* d_out, int out_size) {
    const float* inputs   = (const float*)d_in[0];
    const float* norm_w   = (const float*)d_in[1];
    const float* router_w = (const float*)d_in[2];
    const float* router_b = (const float*)d_in[3];
    const float* w_in     = (const float*)d_in[4];
    const float* b_in     = (const float*)d_in[5];
    const float* w_out    = (const float*)d_in[6];
    const float* b_out    = (const float*)d_in[7];
    float* out = (float*)d_out;

    __nv_bfloat16 *xnh, *WiT, *WoT, *hs;
    __half2* aw;
    float *partial, *probs, *bi, *bo, *cA, *cW, *h0;
    cudaGetSymbolAddress((void**)&xnh, g_xnh);
    cudaGetSymbolAddress((void**)&partial, g_partial);
    cudaGetSymbolAddress((void**)&probs, g_probs);
    cudaGetSymbolAddress((void**)&WiT, g_WiT);
    cudaGetSymbolAddress((void**)&bi, g_bi);
    cudaGetSymbolAddress((void**)&WoT, g_WoT);
    cudaGetSymbolAddress((void**)&bo, g_bo);
    cudaGetSymbolAddress((void**)&aw, g_aw);
    cudaGetSymbolAddress((void**)&hs, g_hs);
    cudaGetSymbolAddress((void**)&cA, g_cA);
    cudaGetSymbolAddress((void**)&cW, g_cW);
    cudaGetSymbolAddress((void**)&h0, g_h0);

    const int DYN = 4 * STAGE_BYTES;
    cudaFuncSetAttribute(hgemm_kernel, cudaFuncAttributeMaxDynamicSharedMemorySize, DYN);

    rmsnorm_kernel<<<NB * SEQ, 256>>>(inputs, norm_w, xnh);
    pool1_kernel<<<NB * 32, 1024>>>(xnh, partial);
    pool_router_kernel<<<1, 1024>>>(partial, router_w, router_b, probs);
    mix_all_kernel<<<3896, 256>>>(WiT, WoT, bi, bo, w_in, w_out, b_in, b_out, probs);
    {   // GEMM1 -> aw pairs
        dim3 grid(D2 / 128, SEQ / 128, NB);
        hgemm_kernel<<<grid, 256, DYN>>>(xnh, WiT, bi, nullptr, nullptr, aw, HID, D2,
                                         (long long)SEQ * HID, (long long)HID * D2, 0);
    }
    scan_a_kernel<<<NB * 5 * NCH, 256>>>(aw, cA, cW);
    scan_b_kernel<<<NB * 5, 256>>>(cA, cW, h0, out + (long long)out_size - 1);
    scan_c_kernel<<<NB * 5 * NCH, 256>>>(aw, h0, hs, out + (long long)NB * SEQ * HID);
    {   // GEMM2: out = hs @ WoT^T + bo + inputs
        dim3 grid(HID / 128, SEQ / 128, NB);
        hgemm_kernel<<<grid, 256, DYN>>>(hs, WoT, bo, inputs, out, nullptr, DI, HID,
                                         (long long)SEQ * DI, (long long)DI * HID,
                                         (long long)SEQ * HID);
    }
}

// round 7
// speedup vs baseline: 9.0776x; 1.0218x over previous
#include <cuda_runtime.h>
#include <cuda_bf16.h>
#include <cuda_fp16.h>
#include <math.h>
#include <stdint.h>

#define HID 1024
#define NE 3
#define DI 1280
#define D2 2560
#define NB 4
#define SEQ 4096
#define EPSV 1e-6f
#define NCH 32
#define CH  128

// ---------------- scratch (device globals) ----------------
__device__ __nv_bfloat16 g_xnh[(size_t)NB * SEQ * HID];
__device__ float g_partial[NB * 128 * HID];              // per-32-row chunks
__device__ float g_probs[NB * NE];
__device__ __nv_bfloat16 g_WiT[(size_t)NB * HID * D2];   // permuted rows (hid/gate interleave)
__device__ float g_bi[NB * D2];
__device__ __nv_bfloat16 g_WoT[(size_t)NB * DI * HID];
__device__ float g_bo[NB * HID];
__device__ __half2 g_aw[(size_t)NB * SEQ * DI];
__device__ __nv_bfloat16 g_hs[(size_t)NB * SEQ * DI];
__device__ float g_cA[NB * NCH * DI];
__device__ float g_cW[NB * NCH * DI];
__device__ float g_h0[NB * NCH * DI];

// ---------------- PTX helpers ----------------
__device__ __forceinline__ uint32_t smem_u32(const void* p) {
    uint32_t a;
    asm("{ .reg .u64 t; cvta.to.shared.u64 t, %1; cvt.u32.u64 %0, t; }" : "=r"(a) : "l"(p));
    return a;
}
__device__ __forceinline__ void cpa16(uint32_t dst, const void* src) {
    asm volatile("{\n .reg .u64 g;\n cvta.to.global.u64 g, %1;\n"
                 " cp.async.cg.shared.global [%0], [g], 16;\n}"
                 :: "r"(dst), "l"(src));
}
__device__ __forceinline__ void ldsm_x4(uint32_t& r0, uint32_t& r1, uint32_t& r2, uint32_t& r3,
                                        uint32_t addr) {
    asm volatile("ldmatrix.sync.aligned.m8n8.x4.shared.b16 {%0,%1,%2,%3}, [%4];"
                 : "=r"(r0), "=r"(r1), "=r"(r2), "=r"(r3) : "r"(addr));
}
__device__ __forceinline__ void mma_bf16(float& d0, float& d1, float& d2, float& d3,
                                         uint32_t a0, uint32_t a1, uint32_t a2, uint32_t a3,
                                         uint32_t b0, uint32_t b1) {
    asm volatile("mma.sync.aligned.m16n8k16.row.col.f32.bf16.bf16.f32 "
                 "{%0,%1,%2,%3}, {%4,%5,%6,%7}, {%8,%9}, {%0,%1,%2,%3};"
                 : "+f"(d0), "+f"(d1), "+f"(d2), "+f"(d3)
                 : "r"(a0), "r"(a1), "r"(a2), "r"(a3), "r"(b0), "r"(b1));
}

// ---------------- 1. fused RMSNorm -> bf16 + pooled partial ----------------
// block = 32 rows of one batch; 8 warps, warp handles 4 rows; grid = NB*128
__global__ __launch_bounds__(256) void norm_pool_kernel(const float* __restrict__ in,
                                                        const float* __restrict__ nw,
                                                        __nv_bfloat16* __restrict__ xnh,
                                                        float* __restrict__ partial) {
    __shared__ float sp[8][1024];
    const int blk = blockIdx.x;
    const int b = blk >> 7, ch = blk & 127;
    const int wid = threadIdx.x >> 5, lane = threadIdx.x & 31;

    float4 wv[8];
    #pragma unroll
    for (int i = 0; i < 8; i++) wv[i] = *(const float4*)(nw + i * 128 + lane * 4);

    float4 pacc[8];
    #pragma unroll
    for (int i = 0; i < 8; i++) pacc[i] = make_float4(0.f, 0.f, 0.f, 0.f);

    const long long rowBase = (long long)b * SEQ + ch * 32 + wid * 4;
    #pragma unroll
    for (int r = 0; r < 4; r++) {
        const float* rp = in + (rowBase + r) * HID;
        float4 v[8];
        float ss = 0.f;
        #pragma unroll
        for (int i = 0; i < 8; i++) {
            v[i] = *(const float4*)(rp + i * 128 + lane * 4);
            ss += v[i].x * v[i].x + v[i].y * v[i].y + v[i].z * v[i].z + v[i].w * v[i].w;
        }
        #pragma unroll
        for (int o = 16; o > 0; o >>= 1) ss += __shfl_xor_sync(0xffffffffu, ss, o);
        float scale = rsqrtf(ss * (1.0f / HID) + EPSV);
        __nv_bfloat16* op = xnh + (rowBase + r) * HID;
        #pragma unroll
        for (int i = 0; i < 8; i++) {
            float x0 = v[i].x * scale * wv[i].x;
            float x1 = v[i].y * scale * wv[i].y;
            float x2 = v[i].z * scale * wv[i].z;
            float x3 = v[i].w * scale * wv[i].w;
            pacc[i].x += x0; pacc[i].y += x1; pacc[i].z += x2; pacc[i].w += x3;
            __nv_bfloat162 p0 = __floats2bfloat162_rn(x0, x1);
            __nv_bfloat162 p1 = __floats2bfloat162_rn(x2, x3);
            uint2 u;
            u.x = *(uint32_t*)&p0;
            u.y = *(uint32_t*)&p1;
            *(uint2*)(op + i * 128 + lane * 4) = u;
        }
    }
    // cross-warp reduce pooled partials
    #pragma unroll
    for (int i = 0; i < 8; i++) *(float4*)(&sp[wid][i * 128 + lane * 4]) = pacc[i];
    __syncthreads();
    float* pp = partial + (long long)(b * 128 + ch) * HID;
    int h = threadIdx.x * 4;
    float4 s = make_float4(0.f, 0.f, 0.f, 0.f);
    #pragma unroll
    for (int w = 0; w < 8; w++) {
        float4 q = *(float4*)(&sp[w][h]);
        s.x += q.x; s.y += q.y; s.z += q.z; s.w += q.w;
    }
    *(float4*)(pp + h) = s;
}

// ---------------- 2. fused pool2 + router (1 block, 1024 threads) ----------------
__global__ void pool_router_kernel(const float* __restrict__ partial,
                                   const float* __restrict__ rw,
                                   const float* __restrict__ rb,
                                   float* __restrict__ probs) {
    __shared__ float red[12][32];
    __shared__ float logits[12];
    int h = threadIdx.x;
    int wid = h >> 5, lid = h & 31;
    float p[NB];
    #pragma unroll
    for (int b = 0; b < NB; b++) {
        float s = 0.f;
        for (int c = 0; c < 128; c++) s += partial[(long long)(b * 128 + c) * HID + h];
        p[b] = s * (1.0f / SEQ);
    }
    float r0 = rw[h * NE + 0], r1 = rw[h * NE + 1], r2 = rw[h * NE + 2];
    float acc[12];
    #pragma unroll
    for (int b = 0; b < NB; b++) {
        acc[b * 3 + 0] = p[b] * r0;
        acc[b * 3 + 1] = p[b] * r1;
        acc[b * 3 + 2] = p[b] * r2;
    }
    #pragma unroll
    for (int i = 0; i < 12; i++) {
        float v = acc[i];
        #pragma unroll
        for (int o = 16; o > 0; o >>= 1) v += __shfl_xor_sync(0xffffffffu, v, o);
        if (lid == 0) red[i][wid] = v;
    }
    __syncthreads();
    if (wid == 0) {
        #pragma unroll
        for (int i = 0; i < 12; i++) {
            float v = red[i][lid];
            #pragma unroll
            for (int o = 16; o > 0; o >>= 1) v += __shfl_xor_sync(0xffffffffu, v, o);
            if (lid == 0) logits[i] = v;
        }
    }
    __syncthreads();
    if (h < NB) {
        int b = h;
        float l0 = logits[b * 3 + 0] + rb[0];
        float l1 = logits[b * 3 + 1] + rb[1];
        float l2 = logits[b * 3 + 2] + rb[2];
        float mx = fmaxf(l0, fmaxf(l1, l2));
        float e0 = expf(l0 - mx), e1 = expf(l1 - mx), e2 = expf(l2 - mx);
        float inv = 1.0f / (e0 + e1 + e2);
        probs[b * 3 + 0] = e0 * inv;
        probs[b * 3 + 1] = e1 * inv;
        probs[b * 3 + 2] = e2 * inv;
    }
}

// ---------------- 3. fused mixing ----------------
__device__ __forceinline__ void mixT_body(__nv_bfloat16* __restrict__ dst,
                                          const float* __restrict__ src,
                                          const float* __restrict__ probs,
                                          int K, int N, int bx, int by, int tid, int perm) {
    __shared__ float t0[32][33], t1[32][33], t2[32][33];
    int tx = tid & 31, ty = tid >> 5;
    int k0 = by * 32, n0 = bx * 32;
    long long eSz = (long long)K * N;
    #pragma unroll
    for (int i = 0; i < 4; i++) {
        int k = k0 + ty + i * 8;
        long long o = (long long)k * N + n0 + tx;
        t0[ty + i * 8][tx] = src[o];
        t1[ty + i * 8][tx] = src[eSz + o];
        t2[ty + i * 8][tx] = src[2 * eSz + o];
    }
    __syncthreads();
    #pragma unroll
    for (int b = 0; b < NB; b++) {
        float p0 = probs[b * 3 + 0], p1 = probs[b * 3 + 1], p2 = probs[b * 3 + 2];
        #pragma unroll
        for (int i = 0; i < 4; i++) {
            int n = n0 + ty + i * 8;
            int k = k0 + tx;
            float v = p0 * t0[tx][ty + i * 8] + p1 * t1[tx][ty + i * 8] + p2 * t2[tx][ty + i * 8];
            long long r = perm ? ((n < DI) ? 2 * n : 2 * (n - DI) + 1) : n;
            dst[(long long)b * eSz + r * K + k] = __float2bfloat16(v);
        }
    }
}

__global__ void mix_all_kernel(__nv_bfloat16* __restrict__ WiT, __nv_bfloat16* __restrict__ WoT,
                               float* __restrict__ bi, float* __restrict__ bo,
                               const float* __restrict__ w_in, const float* __restrict__ w_out,
                               const float* __restrict__ b_in, const float* __restrict__ b_out,
                               const float* __restrict__ probs) {
    int bid = blockIdx.x, tid = threadIdx.x;
    if (bid < 2560) {
        mixT_body(WiT, w_in, probs, HID, D2, bid % 80, bid / 80, tid, 1);
    } else if (bid < 3840) {
        int id = bid - 2560;
        mixT_body(WoT, w_out, probs, DI, HID, id % 32, id / 32, tid, 0);
    } else if (bid < 3880) {
        int i = (bid - 3840) * 256 + tid;
        if (i < NB * D2) {
            int b = i / D2, j = i - b * D2;
            float v = probs[b * 3 + 0] * b_in[j] + probs[b * 3 + 1] * b_in[D2 + j] +
                      probs[b * 3 + 2] * b_in[2 * D2 + j];
            long long r = (j < DI) ? 2 * j : 2 * (j - DI) + 1;
            bi[(long long)b * D2 + r] = v;
        }
    } else {
        int i = (bid - 3880) * 256 + tid;
        if (i < NB * HID) {
            int b = i / HID, j = i - b * HID;
            bo[i] = probs[b * 3 + 0] * b_out[j] + probs[b * 3 + 1] * b_out[HID + j] +
                    probs[b * 3 + 2] * b_out[2 * HID + j];
        }
    }
}

// ---------------- 4/8. bf16 GEMM: cp.async 4-stage + ldmatrix ----------------
#define STAGE_BYTES 16384

__global__ __launch_bounds__(256, 2) void hgemm_kernel(
    const __nv_bfloat16* __restrict__ A, const __nv_bfloat16* __restrict__ B,
    const float* __restrict__ bias, const float* __restrict__ resid,
    float* __restrict__ C, __half2* __restrict__ awOut, int K, int N,
    long long sA, long long sB, long long sC) {
    extern __shared__ uint8_t dsm[];
    const uint32_t smb = smem_u32(dsm);
    const int tid = threadIdx.x;
    const int wid = tid >> 5;
    const int lane = tid & 31;
    const int bb = blockIdx.z;

    const __nv_bfloat16* Abase = A + (long long)bb * sA + (long long)blockIdx.y * 128 * K;
    const __nv_bfloat16* Bbase = B + (long long)bb * sB + (long long)blockIdx.x * 128 * K;

    const int g = lane >> 2, t = lane & 3;
    const int wm = wid >> 2;
    const int wn = wid & 3;

    float acc[4][4][4];
    #pragma unroll
    for (int i = 0; i < 4; i++)
        #pragma unroll
        for (int j = 0; j < 4; j++)
            #pragma unroll
            for (int q = 0; q < 4; q++) acc[i][j][q] = 0.f;

    const int KT = K >> 5;

    auto issue = [&](int kt, int stg) {
        uint32_t sb = smb + stg * STAGE_BYTES;
        #pragma unroll
        for (int u = 0; u < 2; u++) {
            int c = tid + u * 256;
            int row = c >> 2, k16 = c & 3;
            int phys = k16 ^ ((row >> 1) & 3);
            uint32_t off = row * 64 + phys * 16;
            cpa16(sb + off, Abase + (long long)row * K + kt * 32 + k16 * 8);
            cpa16(sb + 8192 + off, Bbase + (long long)row * K + kt * 32 + k16 * 8);
        }
    };

    issue(0, 0);
    asm volatile("cp.async.commit_group;" ::: "memory");
    issue(1, 1);
    asm volatile("cp.async.commit_group;" ::: "memory");
    issue(2, 2);
    asm volatile("cp.async.commit_group;" ::: "memory");

    const int mi = lane >> 3;
    const int l7 = lane & 7;

    for (int kt = 0; kt < KT; kt++) {
        asm volatile("cp.async.wait_group 2;" ::: "memory");
        __syncthreads();
        if (kt + 3 < KT) issue(kt + 3, (kt + 3) & 3);
        asm volatile("cp.async.commit_group;" ::: "memory");

        uint32_t sa = smb + (kt & 3) * STAGE_BYTES;
        uint32_t sbm = sa + 8192;
        #pragma unroll
        for (int ks = 0; ks < 2; ks++) {
            uint32_t af[4][4], bf[4][2];
            #pragma unroll
            for (int mf = 0; mf < 4; mf++) {
                int row = wm * 64 + mf * 16 + l7 + (mi & 1) * 8;
                int chunk = 2 * ks + (mi >> 1);
                int phys = chunk ^ ((row >> 1) & 3);
                ldsm_x4(af[mf][0], af[mf][1], af[mf][2], af[mf][3],
                        sa + row * 64 + phys * 16);
            }
            #pragma unroll
            for (int p = 0; p < 2; p++) {
                int row = wn * 32 + p * 16 + l7 + (mi >> 1) * 8;
                int chunk = 2 * ks + (mi & 1);
                int phys = chunk ^ ((row >> 1) & 3);
                uint32_t r0, r1, r2, r3;
                ldsm_x4(r0, r1, r2, r3, sbm + row * 64 + phys * 16);
                bf[2 * p][0] = r0; bf[2 * p][1] = r1;
                bf[2 * p + 1][0] = r2; bf[2 * p + 1][1] = r3;
            }
            #pragma unroll
            for (int mf = 0; mf < 4; mf++)
                #pragma unroll
                for (int nf = 0; nf < 4; nf++)
                    mma_bf16(acc[mf][nf][0], acc[mf][nf][1], acc[mf][nf][2], acc[mf][nf][3],
                             af[mf][0], af[mf][1], af[mf][2], af[mf][3],
                             bf[nf][0], bf[nf][1]);
        }
    }

    const long long m0 = (long long)blockIdx.y * 128;
    const int n0 = blockIdx.x * 128;
    const float* bp = bias + (long long)bb * N + n0;

    if (awOut) {
        // stage (a,w) half2 tile in smem (stride 65 -> conflict-free), then coalesced store
        __syncthreads();
        uint32_t* sw = (uint32_t*)dsm;
        #pragma unroll
        for (int mf = 0; mf < 4; mf++) {
            int rl = (wm * 4 + mf) * 16 + g;
            #pragma unroll
            for (int nf = 0; nf < 4; nf++) {
                int col = (wn * 4 + nf) * 8 + 2 * t;
                float2 bv = *(const float2*)(bp + col);
                int dl = (wn * 4 + nf) * 4 + t;
                {
                    float hid = acc[mf][nf][0] + bv.x;
                    float gat = acc[mf][nf][1] + bv.y;
                    float z = __fdividef(1.f, 1.f + __expf(-gat));
                    float ht = (hid >= 0.f) ? (hid + 0.5f) : __fdividef(1.f, 1.f + __expf(-hid));
                    __half2 hv = __floats2half2_rn(1.0f - z, z * ht);
                    sw[rl * 65 + dl] = *(uint32_t*)&hv;
                }
                {
                    float hid = acc[mf][nf][2] + bv.x;
                    float gat = acc[mf][nf][3] + bv.y;
                    float z = __fdividef(1.f, 1.f + __expf(-gat));
                    float ht = (hid >= 0.f) ? (hid + 0.5f) : __fdividef(1.f, 1.f + __expf(-hid));
                    __half2 hv = __floats2half2_rn(1.0f - z, z * ht);
                    sw[(rl + 8) * 65 + dl] = *(uint32_t*)&hv;
                }
            }
        }
        __syncthreads();
        __half2* ap = awOut + (long long)bb * SEQ * DI;
        const int d0 = n0 >> 1;
        #pragma unroll
        for (int i = 0; i < 8; i++) {
            int lin = i * 256 + tid;
            int row = lin >> 4, c16 = lin & 15;
            uint32_t v0 = sw[row * 65 + c16 * 4 + 0];
            uint32_t v1 = sw[row * 65 + c16 * 4 + 1];
            uint32_t v2 = sw[row * 65 + c16 * 4 + 2];
            uint32_t v3 = sw[row * 65 + c16 * 4 + 3];
            uint4 u = make_uint4(v0, v1, v2, v3);
            *(uint4*)(ap + (m0 + row) * DI + d0 + c16 * 4) = u;
        }
        return;
    }

    float* Cp = C + (long long)bb * sC;
    const float* Rp = resid ? (resid + (long long)bb * sC) : nullptr;
    #pragma unroll
    for (int mf = 0; mf < 4; mf++) {
        long long r0 = m0 + (wm * 4 + mf) * 16 + g;
        #pragma unroll
        for (int nf = 0; nf < 4; nf++) {
            int col = (wn * 4 + nf) * 8 + 2 * t;
            float2 bv = *(const float2*)(bp + col);
            long long o0 = r0 * N + n0 + col;
            long long o1 = (r0 + 8) * N + n0 + col;
            float2 v0 = make_float2(acc[mf][nf][0] + bv.x, acc[mf][nf][1] + bv.y);
            float2 v1 = make_float2(acc[mf][nf][2] + bv.x, acc[mf][nf][3] + bv.y);
            if (Rp) {
                float2 q0 = *(const float2*)(Rp + o0);
                float2 q1 = *(const float2*)(Rp + o1);
                v0.x += q0.x; v0.y += q0.y;
                v1.x += q1.x; v1.y += q1.y;
            }
            *(float2*)(Cp + o0) = v0;
            *(float2*)(Cp + o1) = v1;
        }
    }
}

// ---------------- 5-7. chunked GRU scan (pure FMA) ----------------
__global__ __launch_bounds__(256) void scan_a_kernel(const __half2* __restrict__ aw,
                                                     float* __restrict__ cA,
                                                     float* __restrict__ cW) {
    __shared__ uint32_t sa[16][256];
    int bid = blockIdx.x;
    int b = bid / (5 * NCH);
    int rem = bid % (5 * NCH);
    int gA = rem / NCH, c = rem % NCH;
    int d0 = gA * 256;
    const int tid = threadIdx.x;
    const uint32_t* ab = (const uint32_t*)(aw + (long long)b * SEQ * DI);
    float Acc = 1.f, Wcc = 0.f;
    for (int s0 = c * CH; s0 < (c + 1) * CH; s0 += 16) {
        #pragma unroll
        for (int i = 0; i < 4; i++) {
            int lin = i * 256 + tid;
            int row = lin >> 6;
            int c4 = (lin & 63) * 4;
            *(uint4*)&sa[row][c4] = *(const uint4*)(ab + (long long)(s0 + row) * DI + d0 + c4);
        }
        __syncthreads();
        #pragma unroll
        for (int s = 0; s < 16; s++) {
            uint32_t u = sa[s][tid];
            __half2 hv = *(__half2*)&u;
            float a = __low2float(hv), w = __high2float(hv);
            Acc = a * Acc;
            Wcc = fmaf(a, Wcc, w);
        }
        __syncthreads();
    }
    int o = (b * NCH + c) * DI + d0 + tid;
    cA[o] = Acc;
    cW[o] = Wcc;
}

__global__ void scan_b_kernel(const float* __restrict__ cA, const float* __restrict__ cW,
                              float* __restrict__ h0, float* __restrict__ auxp) {
    if (blockIdx.x == 0 && threadIdx.x == 0) *auxp = 0.0f;
    int b = blockIdx.x / 5, gA = blockIdx.x % 5;
    int d = gA * 256 + threadIdx.x;
    float h = 0.f;
    #pragma unroll
    for (int c = 0; c < NCH; c++) {
        int o = (b * NCH + c) * DI + d;
        h0[o] = h;
        h = fmaf(cA[o], h, cW[o]);
    }
}

__global__ __launch_bounds__(256) void scan_c_kernel(const __half2* __restrict__ aw,
                                                     const float* __restrict__ h0,
                                                     __nv_bfloat16* __restrict__ hsb,
                                                     float* __restrict__ ns) {
    __shared__ uint32_t sa[16][256];
    __shared__ __nv_bfloat16 sO[16][256];
    int bid = blockIdx.x;
    int b = bid / (5 * NCH);
    int rem = bid % (5 * NCH);
    int gA = rem / NCH, c = rem % NCH;
    int d0 = gA * 256;
    const int tid = threadIdx.x;
    const uint32_t* ab = (const uint32_t*)(aw + (long long)b * SEQ * DI);
    __nv_bfloat16* hb = hsb + (long long)b * SEQ * DI;
    float h = h0[(b * NCH + c) * DI + d0 + tid];
    for (int s0 = c * CH; s0 < (c + 1) * CH; s0 += 16) {
        #pragma unroll
        for (int i = 0; i < 4; i++) {
            int lin = i * 256 + tid;
            int row = lin >> 6;
            int c4 = (lin & 63) * 4;
            *(uint4*)&sa[row][c4] = *(const uint4*)(ab + (long long)(s0 + row) * DI + d0 + c4);
        }
        __syncthreads();
        #pragma unroll
        for (int s = 0; s < 16; s++) {
            uint32_t u = sa[s][tid];
            __half2 hv = *(__half2*)&u;
            h = fmaf(__low2float(hv), h, __high2float(hv));
            sO[s][tid] = __float2bfloat16(h);
        }
        __syncthreads();
        #pragma unroll
        for (int i = 0; i < 2; i++) {
            int lin = i * 256 + tid;
            int row = lin >> 5;
            int cc = (lin & 31) * 8;
            *(uint4*)(hb + (long long)(s0 + row) * DI + d0 + cc) = *(uint4*)&sO[row][cc];
        }
        __syncthreads();
    }
    if (c == NCH - 1) ns[b * DI + d0 + tid] = h;
}

// ---------------- launch ----------------
extern "C" void kernel_launch(void* const* d_in, const int* in_sizes, int n_in,
                              void* d_out, int out_size) {
    const float* inputs   = (const float*)d_in[0];
    const float* norm_w   = (const float*)d_in[1];
    const float* router_w = (const float*)d_in[2];
    const float* router_b = (const float*)d_in[3];
    const float* w_in     = (const float*)d_in[4];
    const float* b_in     = (const float*)d_in[5];
    const float* w_out    = (const float*)d_in[6];
    const float* b_out    = (const float*)d_in[7];
    float* out = (float*)d_out;

    __nv_bfloat16 *xnh, *WiT, *WoT, *hs;
    __half2* aw;
    float *partial, *probs, *bi, *bo, *cA, *cW, *h0;
    cudaGetSymbolAddress((void**)&xnh, g_xnh);
    cudaGetSymbolAddress((void**)&partial, g_partial);
    cudaGetSymbolAddress((void**)&probs, g_probs);
    cudaGetSymbolAddress((void**)&WiT, g_WiT);
    cudaGetSymbolAddress((void**)&bi, g_bi);
    cudaGetSymbolAddress((void**)&WoT, g_WoT);
    cudaGetSymbolAddress((void**)&bo, g_bo);
    cudaGetSymbolAddress((void**)&aw, g_aw);
    cudaGetSymbolAddress((void**)&hs, g_hs);
    cudaGetSymbolAddress((void**)&cA, g_cA);
    cudaGetSymbolAddress((void**)&cW, g_cW);
    cudaGetSymbolAddress((void**)&h0, g_h0);

    const int DYN = 4 * STAGE_BYTES;
    cudaFuncSetAttribute(hgemm_kernel, cudaFuncAttributeMaxDynamicSharedMemorySize, DYN);

    norm_pool_kernel<<<NB * 128, 256>>>(inputs, norm_w, xnh, partial);
    pool_router_kernel<<<1, 1024>>>(partial, router_w, router_b, probs);
    mix_all_kernel<<<3896, 256>>>(WiT, WoT, bi, bo, w_in, w_out, b_in, b_out, probs);
    {   // GEMM1 -> aw pairs  (4th launch: profiled)
        dim3 grid(D2 / 128, SEQ / 128, NB);
        hgemm_kernel<<<grid, 256, DYN>>>(xnh, WiT, bi, nullptr, nullptr, aw, HID, D2,
                                         (long long)SEQ * HID, (long long)HID * D2, 0);
    }
    scan_a_kernel<<<NB * 5 * NCH, 256>>>(aw, cA, cW);
    scan_b_kernel<<<NB * 5, 256>>>(cA, cW, h0, out + (long long)out_size - 1);
    scan_c_kernel<<<NB * 5 * NCH, 256>>>(aw, h0, hs, out + (long long)NB * SEQ * HID);
    {   // GEMM2: out = hs @ WoT^T + bo + inputs
        dim3 grid(HID / 128, SEQ / 128, NB);
        hgemm_kernel<<<grid, 256, DYN>>>(hs, WoT, bo, inputs, out, nullptr, DI, HID,
                                         (long long)SEQ * DI, (long long)DI * HID,
                                         (long long)SEQ * HID);
    }
}

// round 8
// speedup vs baseline: 9.2128x; 1.0149x over previous
#include <cuda_runtime.h>
#include <cuda_bf16.h>
#include <cuda_fp16.h>
#include <math.h>
#include <stdint.h>

#define HID 1024
#define NE 3
#define DI 1280
#define D2 2560
#define NB 4
#define SEQ 4096
#define EPSV 1e-6f
#define NCH 32
#define CH  128

// ---------------- scratch (device globals) ----------------
__device__ __nv_bfloat16 g_xnh[(size_t)NB * SEQ * HID];
__device__ float g_partial[NB * 128 * HID];
__device__ float g_probs[NB * NE];
__device__ __nv_bfloat16 g_WiT[(size_t)NB * HID * D2];   // hid/gate interleaved rows
__device__ float g_bi[NB * D2];
__device__ __nv_bfloat16 g_WoT[(size_t)NB * DI * HID];
__device__ float g_bo[NB * HID];
__device__ __half2 g_aw[(size_t)NB * SEQ * DI];
__device__ __nv_bfloat16 g_hs[(size_t)NB * SEQ * DI];
__device__ float g_cA[NB * NCH * DI];
__device__ float g_cW[NB * NCH * DI];
__device__ float g_h0[NB * NCH * DI];

// ---------------- PTX helpers ----------------
__device__ __forceinline__ uint32_t smem_u32(const void* p) {
    uint32_t a;
    asm("{ .reg .u64 t; cvta.to.shared.u64 t, %1; cvt.u32.u64 %0, t; }" : "=r"(a) : "l"(p));
    return a;
}
__device__ __forceinline__ void cpa16(uint32_t dst, const void* src) {
    asm volatile("{\n .reg .u64 g;\n cvta.to.global.u64 g, %1;\n"
                 " cp.async.cg.shared.global [%0], [g], 16;\n}"
                 :: "r"(dst), "l"(src));
}
__device__ __forceinline__ void ldsm_x4(uint32_t& r0, uint32_t& r1, uint32_t& r2, uint32_t& r3,
                                        uint32_t addr) {
    asm volatile("ldmatrix.sync.aligned.m8n8.x4.shared.b16 {%0,%1,%2,%3}, [%4];"
                 : "=r"(r0), "=r"(r1), "=r"(r2), "=r"(r3) : "r"(addr));
}
__device__ __forceinline__ void mma_bf16(float& d0, float& d1, float& d2, float& d3,
                                         uint32_t a0, uint32_t a1, uint32_t a2, uint32_t a3,
                                         uint32_t b0, uint32_t b1) {
    asm volatile("mma.sync.aligned.m16n8k16.row.col.f32.bf16.bf16.f32 "
                 "{%0,%1,%2,%3}, {%4,%5,%6,%7}, {%8,%9}, {%0,%1,%2,%3};"
                 : "+f"(d0), "+f"(d1), "+f"(d2), "+f"(d3)
                 : "r"(a0), "r"(a1), "r"(a2), "r"(a3), "r"(b0), "r"(b1));
}

// ---------------- 1. fused RMSNorm -> bf16 + pooled partial ----------------
__global__ __launch_bounds__(256) void norm_pool_kernel(const float* __restrict__ in,
                                                        const float* __restrict__ nw,
                                                        __nv_bfloat16* __restrict__ xnh,
                                                        float* __restrict__ partial) {
    __shared__ float sp[8][1024];
    const int blk = blockIdx.x;
    const int b = blk >> 7, ch = blk & 127;
    const int wid = threadIdx.x >> 5, lane = threadIdx.x & 31;

    float4 wv[8];
    #pragma unroll
    for (int i = 0; i < 8; i++) wv[i] = *(const float4*)(nw + i * 128 + lane * 4);

    float4 pacc[8];
    #pragma unroll
    for (int i = 0; i < 8; i++) pacc[i] = make_float4(0.f, 0.f, 0.f, 0.f);

    const long long rowBase = (long long)b * SEQ + ch * 32 + wid * 4;
    #pragma unroll
    for (int r = 0; r < 4; r++) {
        const float* rp = in + (rowBase + r) * HID;
        float4 v[8];
        float ss = 0.f;
        #pragma unroll
        for (int i = 0; i < 8; i++) {
            v[i] = *(const float4*)(rp + i * 128 + lane * 4);
            ss += v[i].x * v[i].x + v[i].y * v[i].y + v[i].z * v[i].z + v[i].w * v[i].w;
        }
        #pragma unroll
        for (int o = 16; o > 0; o >>= 1) ss += __shfl_xor_sync(0xffffffffu, ss, o);
        float scale = rsqrtf(ss * (1.0f / HID) + EPSV);
        __nv_bfloat16* op = xnh + (rowBase + r) * HID;
        #pragma unroll
        for (int i = 0; i < 8; i++) {
            float x0 = v[i].x * scale * wv[i].x;
            float x1 = v[i].y * scale * wv[i].y;
            float x2 = v[i].z * scale * wv[i].z;
            float x3 = v[i].w * scale * wv[i].w;
            pacc[i].x += x0; pacc[i].y += x1; pacc[i].z += x2; pacc[i].w += x3;
            __nv_bfloat162 p0 = __floats2bfloat162_rn(x0, x1);
            __nv_bfloat162 p1 = __floats2bfloat162_rn(x2, x3);
            uint2 u;
            u.x = *(uint32_t*)&p0;
            u.y = *(uint32_t*)&p1;
            *(uint2*)(op + i * 128 + lane * 4) = u;
        }
    }
    #pragma unroll
    for (int i = 0; i < 8; i++) *(float4*)(&sp[wid][i * 128 + lane * 4]) = pacc[i];
    __syncthreads();
    float* pp = partial + (long long)(b * 128 + ch) * HID;
    int h = threadIdx.x * 4;
    float4 s = make_float4(0.f, 0.f, 0.f, 0.f);
    #pragma unroll
    for (int w = 0; w < 8; w++) {
        float4 q = *(float4*)(&sp[w][h]);
        s.x += q.x; s.y += q.y; s.z += q.z; s.w += q.w;
    }
    *(float4*)(pp + h) = s;
}

// ---------------- 2. router (one block per batch) ----------------
__global__ void router_kernel(const float* __restrict__ partial,
                              const float* __restrict__ rw,
                              const float* __restrict__ rb,
                              float* __restrict__ probs) {
    __shared__ float red[3][32];
    const int b = blockIdx.x;
    const int h = threadIdx.x;
    const int wid = h >> 5, lid = h & 31;
    float s = 0.f;
    for (int c = 0; c < 128; c++) s += partial[(long long)(b * 128 + c) * HID + h];
    float p = s * (1.0f / SEQ);
    float a0 = p * rw[h * NE + 0];
    float a1 = p * rw[h * NE + 1];
    float a2 = p * rw[h * NE + 2];
    #pragma unroll
    for (int o = 16; o > 0; o >>= 1) {
        a0 += __shfl_xor_sync(0xffffffffu, a0, o);
        a1 += __shfl_xor_sync(0xffffffffu, a1, o);
        a2 += __shfl_xor_sync(0xffffffffu, a2, o);
    }
    if (lid == 0) { red[0][wid] = a0; red[1][wid] = a1; red[2][wid] = a2; }
    __syncthreads();
    if (h == 0) {
        float l0 = rb[0], l1 = rb[1], l2 = rb[2];
        #pragma unroll
        for (int w = 0; w < 32; w++) { l0 += red[0][w]; l1 += red[1][w]; l2 += red[2][w]; }
        float mx = fmaxf(l0, fmaxf(l1, l2));
        float e0 = expf(l0 - mx), e1 = expf(l1 - mx), e2 = expf(l2 - mx);
        float inv = 1.0f / (e0 + e1 + e2);
        probs[b * 3 + 0] = e0 * inv;
        probs[b * 3 + 1] = e1 * inv;
        probs[b * 3 + 2] = e2 * inv;
    }
}

// ---------------- 3. fused mixing ----------------
__device__ __forceinline__ void mixT_body(__nv_bfloat16* __restrict__ dst,
                                          const float* __restrict__ src,
                                          const float* __restrict__ probs,
                                          int K, int N, int bx, int by, int tid, int perm) {
    __shared__ float t0[32][33], t1[32][33], t2[32][33];
    int tx = tid & 31, ty = tid >> 5;
    int k0 = by * 32, n0 = bx * 32;
    long long eSz = (long long)K * N;
    #pragma unroll
    for (int i = 0; i < 4; i++) {
        int k = k0 + ty + i * 8;
        long long o = (long long)k * N + n0 + tx;
        t0[ty + i * 8][tx] = src[o];
        t1[ty + i * 8][tx] = src[eSz + o];
        t2[ty + i * 8][tx] = src[2 * eSz + o];
    }
    __syncthreads();
    #pragma unroll
    for (int b = 0; b < NB; b++) {
        float p0 = probs[b * 3 + 0], p1 = probs[b * 3 + 1], p2 = probs[b * 3 + 2];
        #pragma unroll
        for (int i = 0; i < 4; i++) {
            int n = n0 + ty + i * 8;
            int k = k0 + tx;
            float v = p0 * t0[tx][ty + i * 8] + p1 * t1[tx][ty + i * 8] + p2 * t2[tx][ty + i * 8];
            long long r = perm ? ((n < DI) ? 2 * n : 2 * (n - DI) + 1) : n;
            dst[(long long)b * eSz + r * K + k] = __float2bfloat16(v);
        }
    }
}

__global__ void mix_all_kernel(__nv_bfloat16* __restrict__ WiT, __nv_bfloat16* __restrict__ WoT,
                               float* __restrict__ bi, float* __restrict__ bo,
                               const float* __restrict__ w_in, const float* __restrict__ w_out,
                               const float* __restrict__ b_in, const float* __restrict__ b_out,
                               const float* __restrict__ probs) {
    int bid = blockIdx.x, tid = threadIdx.x;
    if (bid < 2560) {
        mixT_body(WiT, w_in, probs, HID, D2, bid % 80, bid / 80, tid, 1);
    } else if (bid < 3840) {
        int id = bid - 2560;
        mixT_body(WoT, w_out, probs, DI, HID, id % 32, id / 32, tid, 0);
    } else if (bid < 3880) {
        int i = (bid - 3840) * 256 + tid;
        if (i < NB * D2) {
            int b = i / D2, j = i - b * D2;
            float v = probs[b * 3 + 0] * b_in[j] + probs[b * 3 + 1] * b_in[D2 + j] +
                      probs[b * 3 + 2] * b_in[2 * D2 + j];
            long long r = (j < DI) ? 2 * j : 2 * (j - DI) + 1;
            bi[(long long)b * D2 + r] = v;
        }
    } else {
        int i = (bid - 3880) * 256 + tid;
        if (i < NB * HID) {
            int b = i / HID, j = i - b * HID;
            bo[i] = probs[b * 3 + 0] * b_out[j] + probs[b * 3 + 1] * b_out[HID + j] +
                    probs[b * 3 + 2] * b_out[2 * HID + j];
        }
    }
}

// ---------------- 4/7. bf16 GEMM: cp.async 4-stage + ldmatrix ----------------
// awOut mode also computes the per-chunk GRU composites (fused scan_a).
#define STAGE_BYTES 16384

__global__ __launch_bounds__(256, 2) void hgemm_kernel(
    const __nv_bfloat16* __restrict__ A, const __nv_bfloat16* __restrict__ B,
    const float* __restrict__ bias, const float* __restrict__ resid,
    float* __restrict__ C, __half2* __restrict__ awOut,
    float* __restrict__ cA, float* __restrict__ cW, int K, int N,
    long long sA, long long sB, long long sC) {
    extern __shared__ uint8_t dsm[];
    const uint32_t smb = smem_u32(dsm);
    const int tid = threadIdx.x;
    const int wid = tid >> 5;
    const int lane = tid & 31;
    const int bb = blockIdx.z;

    const __nv_bfloat16* Abase = A + (long long)bb * sA + (long long)blockIdx.y * 128 * K;
    const __nv_bfloat16* Bbase = B + (long long)bb * sB + (long long)blockIdx.x * 128 * K;

    const int g = lane >> 2, t = lane & 3;
    const int wm = wid >> 2;
    const int wn = wid & 3;

    float acc[4][4][4];
    #pragma unroll
    for (int i = 0; i < 4; i++)
        #pragma unroll
        for (int j = 0; j < 4; j++)
            #pragma unroll
            for (int q = 0; q < 4; q++) acc[i][j][q] = 0.f;

    const int KT = K >> 5;

    auto issue = [&](int kt, int stg) {
        uint32_t sb = smb + stg * STAGE_BYTES;
        #pragma unroll
        for (int u = 0; u < 2; u++) {
            int c = tid + u * 256;
            int row = c >> 2, k16 = c & 3;
            int phys = k16 ^ ((row >> 1) & 3);
            uint32_t off = row * 64 + phys * 16;
            cpa16(sb + off, Abase + (long long)row * K + kt * 32 + k16 * 8);
            cpa16(sb + 8192 + off, Bbase + (long long)row * K + kt * 32 + k16 * 8);
        }
    };

    issue(0, 0);
    asm volatile("cp.async.commit_group;" ::: "memory");
    issue(1, 1);
    asm volatile("cp.async.commit_group;" ::: "memory");
    issue(2, 2);
    asm volatile("cp.async.commit_group;" ::: "memory");

    const int mi = lane >> 3;
    const int l7 = lane & 7;

    for (int kt = 0; kt < KT; kt++) {
        asm volatile("cp.async.wait_group 2;" ::: "memory");
        __syncthreads();
        if (kt + 3 < KT) issue(kt + 3, (kt + 3) & 3);
        asm volatile("cp.async.commit_group;" ::: "memory");

        uint32_t sa = smb + (kt & 3) * STAGE_BYTES;
        uint32_t sbm = sa + 8192;
        #pragma unroll
        for (int ks = 0; ks < 2; ks++) {
            uint32_t af[4][4], bf[4][2];
            #pragma unroll
            for (int mf = 0; mf < 4; mf++) {
                int row = wm * 64 + mf * 16 + l7 + (mi & 1) * 8;
                int chunk = 2 * ks + (mi >> 1);
                int phys = chunk ^ ((row >> 1) & 3);
                ldsm_x4(af[mf][0], af[mf][1], af[mf][2], af[mf][3],
                        sa + row * 64 + phys * 16);
            }
            #pragma unroll
            for (int p = 0; p < 2; p++) {
                int row = wn * 32 + p * 16 + l7 + (mi >> 1) * 8;
                int chunk = 2 * ks + (mi & 1);
                int phys = chunk ^ ((row >> 1) & 3);
                uint32_t r0, r1, r2, r3;
                ldsm_x4(r0, r1, r2, r3, sbm + row * 64 + phys * 16);
                bf[2 * p][0] = r0; bf[2 * p][1] = r1;
                bf[2 * p + 1][0] = r2; bf[2 * p + 1][1] = r3;
            }
            #pragma unroll
            for (int mf = 0; mf < 4; mf++)
                #pragma unroll
                for (int nf = 0; nf < 4; nf++)
                    mma_bf16(acc[mf][nf][0], acc[mf][nf][1], acc[mf][nf][2], acc[mf][nf][3],
                             af[mf][0], af[mf][1], af[mf][2], af[mf][3],
                             bf[nf][0], bf[nf][1]);
        }
    }

    const long long m0 = (long long)blockIdx.y * 128;
    const int n0 = blockIdx.x * 128;
    const float* bp = bias + (long long)bb * N + n0;

    if (awOut) {
        // stage (a,w) half2 tile in smem (stride 65), coalesced store + fused chunk composite
        __syncthreads();
        uint32_t* sw = (uint32_t*)dsm;
        #pragma unroll
        for (int mf = 0; mf < 4; mf++) {
            int rl = (wm * 4 + mf) * 16 + g;
            #pragma unroll
            for (int nf = 0; nf < 4; nf++) {
                int col = (wn * 4 + nf) * 8 + 2 * t;
                float2 bv = *(const float2*)(bp + col);
                int dl = (wn * 4 + nf) * 4 + t;
                {
                    float hid = acc[mf][nf][0] + bv.x;
                    float gat = acc[mf][nf][1] + bv.y;
                    float z = __fdividef(1.f, 1.f + __expf(-gat));
                    float ht = (hid >= 0.f) ? (hid + 0.5f) : __fdividef(1.f, 1.f + __expf(-hid));
                    __half2 hv = __floats2half2_rn(1.0f - z, z * ht);
                    sw[rl * 65 + dl] = *(uint32_t*)&hv;
                }
                {
                    float hid = acc[mf][nf][2] + bv.x;
                    float gat = acc[mf][nf][3] + bv.y;
                    float z = __fdividef(1.f, 1.f + __expf(-gat));
                    float ht = (hid >= 0.f) ? (hid + 0.5f) : __fdividef(1.f, 1.f + __expf(-hid));
                    __half2 hv = __floats2half2_rn(1.0f - z, z * ht);
                    sw[(rl + 8) * 65 + dl] = *(uint32_t*)&hv;
                }
            }
        }
        __syncthreads();
        __half2* ap = awOut + (long long)bb * SEQ * DI;
        const int d0 = n0 >> 1;
        #pragma unroll
        for (int i = 0; i < 8; i++) {
            int lin = i * 256 + tid;
            int row = lin >> 4, c16 = lin & 15;
            uint4 u = make_uint4(sw[row * 65 + c16 * 4 + 0], sw[row * 65 + c16 * 4 + 1],
                                 sw[row * 65 + c16 * 4 + 2], sw[row * 65 + c16 * 4 + 3]);
            *(uint4*)(ap + (m0 + row) * DI + d0 + c16 * 4) = u;
        }
        // fused scan_a: chunk composite over the 128 rows of this tile (rows = s within chunk)
        {
            const int d = tid >> 2;       // 0..63
            const int q = tid & 3;        // quarter (32 rows each)
            float Acc = 1.f, Wcc = 0.f;
            #pragma unroll 8
            for (int i = 0; i < 32; i++) {
                uint32_t u = sw[(q * 32 + i) * 65 + d];
                __half2 hv = *(__half2*)&u;
                float a = __low2float(hv), w = __high2float(hv);
                Acc = a * Acc;
                Wcc = fmaf(a, Wcc, w);
            }
            // ordered combine across the 4 quarters (lanes base..base+3 of same warp)
            const int base = lane & ~3;
            float Af = __shfl_sync(0xffffffffu, Acc, base);
            float Wf = __shfl_sync(0xffffffffu, Wcc, base);
            #pragma unroll
            for (int j = 1; j < 4; j++) {
                float Aj = __shfl_sync(0xffffffffu, Acc, base + j);
                float Wj = __shfl_sync(0xffffffffu, Wcc, base + j);
                Wf = fmaf(Aj, Wf, Wj);
                Af = Aj * Af;
            }
            if (q == 0) {
                int o = (bb * NCH + blockIdx.y) * DI + d0 + d;
                cA[o] = Af;
                cW[o] = Wf;
            }
        }
        return;
    }

    float* Cp = C + (long long)bb * sC;
    const float* Rp = resid ? (resid + (long long)bb * sC) : nullptr;
    #pragma unroll
    for (int mf = 0; mf < 4; mf++) {
        long long r0 = m0 + (wm * 4 + mf) * 16 + g;
        #pragma unroll
        for (int nf = 0; nf < 4; nf++) {
            int col = (wn * 4 + nf) * 8 + 2 * t;
            float2 bv = *(const float2*)(bp + col);
            long long o0 = r0 * N + n0 + col;
            long long o1 = (r0 + 8) * N + n0 + col;
            float2 v0 = make_float2(acc[mf][nf][0] + bv.x, acc[mf][nf][1] + bv.y);
            float2 v1 = make_float2(acc[mf][nf][2] + bv.x, acc[mf][nf][3] + bv.y);
            if (Rp) {
                float2 q0 = *(const float2*)(Rp + o0);
                float2 q1 = *(const float2*)(Rp + o1);
                v0.x += q0.x; v0.y += q0.y;
                v1.x += q1.x; v1.y += q1.y;
            }
            *(float2*)(Cp + o0) = v0;
            *(float2*)(Cp + o1) = v1;
        }
    }
}

// ---------------- 5/6. scan prefix + replay ----------------
__global__ void scan_b_kernel(const float* __restrict__ cA, const float* __restrict__ cW,
                              float* __restrict__ h0, float* __restrict__ auxp) {
    if (blockIdx.x == 0 && threadIdx.x == 0) *auxp = 0.0f;
    int b = blockIdx.x / 5, gA = blockIdx.x % 5;
    int d = gA * 256 + threadIdx.x;
    float h = 0.f;
    #pragma unroll
    for (int c = 0; c < NCH; c++) {
        int o = (b * NCH + c) * DI + d;
        h0[o] = h;
        h = fmaf(cA[o], h, cW[o]);
    }
}

__global__ __launch_bounds__(256) void scan_c_kernel(const __half2* __restrict__ aw,
                                                     const float* __restrict__ h0,
                                                     __nv_bfloat16* __restrict__ hsb,
                                                     float* __restrict__ ns) {
    __shared__ uint32_t sa[16][256];
    __shared__ __nv_bfloat16 sO[16][256];
    int bid = blockIdx.x;
    int b = bid / (5 * NCH);
    int rem = bid % (5 * NCH);
    int gA = rem / NCH, c = rem % NCH;
    int d0 = gA * 256;
    const int tid = threadIdx.x;
    const uint32_t* ab = (const uint32_t*)(aw + (long long)b * SEQ * DI);
    __nv_bfloat16* hb = hsb + (long long)b * SEQ * DI;
    float h = h0[(b * NCH + c) * DI + d0 + tid];
    for (int s0 = c * CH; s0 < (c + 1) * CH; s0 += 16) {
        #pragma unroll
        for (int i = 0; i < 4; i++) {
            int lin = i * 256 + tid;
            int row = lin >> 6;
            int c4 = (lin & 63) * 4;
            *(uint4*)&sa[row][c4] = *(const uint4*)(ab + (long long)(s0 + row) * DI + d0 + c4);
        }
        __syncthreads();
        #pragma unroll
        for (int s = 0; s < 16; s++) {
            uint32_t u = sa[s][tid];
            __half2 hv = *(__half2*)&u;
            h = fmaf(__low2float(hv), h, __high2float(hv));
            sO[s][tid] = __float2bfloat16(h);
        }
        __syncthreads();
        #pragma unroll
        for (int i = 0; i < 2; i++) {
            int lin = i * 256 + tid;
            int row = lin >> 5;
            int cc = (lin & 31) * 8;
            *(uint4*)(hb + (long long)(s0 + row) * DI + d0 + cc) = *(uint4*)&sO[row][cc];
        }
        __syncthreads();
    }
    if (c == NCH - 1) ns[b * DI + d0 + tid] = h;
}

// ---------------- launch ----------------
extern "C" void kernel_launch(void* const* d_in, const int* in_sizes, int n_in,
                              void* d_out, int out_size) {
    const float* inputs   = (const float*)d_in[0];
    const float* norm_w   = (const float*)d_in[1];
    const float* router_w = (const float*)d_in[2];
    const float* router_b = (const float*)d_in[3];
    const float* w_in     = (const float*)d_in[4];
    const float* b_in     = (const float*)d_in[5];
    const float* w_out    = (const float*)d_in[6];
    const float* b_out    = (const float*)d_in[7];
    float* out = (float*)d_out;

    __nv_bfloat16 *xnh, *WiT, *WoT, *hs;
    __half2* aw;
    float *partial, *probs, *bi, *bo, *cA, *cW, *h0;
    cudaGetSymbolAddress((void**)&xnh, g_xnh);
    cudaGetSymbolAddress((void**)&partial, g_partial);
    cudaGetSymbolAddress((void**)&probs, g_probs);
    cudaGetSymbolAddress((void**)&WiT, g_WiT);
    cudaGetSymbolAddress((void**)&bi, g_bi);
    cudaGetSymbolAddress((void**)&WoT, g_WoT);
    cudaGetSymbolAddress((void**)&bo, g_bo);
    cudaGetSymbolAddress((void**)&aw, g_aw);
    cudaGetSymbolAddress((void**)&hs, g_hs);
    cudaGetSymbolAddress((void**)&cA, g_cA);
    cudaGetSymbolAddress((void**)&cW, g_cW);
    cudaGetSymbolAddress((void**)&h0, g_h0);

    const int DYN = 4 * STAGE_BYTES;
    cudaFuncSetAttribute(hgemm_kernel, cudaFuncAttributeMaxDynamicSharedMemorySize, DYN);

    norm_pool_kernel<<<NB * 128, 256>>>(inputs, norm_w, xnh, partial);
    router_kernel<<<NB, 1024>>>(partial, router_w, router_b, probs);
    mix_all_kernel<<<3896, 256>>>(WiT, WoT, bi, bo, w_in, w_out, b_in, b_out, probs);
    {   // GEMM1 -> aw pairs + fused chunk composites (4th launch: profiled)
        dim3 grid(D2 / 128, SEQ / 128, NB);
        hgemm_kernel<<<grid, 256, DYN>>>(xnh, WiT, bi, nullptr, nullptr, aw, cA, cW, HID, D2,
                                         (long long)SEQ * HID, (long long)HID * D2, 0);
    }
    scan_b_kernel<<<NB * 5, 256>>>(cA, cW, h0, out + (long long)out_size - 1);
    scan_c_kernel<<<NB * 5 * NCH, 256>>>(aw, h0, hs, out + (long long)NB * SEQ * HID);
    {   // GEMM2: out = hs @ WoT^T + bo + inputs
        dim3 grid(HID / 128, SEQ / 128, NB);
        hgemm_kernel<<<grid, 256, DYN>>>(hs, WoT, bo, inputs, out, nullptr, nullptr, nullptr,
                                         DI, HID,
                                         (long long)SEQ * DI, (long long)DI * HID,
                                         (long long)SEQ * HID);
    }
}

// round 9
// speedup vs baseline: 9.8609x; 1.0703x over previous
#include <cuda_runtime.h>
#include <cuda_bf16.h>
#include <cuda_fp16.h>
#include <math.h>
#include <stdint.h>

#define HID 1024
#define NE 3
#define DI 1280
#define D2 2560
#define NB 4
#define SEQ 4096
#define EPSV 1e-6f
#define NCH 32
#define CH  128

// ---------------- scratch (device globals) ----------------
__device__ __nv_bfloat16 g_xnh[(size_t)NB * SEQ * HID];
__device__ float g_partial[NB * 128 * HID];
__device__ float g_probs[NB * NE];
__device__ __nv_bfloat16 g_WiT[(size_t)NB * HID * D2];   // hid/gate interleaved rows
__device__ float g_bi[NB * D2];
__device__ __nv_bfloat16 g_WoT[(size_t)NB * DI * HID];
__device__ float g_bo[NB * HID];
__device__ __half2 g_aw[(size_t)NB * SEQ * DI];
__device__ __nv_bfloat16 g_hs[(size_t)NB * SEQ * DI];
__device__ float g_cA[NB * NCH * DI];
__device__ float g_cW[NB * NCH * DI];
__device__ float g_h0[NB * NCH * DI];

// ---------------- PTX helpers ----------------
__device__ __forceinline__ uint32_t smem_u32(const void* p) {
    uint32_t a;
    asm("{ .reg .u64 t; cvta.to.shared.u64 t, %1; cvt.u32.u64 %0, t; }" : "=r"(a) : "l"(p));
    return a;
}
__device__ __forceinline__ void cpa16(uint32_t dst, const void* src) {
    asm volatile("{\n .reg .u64 g;\n cvta.to.global.u64 g, %1;\n"
                 " cp.async.cg.shared.global [%0], [g], 16;\n}"
                 :: "r"(dst), "l"(src));
}
__device__ __forceinline__ void ldsm_x4(uint32_t& r0, uint32_t& r1, uint32_t& r2, uint32_t& r3,
                                        uint32_t addr) {
    asm volatile("ldmatrix.sync.aligned.m8n8.x4.shared.b16 {%0,%1,%2,%3}, [%4];"
                 : "=r"(r0), "=r"(r1), "=r"(r2), "=r"(r3) : "r"(addr));
}
__device__ __forceinline__ void mma_bf16(float& d0, float& d1, float& d2, float& d3,
                                         uint32_t a0, uint32_t a1, uint32_t a2, uint32_t a3,
                                         uint32_t b0, uint32_t b1) {
    asm volatile("mma.sync.aligned.m16n8k16.row.col.f32.bf16.bf16.f32 "
                 "{%0,%1,%2,%3}, {%4,%5,%6,%7}, {%8,%9}, {%0,%1,%2,%3};"
                 : "+f"(d0), "+f"(d1), "+f"(d2), "+f"(d3)
                 : "r"(a0), "r"(a1), "r"(a2), "r"(a3), "r"(b0), "r"(b1));
}

// ---------------- 1. fused RMSNorm -> bf16 + pooled partial ----------------
__global__ __launch_bounds__(256) void norm_pool_kernel(const float* __restrict__ in,
                                                        const float* __restrict__ nw,
                                                        __nv_bfloat16* __restrict__ xnh,
                                                        float* __restrict__ partial) {
    __shared__ float sp[8][1024];
    const int blk = blockIdx.x;
    const int b = blk >> 7, ch = blk & 127;
    const int wid = threadIdx.x >> 5, lane = threadIdx.x & 31;

    float4 wv[8];
    #pragma unroll
    for (int i = 0; i < 8; i++) wv[i] = *(const float4*)(nw + i * 128 + lane * 4);

    float4 pacc[8];
    #pragma unroll
    for (int i = 0; i < 8; i++) pacc[i] = make_float4(0.f, 0.f, 0.f, 0.f);

    const long long rowBase = (long long)b * SEQ + ch * 32 + wid * 4;
    #pragma unroll
    for (int r = 0; r < 4; r++) {
        const float* rp = in + (rowBase + r) * HID;
        float4 v[8];
        float ss = 0.f;
        #pragma unroll
        for (int i = 0; i < 8; i++) {
            v[i] = *(const float4*)(rp + i * 128 + lane * 4);
            ss += v[i].x * v[i].x + v[i].y * v[i].y + v[i].z * v[i].z + v[i].w * v[i].w;
        }
        #pragma unroll
        for (int o = 16; o > 0; o >>= 1) ss += __shfl_xor_sync(0xffffffffu, ss, o);
        float scale = rsqrtf(ss * (1.0f / HID) + EPSV);
        __nv_bfloat16* op = xnh + (rowBase + r) * HID;
        #pragma unroll
        for (int i = 0; i < 8; i++) {
            float x0 = v[i].x * scale * wv[i].x;
            float x1 = v[i].y * scale * wv[i].y;
            float x2 = v[i].z * scale * wv[i].z;
            float x3 = v[i].w * scale * wv[i].w;
            pacc[i].x += x0; pacc[i].y += x1; pacc[i].z += x2; pacc[i].w += x3;
            __nv_bfloat162 p0 = __floats2bfloat162_rn(x0, x1);
            __nv_bfloat162 p1 = __floats2bfloat162_rn(x2, x3);
            uint2 u;
            u.x = *(uint32_t*)&p0;
            u.y = *(uint32_t*)&p1;
            *(uint2*)(op + i * 128 + lane * 4) = u;
        }
    }
    #pragma unroll
    for (int i = 0; i < 8; i++) *(float4*)(&sp[wid][i * 128 + lane * 4]) = pacc[i];
    __syncthreads();
    float* pp = partial + (long long)(b * 128 + ch) * HID;
    int h = threadIdx.x * 4;
    float4 s = make_float4(0.f, 0.f, 0.f, 0.f);
    #pragma unroll
    for (int w = 0; w < 8; w++) {
        float4 q = *(float4*)(&sp[w][h]);
        s.x += q.x; s.y += q.y; s.z += q.z; s.w += q.w;
    }
    *(float4*)(pp + h) = s;
}

// ---------------- 2. router (one block per batch) ----------------
__global__ void router_kernel(const float* __restrict__ partial,
                              const float* __restrict__ rw,
                              const float* __restrict__ rb,
                              float* __restrict__ probs) {
    __shared__ float red[3][32];
    const int b = blockIdx.x;
    const int h = threadIdx.x;
    const int wid = h >> 5, lid = h & 31;
    float s = 0.f;
    for (int c = 0; c < 128; c++) s += partial[(long long)(b * 128 + c) * HID + h];
    float p = s * (1.0f / SEQ);
    float a0 = p * rw[h * NE + 0];
    float a1 = p * rw[h * NE + 1];
    float a2 = p * rw[h * NE + 2];
    #pragma unroll
    for (int o = 16; o > 0; o >>= 1) {
        a0 += __shfl_xor_sync(0xffffffffu, a0, o);
        a1 += __shfl_xor_sync(0xffffffffu, a1, o);
        a2 += __shfl_xor_sync(0xffffffffu, a2, o);
    }
    if (lid == 0) { red[0][wid] = a0; red[1][wid] = a1; red[2][wid] = a2; }
    __syncthreads();
    if (h == 0) {
        float l0 = rb[0], l1 = rb[1], l2 = rb[2];
        #pragma unroll
        for (int w = 0; w < 32; w++) { l0 += red[0][w]; l1 += red[1][w]; l2 += red[2][w]; }
        float mx = fmaxf(l0, fmaxf(l1, l2));
        float e0 = expf(l0 - mx), e1 = expf(l1 - mx), e2 = expf(l2 - mx);
        float inv = 1.0f / (e0 + e1 + e2);
        probs[b * 3 + 0] = e0 * inv;
        probs[b * 3 + 1] = e1 * inv;
        probs[b * 3 + 2] = e2 * inv;
    }
}

// ---------------- 3. fused mixing ----------------
__device__ __forceinline__ void mixT_body(__nv_bfloat16* __restrict__ dst,
                                          const float* __restrict__ src,
                                          const float* __restrict__ probs,
                                          int K, int N, int bx, int by, int tid, int perm) {
    __shared__ float t0[32][33], t1[32][33], t2[32][33];
    int tx = tid & 31, ty = tid >> 5;
    int k0 = by * 32, n0 = bx * 32;
    long long eSz = (long long)K * N;
    #pragma unroll
    for (int i = 0; i < 4; i++) {
        int k = k0 + ty + i * 8;
        long long o = (long long)k * N + n0 + tx;
        t0[ty + i * 8][tx] = src[o];
        t1[ty + i * 8][tx] = src[eSz + o];
        t2[ty + i * 8][tx] = src[2 * eSz + o];
    }
    __syncthreads();
    #pragma unroll
    for (int b = 0; b < NB; b++) {
        float p0 = probs[b * 3 + 0], p1 = probs[b * 3 + 1], p2 = probs[b * 3 + 2];
        #pragma unroll
        for (int i = 0; i < 4; i++) {
            int n = n0 + ty + i * 8;
            int k = k0 + tx;
            float v = p0 * t0[tx][ty + i * 8] + p1 * t1[tx][ty + i * 8] + p2 * t2[tx][ty + i * 8];
            long long r = perm ? ((n < DI) ? 2 * n : 2 * (n - DI) + 1) : n;
            dst[(long long)b * eSz + r * K + k] = __float2bfloat16(v);
        }
    }
}

__global__ void mix_all_kernel(__nv_bfloat16* __restrict__ WiT, __nv_bfloat16* __restrict__ WoT,
                               float* __restrict__ bi, float* __restrict__ bo,
                               const float* __restrict__ w_in, const float* __restrict__ w_out,
                               const float* __restrict__ b_in, const float* __restrict__ b_out,
                               const float* __restrict__ probs) {
    int bid = blockIdx.x, tid = threadIdx.x;
    if (bid < 2560) {
        mixT_body(WiT, w_in, probs, HID, D2, bid % 80, bid / 80, tid, 1);
    } else if (bid < 3840) {
        int id = bid - 2560;
        mixT_body(WoT, w_out, probs, DI, HID, id % 32, id / 32, tid, 0);
    } else if (bid < 3880) {
        int i = (bid - 3840) * 256 + tid;
        if (i < NB * D2) {
            int b = i / D2, j = i - b * D2;
            float v = probs[b * 3 + 0] * b_in[j] + probs[b * 3 + 1] * b_in[D2 + j] +
                      probs[b * 3 + 2] * b_in[2 * D2 + j];
            long long r = (j < DI) ? 2 * j : 2 * (j - DI) + 1;
            bi[(long long)b * D2 + r] = v;
        }
    } else {
        int i = (bid - 3880) * 256 + tid;
        if (i < NB * HID) {
            int b = i / HID, j = i - b * HID;
            bo[i] = probs[b * 3 + 0] * b_out[j] + probs[b * 3 + 1] * b_out[HID + j] +
                    probs[b * 3 + 2] * b_out[2 * HID + j];
        }
    }
}

// ---------------- 4/7. bf16 GEMM: cp.async 3-stage BK=64 + ldmatrix ----------------
#define STAGE_BYTES 32768

__global__ __launch_bounds__(256, 2) void hgemm_kernel(
    const __nv_bfloat16* __restrict__ A, const __nv_bfloat16* __restrict__ B,
    const float* __restrict__ bias, const float* __restrict__ resid,
    float* __restrict__ C, __half2* __restrict__ awOut,
    float* __restrict__ cA, float* __restrict__ cW, int K, int N,
    long long sA, long long sB, long long sC) {
    extern __shared__ uint8_t dsm[];
    const uint32_t smb = smem_u32(dsm);
    const int tid = threadIdx.x;
    const int wid = tid >> 5;
    const int lane = tid & 31;
    const int bb = blockIdx.z;

    const __nv_bfloat16* Abase = A + (long long)bb * sA + (long long)blockIdx.y * 128 * K;
    const __nv_bfloat16* Bbase = B + (long long)bb * sB + (long long)blockIdx.x * 128 * K;

    const int g = lane >> 2, t = lane & 3;
    const int wm = wid >> 2;
    const int wn = wid & 3;

    float acc[4][4][4];
    #pragma unroll
    for (int i = 0; i < 4; i++)
        #pragma unroll
        for (int j = 0; j < 4; j++)
            #pragma unroll
            for (int q = 0; q < 4; q++) acc[i][j][q] = 0.f;

    const int KT = K >> 6;   // BK = 64

    // 128B rows (64 bf16), 8 chunks of 16B, swizzle: phys = chunk ^ (row & 7)
    auto issue = [&](int kt, int stg) {
        uint32_t sb = smb + stg * STAGE_BYTES;
        #pragma unroll
        for (int u = 0; u < 4; u++) {
            int c = tid + u * 256;
            int row = c >> 3, k16 = c & 7;
            int phys = k16 ^ (row & 7);
            uint32_t off = row * 128 + phys * 16;
            cpa16(sb + off, Abase + (long long)row * K + kt * 64 + k16 * 8);
            cpa16(sb + 16384 + off, Bbase + (long long)row * K + kt * 64 + k16 * 8);
        }
    };

    issue(0, 0);
    asm volatile("cp.async.commit_group;" ::: "memory");
    issue(1, 1);
    asm volatile("cp.async.commit_group;" ::: "memory");

    const int mi = lane >> 3;
    const int l7 = lane & 7;

    int stC = 0, stI = 2;    // compute stage, issue stage
    for (int kt = 0; kt < KT; kt++) {
        asm volatile("cp.async.wait_group 1;" ::: "memory");
        __syncthreads();
        if (kt + 2 < KT) issue(kt + 2, stI);
        asm volatile("cp.async.commit_group;" ::: "memory");

        uint32_t sa = smb + stC * STAGE_BYTES;
        uint32_t sbm = sa + 16384;
        #pragma unroll
        for (int ks = 0; ks < 4; ks++) {
            uint32_t af[4][4], bf[4][2];
            #pragma unroll
            for (int mf = 0; mf < 4; mf++) {
                int row = wm * 64 + mf * 16 + l7 + (mi & 1) * 8;
                int chunk = 2 * ks + (mi >> 1);
                int phys = chunk ^ (row & 7);
                ldsm_x4(af[mf][0], af[mf][1], af[mf][2], af[mf][3],
                        sa + row * 128 + phys * 16);
            }
            #pragma unroll
            for (int p = 0; p < 2; p++) {
                int row = wn * 32 + p * 16 + l7 + (mi >> 1) * 8;
                int chunk = 2 * ks + (mi & 1);
                int phys = chunk ^ (row & 7);
                uint32_t r0, r1, r2, r3;
                ldsm_x4(r0, r1, r2, r3, sbm + row * 128 + phys * 16);
                bf[2 * p][0] = r0; bf[2 * p][1] = r1;
                bf[2 * p + 1][0] = r2; bf[2 * p + 1][1] = r3;
            }
            #pragma unroll
            for (int mf = 0; mf < 4; mf++)
                #pragma unroll
                for (int nf = 0; nf < 4; nf++)
                    mma_bf16(acc[mf][nf][0], acc[mf][nf][1], acc[mf][nf][2], acc[mf][nf][3],
                             af[mf][0], af[mf][1], af[mf][2], af[mf][3],
                             bf[nf][0], bf[nf][1]);
        }
        stC = (stC == 2) ? 0 : stC + 1;
        stI = (stI == 2) ? 0 : stI + 1;
    }

    const long long m0 = (long long)blockIdx.y * 128;
    const int n0 = blockIdx.x * 128;
    const float* bp = bias + (long long)bb * N + n0;

    if (awOut) {
        __syncthreads();
        uint32_t* sw = (uint32_t*)dsm;
        #pragma unroll
        for (int mf = 0; mf < 4; mf++) {
            int rl = (wm * 4 + mf) * 16 + g;
            #pragma unroll
            for (int nf = 0; nf < 4; nf++) {
                int col = (wn * 4 + nf) * 8 + 2 * t;
                float2 bv = *(const float2*)(bp + col);
                int dl = (wn * 4 + nf) * 4 + t;
                {
                    float hid = acc[mf][nf][0] + bv.x;
                    float gat = acc[mf][nf][1] + bv.y;
                    float z = __fdividef(1.f, 1.f + __expf(-gat));
                    float ht = (hid >= 0.f) ? (hid + 0.5f) : __fdividef(1.f, 1.f + __expf(-hid));
                    __half2 hv = __floats2half2_rn(1.0f - z, z * ht);
                    sw[rl * 65 + dl] = *(uint32_t*)&hv;
                }
                {
                    float hid = acc[mf][nf][2] + bv.x;
                    float gat = acc[mf][nf][3] + bv.y;
                    float z = __fdividef(1.f, 1.f + __expf(-gat));
                    float ht = (hid >= 0.f) ? (hid + 0.5f) : __fdividef(1.f, 1.f + __expf(-hid));
                    __half2 hv = __floats2half2_rn(1.0f - z, z * ht);
                    sw[(rl + 8) * 65 + dl] = *(uint32_t*)&hv;
                }
            }
        }
        __syncthreads();
        __half2* ap = awOut + (long long)bb * SEQ * DI;
        const int d0 = n0 >> 1;
        #pragma unroll
        for (int i = 0; i < 8; i++) {
            int lin = i * 256 + tid;
            int row = lin >> 4, c16 = lin & 15;
            uint4 u = make_uint4(sw[row * 65 + c16 * 4 + 0], sw[row * 65 + c16 * 4 + 1],
                                 sw[row * 65 + c16 * 4 + 2], sw[row * 65 + c16 * 4 + 3]);
            *(uint4*)(ap + (m0 + row) * DI + d0 + c16 * 4) = u;
        }
        // fused scan_a: chunk composite over the 128 rows of this tile
        {
            const int d = tid >> 2;
            const int q = tid & 3;
            float Acc = 1.f, Wcc = 0.f;
            #pragma unroll 8
            for (int i = 0; i < 32; i++) {
                uint32_t u = sw[(q * 32 + i) * 65 + d];
                __half2 hv = *(__half2*)&u;
                float a = __low2float(hv), w = __high2float(hv);
                Acc = a * Acc;
                Wcc = fmaf(a, Wcc, w);
            }
            const int base = lane & ~3;
            float Af = __shfl_sync(0xffffffffu, Acc, base);
            float Wf = __shfl_sync(0xffffffffu, Wcc, base);
            #pragma unroll
            for (int j = 1; j < 4; j++) {
                float Aj = __shfl_sync(0xffffffffu, Acc, base + j);
                float Wj = __shfl_sync(0xffffffffu, Wcc, base + j);
                Wf = fmaf(Aj, Wf, Wj);
                Af = Aj * Af;
            }
            if (q == 0) {
                int o = (bb * NCH + blockIdx.y) * DI + d0 + d;
                cA[o] = Af;
                cW[o] = Wf;
            }
        }
        return;
    }

    float* Cp = C + (long long)bb * sC;
    const float* Rp = resid ? (resid + (long long)bb * sC) : nullptr;
    #pragma unroll
    for (int mf = 0; mf < 4; mf++) {
        long long r0 = m0 + (wm * 4 + mf) * 16 + g;
        #pragma unroll
        for (int nf = 0; nf < 4; nf++) {
            int col = (wn * 4 + nf) * 8 + 2 * t;
            float2 bv = *(const float2*)(bp + col);
            long long o0 = r0 * N + n0 + col;
            long long o1 = (r0 + 8) * N + n0 + col;
            float2 v0 = make_float2(acc[mf][nf][0] + bv.x, acc[mf][nf][1] + bv.y);
            float2 v1 = make_float2(acc[mf][nf][2] + bv.x, acc[mf][nf][3] + bv.y);
            if (Rp) {
                float2 q0 = *(const float2*)(Rp + o0);
                float2 q1 = *(const float2*)(Rp + o1);
                v0.x += q0.x; v0.y += q0.y;
                v1.x += q1.x; v1.y += q1.y;
            }
            *(float2*)(Cp + o0) = v0;
            *(float2*)(Cp + o1) = v1;
        }
    }
}

// ---------------- 5/6. scan prefix + replay ----------------
__global__ void scan_b_kernel(const float* __restrict__ cA, const float* __restrict__ cW,
                              float* __restrict__ h0, float* __restrict__ auxp) {
    if (blockIdx.x == 0 && threadIdx.x == 0) *auxp = 0.0f;
    int b = blockIdx.x / 5, gA = blockIdx.x % 5;
    int d = gA * 256 + threadIdx.x;
    float h = 0.f;
    #pragma unroll
    for (int c = 0; c < NCH; c++) {
        int o = (b * NCH + c) * DI + d;
        h0[o] = h;
        h = fmaf(cA[o], h, cW[o]);
    }
}

__global__ __launch_bounds__(256) void scan_c_kernel(const __half2* __restrict__ aw,
                                                     const float* __restrict__ h0,
                                                     __nv_bfloat16* __restrict__ hsb,
                                                     float* __restrict__ ns) {
    __shared__ uint32_t sa[16][256];
    __shared__ __nv_bfloat16 sO[16][256];
    int bid = blockIdx.x;
    int b = bid / (5 * NCH);
    int rem = bid % (5 * NCH);
    int gA = rem / NCH, c = rem % NCH;
    int d0 = gA * 256;
    const int tid = threadIdx.x;
    const uint32_t* ab = (const uint32_t*)(aw + (long long)b * SEQ * DI);
    __nv_bfloat16* hb = hsb + (long long)b * SEQ * DI;
    float h = h0[(b * NCH + c) * DI + d0 + tid];
    for (int s0 = c * CH; s0 < (c + 1) * CH; s0 += 16) {
        #pragma unroll
        for (int i = 0; i < 4; i++) {
            int lin = i * 256 + tid;
            int row = lin >> 6;
            int c4 = (lin & 63) * 4;
            *(uint4*)&sa[row][c4] = *(const uint4*)(ab + (long long)(s0 + row) * DI + d0 + c4);
        }
        __syncthreads();
        #pragma unroll
        for (int s = 0; s < 16; s++) {
            uint32_t u = sa[s][tid];
            __half2 hv = *(__half2*)&u;
            h = fmaf(__low2float(hv), h, __high2float(hv));
            sO[s][tid] = __float2bfloat16(h);
        }
        __syncthreads();
        #pragma unroll
        for (int i = 0; i < 2; i++) {
            int lin = i * 256 + tid;
            int row = lin >> 5;
            int cc = (lin & 31) * 8;
            *(uint4*)(hb + (long long)(s0 + row) * DI + d0 + cc) = *(uint4*)&sO[row][cc];
        }
        __syncthreads();
    }
    if (c == NCH - 1) ns[b * DI + d0 + tid] = h;
}

// ---------------- launch ----------------
extern "C" void kernel_launch(void* const* d_in, const int* in_sizes, int n_in,
                              void* d_out, int out_size) {
    const float* inputs   = (const float*)d_in[0];
    const float* norm_w   = (const float*)d_in[1];
    const float* router_w = (const float*)d_in[2];
    const float* router_b = (const float*)d_in[3];
    const float* w_in     = (const float*)d_in[4];
    const float* b_in     = (const float*)d_in[5];
    const float* w_out    = (const float*)d_in[6];
    const float* b_out    = (const float*)d_in[7];
    float* out = (float*)d_out;

    __nv_bfloat16 *xnh, *WiT, *WoT, *hs;
    __half2* aw;
    float *partial, *probs, *bi, *bo, *cA, *cW, *h0;
    cudaGetSymbolAddress((void**)&xnh, g_xnh);
    cudaGetSymbolAddress((void**)&partial, g_partial);
    cudaGetSymbolAddress((void**)&probs, g_probs);
    cudaGetSymbolAddress((void**)&WiT, g_WiT);
    cudaGetSymbolAddress((void**)&bi, g_bi);
    cudaGetSymbolAddress((void**)&WoT, g_WoT);
    cudaGetSymbolAddress((void**)&bo, g_bo);
    cudaGetSymbolAddress((void**)&aw, g_aw);
    cudaGetSymbolAddress((void**)&hs, g_hs);
    cudaGetSymbolAddress((void**)&cA, g_cA);
    cudaGetSymbolAddress((void**)&cW, g_cW);
    cudaGetSymbolAddress((void**)&h0, g_h0);

    const int DYN = 3 * STAGE_BYTES;   // 96 KB
    cudaFuncSetAttribute(hgemm_kernel, cudaFuncAttributeMaxDynamicSharedMemorySize, DYN);

    norm_pool_kernel<<<NB * 128, 256>>>(inputs, norm_w, xnh, partial);
    router_kernel<<<NB, 1024>>>(partial, router_w, router_b, probs);
    mix_all_kernel<<<3896, 256>>>(WiT, WoT, bi, bo, w_in, w_out, b_in, b_out, probs);
    {   // GEMM1 -> aw pairs + fused chunk composites (4th launch: profiled)
        dim3 grid(D2 / 128, SEQ / 128, NB);
        hgemm_kernel<<<grid, 256, DYN>>>(xnh, WiT, bi, nullptr, nullptr, aw, cA, cW, HID, D2,
                                         (long long)SEQ * HID, (long long)HID * D2, 0);
    }
    scan_b_kernel<<<NB * 5, 256>>>(cA, cW, h0, out + (long long)out_size - 1);
    scan_c_kernel<<<NB * 5 * NCH, 256>>>(aw, h0, hs, out + (long long)NB * SEQ * HID);
    {   // GEMM2: out = hs @ WoT^T + bo + inputs
        dim3 grid(HID / 128, SEQ / 128, NB);
        hgemm_kernel<<<grid, 256, DYN>>>(hs, WoT, bo, inputs, out, nullptr, nullptr, nullptr,
                                         DI, HID,
                                         (long long)SEQ * DI, (long long)DI * HID,
                                         (long long)SEQ * HID);
    }
}

// round 11
// speedup vs baseline: 10.0474x; 1.0189x over previous
#include <cuda_runtime.h>
#include <cuda_bf16.h>
#include <cuda_fp16.h>
#include <math.h>
#include <stdint.h>

#define HID 1024
#define NE 3
#define DI 1280
#define D2 2560
#define NB 4
#define SEQ 4096
#define EPSV 1e-6f
#define NCH 32
#define CH  128

// ---------------- scratch (device globals) ----------------
__device__ __nv_bfloat16 g_xnh[(size_t)NB * SEQ * HID];
__device__ float g_partial[NB * 128 * HID];
__device__ float g_probs[NB * NE];
__device__ __nv_bfloat16 g_WiT[(size_t)NB * HID * D2];   // hid/gate interleaved rows
__device__ float g_bi[NB * D2];
__device__ __nv_bfloat16 g_WoT[(size_t)NB * DI * HID];
__device__ float g_bo[NB * HID];
__device__ __half2 g_aw[(size_t)NB * SEQ * DI];
__device__ __nv_bfloat16 g_hs[(size_t)NB * SEQ * DI];
__device__ float g_cA[NB * NCH * DI];
__device__ float g_cW[NB * NCH * DI];
__device__ float g_h0[NB * NCH * DI];

// ---------------- PTX helpers ----------------
__device__ __forceinline__ uint32_t smem_u32(const void* p) {
    uint32_t a;
    asm("{ .reg .u64 t; cvta.to.shared.u64 t, %1; cvt.u32.u64 %0, t; }" : "=r"(a) : "l"(p));
    return a;
}
__device__ __forceinline__ void cpa16(uint32_t dst, const void* src) {
    asm volatile("{\n .reg .u64 g;\n cvta.to.global.u64 g, %1;\n"
                 " cp.async.cg.shared.global [%0], [g], 16;\n}"
                 :: "r"(dst), "l"(src));
}
__device__ __forceinline__ void ldsm_x4(uint32_t& r0, uint32_t& r1, uint32_t& r2, uint32_t& r3,
                                        uint32_t addr) {
    asm volatile("ldmatrix.sync.aligned.m8n8.x4.shared.b16 {%0,%1,%2,%3}, [%4];"
                 : "=r"(r0), "=r"(r1), "=r"(r2), "=r"(r3) : "r"(addr));
}
__device__ __forceinline__ void mma_bf16(float& d0, float& d1, float& d2, float& d3,
                                         uint32_t a0, uint32_t a1, uint32_t a2, uint32_t a3,
                                         uint32_t b0, uint32_t b1) {
    asm volatile("mma.sync.aligned.m16n8k16.row.col.f32.bf16.bf16.f32 "
                 "{%0,%1,%2,%3}, {%4,%5,%6,%7}, {%8,%9}, {%0,%1,%2,%3};"
                 : "+f"(d0), "+f"(d1), "+f"(d2), "+f"(d3)
                 : "r"(a0), "r"(a1), "r"(a2), "r"(a3), "r"(b0), "r"(b1));
}
__device__ __forceinline__ void mbar_init(uint32_t a, uint32_t cnt) {
    asm volatile("mbarrier.init.shared.b64 [%0], %1;" :: "r"(a), "r"(cnt) : "memory");
}
__device__ __forceinline__ void mbar_arrive(uint32_t a) {
    asm volatile("mbarrier.arrive.shared.b64 _, [%0];" :: "r"(a) : "memory");
}
__device__ __forceinline__ void cpasync_mbar_arrive_noinc(uint32_t a) {
    asm volatile("cp.async.mbarrier.arrive.noinc.shared.b64 [%0];" :: "r"(a) : "memory");
}
__device__ __forceinline__ void mbar_wait(uint32_t a, uint32_t parity) {
    asm volatile("{\n\t.reg .pred P;\n"
                 "LW%=:\n\tmbarrier.try_wait.parity.acquire.cta.shared::cta.b64 P, [%0], %1, 0x989680;\n"
                 "\t@!P bra LW%=;\n\t}"
                 :: "r"(a), "r"(parity) : "memory");
}

// ---------------- 1. fused RMSNorm -> bf16 + pooled partial ----------------
__global__ __launch_bounds__(256) void norm_pool_kernel(const float* __restrict__ in,
                                                        const float* __restrict__ nw,
                                                        __nv_bfloat16* __restrict__ xnh,
                                                        float* __restrict__ partial) {
    __shared__ float sp[8][1024];
    const int blk = blockIdx.x;
    const int b = blk >> 7, ch = blk & 127;
    const int wid = threadIdx.x >> 5, lane = threadIdx.x & 31;

    float4 wv[8];
    #pragma unroll
    for (int i = 0; i < 8; i++) wv[i] = *(const float4*)(nw + i * 128 + lane * 4);

    float4 pacc[8];
    #pragma unroll
    for (int i = 0; i < 8; i++) pacc[i] = make_float4(0.f, 0.f, 0.f, 0.f);

    const long long rowBase = (long long)b * SEQ + ch * 32 + wid * 4;
    #pragma unroll
    for (int r = 0; r < 4; r++) {
        const float* rp = in + (rowBase + r) * HID;
        float4 v[8];
        float ss = 0.f;
        #pragma unroll
        for (int i = 0; i < 8; i++) {
            v[i] = *(const float4*)(rp + i * 128 + lane * 4);
            ss += v[i].x * v[i].x + v[i].y * v[i].y + v[i].z * v[i].z + v[i].w * v[i].w;
        }
        #pragma unroll
        for (int o = 16; o > 0; o >>= 1) ss += __shfl_xor_sync(0xffffffffu, ss, o);
        float scale = rsqrtf(ss * (1.0f / HID) + EPSV);
        __nv_bfloat16* op = xnh + (rowBase + r) * HID;
        #pragma unroll
        for (int i = 0; i < 8; i++) {
            float x0 = v[i].x * scale * wv[i].x;
            float x1 = v[i].y * scale * wv[i].y;
            float x2 = v[i].z * scale * wv[i].z;
            float x3 = v[i].w * scale * wv[i].w;
            pacc[i].x += x0; pacc[i].y += x1; pacc[i].z += x2; pacc[i].w += x3;
            __nv_bfloat162 p0 = __floats2bfloat162_rn(x0, x1);
            __nv_bfloat162 p1 = __floats2bfloat162_rn(x2, x3);
            uint2 u;
            u.x = *(uint32_t*)&p0;
            u.y = *(uint32_t*)&p1;
            *(uint2*)(op + i * 128 + lane * 4) = u;
        }
    }
    #pragma unroll
    for (int i = 0; i < 8; i++) *(float4*)(&sp[wid][i * 128 + lane * 4]) = pacc[i];
    __syncthreads();
    float* pp = partial + (long long)(b * 128 + ch) * HID;
    int h = threadIdx.x * 4;
    float4 s = make_float4(0.f, 0.f, 0.f, 0.f);
    #pragma unroll
    for (int w = 0; w < 8; w++) {
        float4 q = *(float4*)(&sp[w][h]);
        s.x += q.x; s.y += q.y; s.z += q.z; s.w += q.w;
    }
    *(float4*)(pp + h) = s;
}

// ---------------- 2. router (one block per batch) ----------------
__global__ void router_kernel(const float* __restrict__ partial,
                              const float* __restrict__ rw,
                              const float* __restrict__ rb,
                              float* __restrict__ probs) {
    __shared__ float red[3][32];
    const int b = blockIdx.x;
    const int h = threadIdx.x;
    const int wid = h >> 5, lid = h & 31;
    float s = 0.f;
    for (int c = 0; c < 128; c++) s += partial[(long long)(b * 128 + c) * HID + h];
    float p = s * (1.0f / SEQ);
    float a0 = p * rw[h * NE + 0];
    float a1 = p * rw[h * NE + 1];
    float a2 = p * rw[h * NE + 2];
    #pragma unroll
    for (int o = 16; o > 0; o >>= 1) {
        a0 += __shfl_xor_sync(0xffffffffu, a0, o);
        a1 += __shfl_xor_sync(0xffffffffu, a1, o);
        a2 += __shfl_xor_sync(0xffffffffu, a2, o);
    }
    if (lid == 0) { red[0][wid] = a0; red[1][wid] = a1; red[2][wid] = a2; }
    __syncthreads();
    if (h == 0) {
        float l0 = rb[0], l1 = rb[1], l2 = rb[2];
        #pragma unroll
        for (int w = 0; w < 32; w++) { l0 += red[0][w]; l1 += red[1][w]; l2 += red[2][w]; }
        float mx = fmaxf(l0, fmaxf(l1, l2));
        float e0 = expf(l0 - mx), e1 = expf(l1 - mx), e2 = expf(l2 - mx);
        float inv = 1.0f / (e0 + e1 + e2);
        probs[b * 3 + 0] = e0 * inv;
        probs[b * 3 + 1] = e1 * inv;
        probs[b * 3 + 2] = e2 * inv;
    }
}

// ---------------- 3. fused mixing ----------------
__device__ __forceinline__ void mixT_body(__nv_bfloat16* __restrict__ dst,
                                          const float* __restrict__ src,
                                          const float* __restrict__ probs,
                                          int K, int N, int bx, int by, int tid, int perm) {
    __shared__ float t0[32][33], t1[32][33], t2[32][33];
    int tx = tid & 31, ty = tid >> 5;
    int k0 = by * 32, n0 = bx * 32;
    long long eSz = (long long)K * N;
    #pragma unroll
    for (int i = 0; i < 4; i++) {
        int k = k0 + ty + i * 8;
        long long o = (long long)k * N + n0 + tx;
        t0[ty + i * 8][tx] = src[o];
        t1[ty + i * 8][tx] = src[eSz + o];
        t2[ty + i * 8][tx] = src[2 * eSz + o];
    }
    __syncthreads();
    #pragma unroll
    for (int b = 0; b < NB; b++) {
        float p0 = probs[b * 3 + 0], p1 = probs[b * 3 + 1], p2 = probs[b * 3 + 2];
        #pragma unroll
        for (int i = 0; i < 4; i++) {
            int n = n0 + ty + i * 8;
            int k = k0 + tx;
            float v = p0 * t0[tx][ty + i * 8] + p1 * t1[tx][ty + i * 8] + p2 * t2[tx][ty + i * 8];
            long long r = perm ? ((n < DI) ? 2 * n : 2 * (n - DI) + 1) : n;
            dst[(long long)b * eSz + r * K + k] = __float2bfloat16(v);
        }
    }
}

__global__ void mix_all_kernel(__nv_bfloat16* __restrict__ WiT, __nv_bfloat16* __restrict__ WoT,
                               float* __restrict__ bi, float* __restrict__ bo,
                               const float* __restrict__ w_in, const float* __restrict__ w_out,
                               const float* __restrict__ b_in, const float* __restrict__ b_out,
                               const float* __restrict__ probs) {
    int bid = blockIdx.x, tid = threadIdx.x;
    if (bid < 2560) {
        mixT_body(WiT, w_in, probs, HID, D2, bid % 80, bid / 80, tid, 1);
    } else if (bid < 3840) {
        int id = bid - 2560;
        mixT_body(WoT, w_out, probs, DI, HID, id % 32, id / 32, tid, 0);
    } else if (bid < 3880) {
        int i = (bid - 3840) * 256 + tid;
        if (i < NB * D2) {
            int b = i / D2, j = i - b * D2;
            float v = probs[b * 3 + 0] * b_in[j] + probs[b * 3 + 1] * b_in[D2 + j] +
                      probs[b * 3 + 2] * b_in[2 * D2 + j];
            long long r = (j < DI) ? 2 * j : 2 * (j - DI) + 1;
            bi[(long long)b * D2 + r] = v;
        }
    } else {
        int i = (bid - 3880) * 256 + tid;
        if (i < NB * HID) {
            int b = i / HID, j = i - b * HID;
            bo[i] = probs[b * 3 + 0] * b_out[j] + probs[b * 3 + 1] * b_out[HID + j] +
                    probs[b * 3 + 2] * b_out[2 * HID + j];
        }
    }
}

// ---------------- 4/7. bf16 GEMM: mbarrier-decoupled cp.async 3-stage BK=64 ----------------
#define STAGE_BYTES 32768
#define MBAR_OFF (3 * STAGE_BYTES)

__global__ __launch_bounds__(256, 2) void hgemm_kernel(
    const __nv_bfloat16* __restrict__ A, const __nv_bfloat16* __restrict__ B,
    const float* __restrict__ bias, const float* __restrict__ resid,
    float* __restrict__ C, __half2* __restrict__ awOut,
    float* __restrict__ cA, float* __restrict__ cW, int K, int N,
    long long sA, long long sB, long long sC) {
    extern __shared__ uint8_t dsm[];
    const uint32_t smb = smem_u32(dsm);
    const uint32_t mb = smb + MBAR_OFF;      // fill[s]=mb+s*16, free[s]=mb+s*16+8
    const int tid = threadIdx.x;
    const int wid = tid >> 5;
    const int lane = tid & 31;
    const int bb = blockIdx.z;

    const __nv_bfloat16* Abase = A + (long long)bb * sA + (long long)blockIdx.y * 128 * K;
    const __nv_bfloat16* Bbase = B + (long long)bb * sB + (long long)blockIdx.x * 128 * K;

    const int g = lane >> 2, t = lane & 3;
    const int wm = wid >> 2;
    const int wn = wid & 3;

    float acc[4][4][4];
    #pragma unroll
    for (int i = 0; i < 4; i++)
        #pragma unroll
        for (int j = 0; j < 4; j++)
            #pragma unroll
            for (int q = 0; q < 4; q++) acc[i][j][q] = 0.f;

    const int KT = K >> 6;   // BK = 64

    if (tid == 0) {
        #pragma unroll
        for (int s = 0; s < 3; s++) {
            mbar_init(mb + s * 16, 256);      // fill: 256 noinc completion-arrives
            mbar_init(mb + s * 16 + 8, 256);  // free: 256 thread arrives
        }
    }
    __syncthreads();

    // 128B rows (64 bf16), 8 chunks of 16B, swizzle: phys = chunk ^ (row & 7)
    auto issue = [&](int kt, int stg) {
        uint32_t sb = smb + stg * STAGE_BYTES;
        #pragma unroll
        for (int u = 0; u < 4; u++) {
            int c = tid + u * 256;
            int row = c >> 3, k16 = c & 7;
            int phys = k16 ^ (row & 7);
            uint32_t off = row * 128 + phys * 16;
            cpa16(sb + off, Abase + (long long)row * K + kt * 64 + k16 * 8);
            cpa16(sb + 16384 + off, Bbase + (long long)row * K + kt * 64 + k16 * 8);
        }
    };

    // prologue: fill stages 0..2
    #pragma unroll
    for (int k = 0; k < 3; k++) {
        issue(k, k);
        cpasync_mbar_arrive_noinc(mb + k * 16);
    }

    const int mi = lane >> 3;
    const int l7 = lane & 7;

    uint32_t cphBits = 0;   // consumer fill-phase per stage
    uint32_t pphBits = 0;   // producer free-phase per stage
    int stC = 0;
    for (int kt = 0; kt < KT; kt++) {
        // consumer: wait fill[stC]
        mbar_wait(mb + stC * 16, (cphBits >> stC) & 1u);
        cphBits ^= (1u << stC);

        uint32_t sa = smb + stC * STAGE_BYTES;
        uint32_t sbm = sa + 16384;
        #pragma unroll
        for (int ks = 0; ks < 4; ks++) {
            uint32_t af[4][4], bf[4][2];
            #pragma unroll
            for (int mf = 0; mf < 4; mf++) {
                int row = wm * 64 + mf * 16 + l7 + (mi & 1) * 8;
                int chunk = 2 * ks + (mi >> 1);
                int phys = chunk ^ (row & 7);
                ldsm_x4(af[mf][0], af[mf][1], af[mf][2], af[mf][3],
                        sa + row * 128 + phys * 16);
            }
            #pragma unroll
            for (int p = 0; p < 2; p++) {
                int row = wn * 32 + p * 16 + l7 + (mi >> 1) * 8;
                int chunk = 2 * ks + (mi & 1);
                int phys = chunk ^ (row & 7);
                uint32_t r0, r1, r2, r3;
                ldsm_x4(r0, r1, r2, r3, sbm + row * 128 + phys * 16);
                bf[2 * p][0] = r0; bf[2 * p][1] = r1;
                bf[2 * p + 1][0] = r2; bf[2 * p + 1][1] = r3;
            }
            #pragma unroll
            for (int mf = 0; mf < 4; mf++)
                #pragma unroll
                for (int nf = 0; nf < 4; nf++)
                    mma_bf16(acc[mf][nf][0], acc[mf][nf][1], acc[mf][nf][2], acc[mf][nf][3],
                             af[mf][0], af[mf][1], af[mf][2], af[mf][3],
                             bf[nf][0], bf[nf][1]);
        }
        // consumer done with stage
        mbar_arrive(mb + stC * 16 + 8);

        // producer: refill this stage for kt+3
        if (kt + 3 < KT) {
            mbar_wait(mb + stC * 16 + 8, (pphBits >> stC) & 1u);
            pphBits ^= (1u << stC);
            issue(kt + 3, stC);
            cpasync_mbar_arrive_noinc(mb + stC * 16);
        }
        stC = (stC == 2) ? 0 : stC + 1;
    }

    const long long m0 = (long long)blockIdx.y * 128;
    const int n0 = blockIdx.x * 128;
    const float* bp = bias + (long long)bb * N + n0;

    if (awOut) {
        __syncthreads();   // all warps done with smem stages before reuse as scratch
        uint32_t* sw = (uint32_t*)dsm;
        #pragma unroll
        for (int mf = 0; mf < 4; mf++) {
            int rl = (wm * 4 + mf) * 16 + g;
            #pragma unroll
            for (int nf = 0; nf < 4; nf++) {
                int col = (wn * 4 + nf) * 8 + 2 * t;
                float2 bv = *(const float2*)(bp + col);
                int dl = (wn * 4 + nf) * 4 + t;
                {
                    float hid = acc[mf][nf][0] + bv.x;
                    float gat = acc[mf][nf][1] + bv.y;
                    float z = __fdividef(1.f, 1.f + __expf(-gat));
                    float ht = (hid >= 0.f) ? (hid + 0.5f) : __fdividef(1.f, 1.f + __expf(-hid));
                    __half2 hv = __floats2half2_rn(1.0f - z, z * ht);
                    sw[rl * 65 + dl] = *(uint32_t*)&hv;
                }
                {
                    float hid = acc[mf][nf][2] + bv.x;
                    float gat = acc[mf][nf][3] + bv.y;
                    float z = __fdividef(1.f, 1.f + __expf(-gat));
                    float ht = (hid >= 0.f) ? (hid + 0.5f) : __fdividef(1.f, 1.f + __expf(-hid));
                    __half2 hv = __floats2half2_rn(1.0f - z, z * ht);
                    sw[(rl + 8) * 65 + dl] = *(uint32_t*)&hv;
                }
            }
        }
        __syncthreads();
        __half2* ap = awOut + (long long)bb * SEQ * DI;
        const int d0 = n0 >> 1;
        #pragma unroll
        for (int i = 0; i < 8; i++) {
            int lin = i * 256 + tid;
            int row = lin >> 4, c16 = lin & 15;
            uint4 u = make_uint4(sw[row * 65 + c16 * 4 + 0], sw[row * 65 + c16 * 4 + 1],
                                 sw[row * 65 + c16 * 4 + 2], sw[row * 65 + c16 * 4 + 3]);
            *(uint4*)(ap + (m0 + row) * DI + d0 + c16 * 4) = u;
        }
        // fused scan_a: chunk composite over the 128 rows of this tile
        {
            const int d = tid >> 2;
            const int q = tid & 3;
            float Acc = 1.f, Wcc = 0.f;
            #pragma unroll 8
            for (int i = 0; i < 32; i++) {
                uint32_t u = sw[(q * 32 + i) * 65 + d];
                __half2 hv = *(__half2*)&u;
                float a = __low2float(hv), w = __high2float(hv);
                Acc = a * Acc;
                Wcc = fmaf(a, Wcc, w);
            }
            const int base = lane & ~3;
            float Af = __shfl_sync(0xffffffffu, Acc, base);
            float Wf = __shfl_sync(0xffffffffu, Wcc, base);
            #pragma unroll
            for (int j = 1; j < 4; j++) {
                float Aj = __shfl_sync(0xffffffffu, Acc, base + j);
                float Wj = __shfl_sync(0xffffffffu, Wcc, base + j);
                Wf = fmaf(Aj, Wf, Wj);
                Af = Aj * Af;
            }
            if (q == 0) {
                int o = (bb * NCH + blockIdx.y) * DI + d0 + d;
                cA[o] = Af;
                cW[o] = Wf;
            }
        }
        return;
    }

    float* Cp = C + (long long)bb * sC;
    const float* Rp = resid ? (resid + (long long)bb * sC) : nullptr;
    #pragma unroll
    for (int mf = 0; mf < 4; mf++) {
        long long r0 = m0 + (wm * 4 + mf) * 16 + g;
        #pragma unroll
        for (int nf = 0; nf < 4; nf++) {
            int col = (wn * 4 + nf) * 8 + 2 * t;
            float2 bv = *(const float2*)(bp + col);
            long long o0 = r0 * N + n0 + col;
            long long o1 = (r0 + 8) * N + n0 + col;
            float2 v0 = make_float2(acc[mf][nf][0] + bv.x, acc[mf][nf][1] + bv.y);
            float2 v1 = make_float2(acc[mf][nf][2] + bv.x, acc[mf][nf][3] + bv.y);
            if (Rp) {
                float2 q0 = *(const float2*)(Rp + o0);
                float2 q1 = *(const float2*)(Rp + o1);
                v0.x += q0.x; v0.y += q0.y;
                v1.x += q1.x; v1.y += q1.y;
            }
            *(float2*)(Cp + o0) = v0;
            *(float2*)(Cp + o1) = v1;
        }
    }
}

// ---------------- 5/6. scan prefix + replay ----------------
__global__ void scan_b_kernel(const float* __restrict__ cA, const float* __restrict__ cW,
                              float* __restrict__ h0, float* __restrict__ auxp) {
    if (blockIdx.x == 0 && threadIdx.x == 0) *auxp = 0.0f;
    int b = blockIdx.x / 5, gA = blockIdx.x % 5;
    int d = gA * 256 + threadIdx.x;
    float h = 0.f;
    #pragma unroll
    for (int c = 0; c < NCH; c++) {
        int o = (b * NCH + c) * DI + d;
        h0[o] = h;
        h = fmaf(cA[o], h, cW[o]);
    }
}

__global__ __launch_bounds__(256) void scan_c_kernel(const __half2* __restrict__ aw,
                                                     const float* __restrict__ h0,
                                                     __nv_bfloat16* __restrict__ hsb,
                                                     float* __restrict__ ns) {
    __shared__ uint32_t sa[16][256];
    __shared__ __nv_bfloat16 sO[16][256];
    int bid = blockIdx.x;
    int b = bid / (5 * NCH);
    int rem = bid % (5 * NCH);
    int gA = rem / NCH, c = rem % NCH;
    int d0 = gA * 256;
    const int tid = threadIdx.x;
    const uint32_t* ab = (const uint32_t*)(aw + (long long)b * SEQ * DI);
    __nv_bfloat16* hb = hsb + (long long)b * SEQ * DI;
    float h = h0[(b * NCH + c) * DI + d0 + tid];
    for (int s0 = c * CH; s0 < (c + 1) * CH; s0 += 16) {
        #pragma unroll
        for (int i = 0; i < 4; i++) {
            int lin = i * 256 + tid;
            int row = lin >> 6;
            int c4 = (lin & 63) * 4;
            *(uint4*)&sa[row][c4] = *(const uint4*)(ab + (long long)(s0 + row) * DI + d0 + c4);
        }
        __syncthreads();
        #pragma unroll
        for (int s = 0; s < 16; s++) {
            uint32_t u = sa[s][tid];
            __half2 hv = *(__half2*)&u;
            h = fmaf(__low2float(hv), h, __high2float(hv));
            sO[s][tid] = __float2bfloat16(h);
        }
        __syncthreads();
        #pragma unroll
        for (int i = 0; i < 2; i++) {
            int lin = i * 256 + tid;
            int row = lin >> 5;
            int cc = (lin & 31) * 8;
            *(uint4*)(hb + (long long)(s0 + row) * DI + d0 + cc) = *(uint4*)&sO[row][cc];
        }
        __syncthreads();
    }
    if (c == NCH - 1) ns[b * DI + d0 + tid] = h;
}

// ---------------- launch ----------------
extern "C" void kernel_launch(void* const* d_in, const int* in_sizes, int n_in,
                              void* d_out, int out_size) {
    const float* inputs   = (const float*)d_in[0];
    const float* norm_w   = (const float*)d_in[1];
    const float* router_w = (const float*)d_in[2];
    const float* router_b = (const float*)d_in[3];
    const float* w_in     = (const float*)d_in[4];
    const float* b_in     = (const float*)d_in[5];
    const float* w_out    = (const float*)d_in[6];
    const float* b_out    = (const float*)d_in[7];
    float* out = (float*)d_out;

    __nv_bfloat16 *xnh, *WiT, *WoT, *hs;
    __half2* aw;
    float *partial, *probs, *bi, *bo, *cA, *cW, *h0;
    cudaGetSymbolAddress((void**)&xnh, g_xnh);
    cudaGetSymbolAddress((void**)&partial, g_partial);
    cudaGetSymbolAddress((void**)&probs, g_probs);
    cudaGetSymbolAddress((void**)&WiT, g_WiT);
    cudaGetSymbolAddress((void**)&bi, g_bi);
    cudaGetSymbolAddress((void**)&WoT, g_WoT);
    cudaGetSymbolAddress((void**)&bo, g_bo);
    cudaGetSymbolAddress((void**)&aw, g_aw);
    cudaGetSymbolAddress((void**)&hs, g_hs);
    cudaGetSymbolAddress((void**)&cA, g_cA);
    cudaGetSymbolAddress((void**)&cW, g_cW);
    cudaGetSymbolAddress((void**)&h0, g_h0);

    const int DYN = 3 * STAGE_BYTES + 64;   // stages + mbarriers
    cudaFuncSetAttribute(hgemm_kernel, cudaFuncAttributeMaxDynamicSharedMemorySize, DYN);

    norm_pool_kernel<<<NB * 128, 256>>>(inputs, norm_w, xnh, partial);
    router_kernel<<<NB, 1024>>>(partial, router_w, router_b, probs);
    mix_all_kernel<<<3896, 256>>>(WiT, WoT, bi, bo, w_in, w_out, b_in, b_out, probs);
    {   // GEMM1 -> aw pairs + fused chunk composites (4th launch: profiled)
        dim3 grid(D2 / 128, SEQ / 128, NB);
        hgemm_kernel<<<grid, 256, DYN>>>(xnh, WiT, bi, nullptr, nullptr, aw, cA, cW, HID, D2,
                                         (long long)SEQ * HID, (long long)HID * D2, 0);
    }
    scan_b_kernel<<<NB * 5, 256>>>(cA, cW, h0, out + (long long)out_size - 1);
    scan_c_kernel<<<NB * 5 * NCH, 256>>>(aw, h0, hs, out + (long long)NB * SEQ * HID);
    {   // GEMM2: out = hs @ WoT^T + bo + inputs
        dim3 grid(HID / 128, SEQ / 128, NB);
        hgemm_kernel<<<grid, 256, DYN>>>(hs, WoT, bo, inputs, out, nullptr, nullptr, nullptr,
                                         DI, HID,
                                         (long long)SEQ * DI, (long long)DI * HID,
                                         (long long)SEQ * HID);
    }
}